// round 4
// baseline (speedup 1.0000x reference)
#include <cuda_runtime.h>
#include <cfloat>
#include <cstddef>

#define NN 4096
#define CC 256
#define VV 4
#define SPLITK 8
#define KCHUNK (NN / SPLITK)   // 512

// ---------------- scratch (static device globals; no cudaMalloc) ----------------
__device__ float g_dn[NN * VV * CC];
__device__ float g_recon[VV * NN * CC];
__device__ float g_relWT[12 * CC];
__device__ float g_sim[(size_t)NN * NN];
__device__ float g_p[(size_t)NN * NN];            // row-softmax numerators (selected rows)
__device__ float g_pT[(size_t)NN * NN];           // transposed col-softmax numerators (full)
__device__ float g_cpart[(size_t)SPLITK * NN * CC];

__device__ float g_rowmax_part[32 * NN];
__device__ int   g_rowidx_part[32 * NN];
__device__ float g_colmax_part[32 * NN];
__device__ int   g_colidx_part[32 * NN];
__device__ float g_rowmax[NN];
__device__ int   g_rowidx[NN];
__device__ float g_colmax[NN];
__device__ int   g_colidx[NN];
__device__ float g_rowsum[NN];
__device__ float g_colsum[NN];

__device__ int   g_rowlist[NN];
__device__ int   g_collist[NN];
__device__ int   g_segcnt[64];
__device__ int   g_segoff[64];
__device__ int   g_nsel[2];        // [0]=row count, [1]=col count

__device__ float g_soft_row[NN * CC];
__device__ float g_soft_col[NN * CC];
__device__ float g_sq_part[12 * 32];
__device__ int   g_cnt_part[12 * 32];

__constant__ int c_OPI[12] = {0,0,0,1,1,1,2,2,2,3,3,3};
__constant__ int c_OPJ[12] = {1,2,3,0,2,3,0,1,3,0,1,2};

// ---------------- fast exp (FMA-pipe polynomial) ---------------------------------
__device__ __forceinline__ float fast_exp(float x) {
    float y = x * 1.4426950408889634f;
    float n = rintf(y);
    float f = y - n;
    const float c1 = 0.6931471805599453f;
    const float c2 = 0.2402265069591007f;
    const float c3 = 0.0555041086648216f;
    const float c4 = 0.0096181291076285f;
    const float c5 = 0.0013333558146428f;
    const float c6 = 0.0001540353039338f;
    float r = c6;
    r = r * f + c5;
    r = r * f + c4;
    r = r * f + c3;
    r = r * f + c2;
    r = r * f + c1;
    r = r * f + 1.0f;
    int e = (int)n;
    return __int_as_float(__float_as_int(r) + (e << 23));
}

// ---------------- normalize ------------------------------------------------------
__global__ void __launch_bounds__(256) normalize_kernel(const float* __restrict__ desc) {
    int rv = blockIdx.x;
    int tid = threadIdx.x;
    __shared__ float ss[256];
    float x = desc[(size_t)rv * CC + tid];
    ss[tid] = x * x;
    __syncthreads();
    for (int off = 128; off > 0; off >>= 1) {
        if (tid < off) ss[tid] += ss[tid + off];
        __syncthreads();
    }
    float den = fmaxf(sqrtf(ss[0]), 1e-12f);
    g_dn[(size_t)rv * CC + tid] = x / den;
}

// ---------------- relWT ----------------------------------------------------------
__global__ void __launch_bounds__(256) relwt_kernel(const float* __restrict__ T,
                                                    const float* __restrict__ WT) {
    int op = blockIdx.x;
    int c = threadIdx.x;
    int i = c_OPI[op], j = c_OPJ[op];
    float s = 0.0f;
    #pragma unroll
    for (int k = 0; k < 16; k++) s += T[i * 16 + k] * WT[k * CC + c];
    #pragma unroll
    for (int k = 0; k < 16; k++) s += T[j * 16 + k] * WT[(16 + k) * CC + c];
    g_relWT[op * CC + c] = s;
}

// ---------------- recon GEMM (z-batched over views) ------------------------------
__global__ void __launch_bounds__(256) recon_gemm_kernel(const float* __restrict__ Wrec) {
    __shared__ float As[8][132];
    __shared__ float Bs[8][68];
    const int tid = threadIdx.x;
    const int v = blockIdx.z;
    const float* A = g_dn + v * CC;
    float* C = g_recon + (size_t)v * NN * CC;
    const int m0 = blockIdx.y * 128;
    const int n0 = blockIdx.x * 64;
    const int tx = (tid & 15) * 4;
    const int ty = (tid >> 4) * 8;
    const int lr = tid >> 1;
    const int lk = (tid & 1) * 4;
    const bool bload = tid < 128;
    const int bk = tid >> 4;
    const int bc = (tid & 15) * 4;

    float acc[8][4];
    #pragma unroll
    for (int i = 0; i < 8; i++)
        #pragma unroll
        for (int j = 0; j < 4; j++) acc[i][j] = 0.0f;

    for (int k0 = 0; k0 < CC; k0 += 8) {
        float4 a = *(const float4*)(A + (size_t)(m0 + lr) * (VV * CC) + k0 + lk);
        float4 b;
        if (bload) b = *(const float4*)(Wrec + (size_t)(k0 + bk) * CC + n0 + bc);
        __syncthreads();
        As[lk + 0][lr] = a.x; As[lk + 1][lr] = a.y; As[lk + 2][lr] = a.z; As[lk + 3][lr] = a.w;
        if (bload) *(float4*)&Bs[bk][bc] = b;
        __syncthreads();
        #pragma unroll
        for (int kk = 0; kk < 8; kk++) {
            float ar[8], br[4];
            *(float4*)(ar)     = *(const float4*)&As[kk][ty];
            *(float4*)(ar + 4) = *(const float4*)&As[kk][ty + 4];
            *(float4*)(br)     = *(const float4*)&Bs[kk][tx];
            #pragma unroll
            for (int i = 0; i < 8; i++)
                #pragma unroll
                for (int j = 0; j < 4; j++)
                    acc[i][j] += ar[i] * br[j];
        }
    }
    #pragma unroll
    for (int i = 0; i < 8; i++) {
        float* Cp = C + (size_t)(m0 + ty + i) * CC + n0 + tx;
        *(float4*)Cp = make_float4(acc[i][0], acc[i][1], acc[i][2], acc[i][3]);
    }
}

// ---------------- sim GEMM (NT) + fused row/col max partials, double-buffered ----
__global__ void __launch_bounds__(256) gemm_nt_stats_kernel(
    const float* __restrict__ A, int lda,
    const float* __restrict__ B, int ldb)
{
    __shared__ union {
        struct { float As[2][8][132]; float Bs[2][8][132]; } mm;
        struct { float cand[16][128]; int cidx[16][128]; } red;
    } sh;

    const int tid = threadIdx.x;
    const int lr = tid >> 1;
    const int lk = (tid & 1) * 4;
    const int row0 = blockIdx.y * 128;
    const int col0 = blockIdx.x * 128;
    const float* Ag = A + (size_t)(row0 + lr) * lda + lk;
    const float* Bg = B + (size_t)(col0 + lr) * ldb + lk;
    const int tx = (tid & 15) * 8;
    const int ty = (tid >> 4) * 8;
    float acc[8][8];
    #pragma unroll
    for (int i = 0; i < 8; i++)
        #pragma unroll
        for (int j = 0; j < 8; j++) acc[i][j] = 0.0f;

#define NT_COMPUTE(BUF)                                                        \
    _Pragma("unroll")                                                          \
    for (int kk = 0; kk < 8; kk++) {                                           \
        float ar[8], br[8];                                                    \
        *(float4*)(ar)     = *(const float4*)&sh.mm.As[BUF][kk][ty];           \
        *(float4*)(ar + 4) = *(const float4*)&sh.mm.As[BUF][kk][ty + 4];       \
        *(float4*)(br)     = *(const float4*)&sh.mm.Bs[BUF][kk][tx];           \
        *(float4*)(br + 4) = *(const float4*)&sh.mm.Bs[BUF][kk][tx + 4];       \
        _Pragma("unroll")                                                      \
        for (int i = 0; i < 8; i++)                                            \
            _Pragma("unroll")                                                  \
            for (int j = 0; j < 8; j++)                                        \
                acc[i][j] += ar[i] * br[j];                                    \
    }

    {
        float4 a = *(const float4*)(Ag);
        float4 b = *(const float4*)(Bg);
        sh.mm.As[0][lk + 0][lr] = a.x; sh.mm.As[0][lk + 1][lr] = a.y;
        sh.mm.As[0][lk + 2][lr] = a.z; sh.mm.As[0][lk + 3][lr] = a.w;
        sh.mm.Bs[0][lk + 0][lr] = b.x; sh.mm.Bs[0][lk + 1][lr] = b.y;
        sh.mm.Bs[0][lk + 2][lr] = b.z; sh.mm.Bs[0][lk + 3][lr] = b.w;
    }
    __syncthreads();
    int buf = 0;
    for (int kt = 1; kt < CC / 8; kt++) {
        float4 a = *(const float4*)(Ag + kt * 8);
        float4 b = *(const float4*)(Bg + kt * 8);
        NT_COMPUTE(buf);
        int nb = buf ^ 1;
        sh.mm.As[nb][lk + 0][lr] = a.x; sh.mm.As[nb][lk + 1][lr] = a.y;
        sh.mm.As[nb][lk + 2][lr] = a.z; sh.mm.As[nb][lk + 3][lr] = a.w;
        sh.mm.Bs[nb][lk + 0][lr] = b.x; sh.mm.Bs[nb][lk + 1][lr] = b.y;
        sh.mm.Bs[nb][lk + 2][lr] = b.z; sh.mm.Bs[nb][lk + 3][lr] = b.w;
        __syncthreads();
        buf = nb;
    }
    NT_COMPUTE(buf);
#undef NT_COMPUTE

    // write sim tile
    #pragma unroll
    for (int i = 0; i < 8; i++) {
        float* Cp = g_sim + (size_t)(row0 + ty + i) * NN + col0 + tx;
        *(float4*)(Cp)     = make_float4(acc[i][0], acc[i][1], acc[i][2], acc[i][3]);
        *(float4*)(Cp + 4) = make_float4(acc[i][4], acc[i][5], acc[i][6], acc[i][7]);
    }

    // ---- fused row-max partials (per col-tile) ----
    __syncthreads();   // done with mm smem
    const int txg = tid & 15;          // col group
    const int tyg = tid >> 4;          // row group
    #pragma unroll
    for (int i = 0; i < 8; i++) {
        float m = acc[i][0]; int jx = 0;
        #pragma unroll
        for (int j = 1; j < 8; j++)
            if (acc[i][j] > m) { m = acc[i][j]; jx = j; }
        sh.red.cand[txg][ty + i] = m;
        sh.red.cidx[txg][ty + i] = tx + jx;
    }
    __syncthreads();
    if (tid < 128) {
        float best = sh.red.cand[0][tid];
        int bidx = sh.red.cidx[0][tid];
        #pragma unroll
        for (int s = 1; s < 16; s++) {
            float v = sh.red.cand[s][tid];
            if (v > best) { best = v; bidx = sh.red.cidx[s][tid]; }
        }
        g_rowmax_part[blockIdx.x * NN + row0 + tid] = best;
        g_rowidx_part[blockIdx.x * NN + row0 + tid] = col0 + bidx;
    }
    __syncthreads();
    // ---- fused col-max partials (per row-tile) ----
    #pragma unroll
    for (int j = 0; j < 8; j++) {
        float m = acc[0][j]; int ii = 0;
        #pragma unroll
        for (int i = 1; i < 8; i++)
            if (acc[i][j] > m) { m = acc[i][j]; ii = i; }
        sh.red.cand[tyg][tx + j] = m;
        sh.red.cidx[tyg][tx + j] = ty + ii;
    }
    __syncthreads();
    if (tid < 128) {
        float best = sh.red.cand[0][tid];
        int bidx = sh.red.cidx[0][tid];
        #pragma unroll
        for (int s = 1; s < 16; s++) {
            float v = sh.red.cand[s][tid];
            if (v > best) { best = v; bidx = sh.red.cidx[s][tid]; }
        }
        g_colmax_part[blockIdx.y * NN + col0 + tid] = best;
        g_colidx_part[blockIdx.y * NN + col0 + tid] = row0 + bidx;
    }
}

// ---------------- final max reduce (row + col), ascending tiles -------------------
__global__ void __launch_bounds__(256) maxreduce_kernel() {
    int n = blockIdx.x * 256 + threadIdx.x;
    float bm = g_rowmax_part[n]; int bi = g_rowidx_part[n];
    for (int s = 1; s < 32; s++) {
        float v = g_rowmax_part[s * NN + n];
        if (v > bm) { bm = v; bi = g_rowidx_part[s * NN + n]; }
    }
    g_rowmax[n] = bm; g_rowidx[n] = bi;
    bm = g_colmax_part[n]; bi = g_colidx_part[n];
    for (int s = 1; s < 32; s++) {
        float v = g_colmax_part[s * NN + n];
        if (v > bm) { bm = v; bi = g_colidx_part[s * NN + n]; }
    }
    g_colmax[n] = bm; g_colidx[n] = bi;
}

// ---------------- mutual compaction: count / scan / fill -------------------------
__device__ __forceinline__ int mutual_flag(int b, int t) {
    if (b < 32) { int n = b * 128 + t; return g_colidx[g_rowidx[n]] == n; }
    else        { int m = (b - 32) * 128 + t; return g_rowidx[g_colidx[m]] == m; }
}

__global__ void __launch_bounds__(128) countseg_kernel() {
    int b = blockIdx.x, t = threadIdx.x;
    __shared__ int sc[128];
    sc[t] = mutual_flag(b, t);
    __syncthreads();
    for (int off = 64; off > 0; off >>= 1) {
        if (t < off) sc[t] += sc[t + off];
        __syncthreads();
    }
    if (t == 0) g_segcnt[b] = sc[0];
}

__global__ void scanseg_kernel() {
    if (threadIdx.x == 0) {
        int off = 0;
        for (int s = 0; s < 32; s++) { g_segoff[s] = off; off += g_segcnt[s]; }
        g_nsel[0] = off;
        off = 0;
        for (int s = 32; s < 64; s++) { g_segoff[s] = off; off += g_segcnt[s]; }
        g_nsel[1] = off;
    }
}

__global__ void __launch_bounds__(128) fillseg_kernel() {
    int b = blockIdx.x, t = threadIdx.x;
    int flag = mutual_flag(b, t);
    __shared__ int sc[128];
    sc[t] = flag;
    __syncthreads();
    for (int off = 1; off < 128; off <<= 1) {
        int v = (t >= off) ? sc[t - off] : 0;
        __syncthreads();
        sc[t] += v;
        __syncthreads();
    }
    if (flag) {
        int rank = sc[t] - 1;
        int idx = (b & 31) * 128 + t;
        if (b < 32) g_rowlist[g_segoff[b] + rank] = idx;
        else        g_collist[g_segoff[b] + rank] = idx;
    }
}

// ---------------- selected row exp + sum ------------------------------------------
__global__ void __launch_bounds__(256) rowexp_sel_kernel() {
    int b = blockIdx.x;
    if (b >= g_nsel[0]) return;
    int row = g_rowlist[b];
    int tid = threadIdx.x;
    const float* srow = g_sim + (size_t)row * NN;
    float* prow = g_p + (size_t)row * NN;
    float rmax = g_rowmax[row];
    float lsum = 0.0f;
    #pragma unroll
    for (int s = 0; s < 16; s++) {
        int idx = tid + 256 * s;
        float e = fast_exp(srow[idx] - rmax);
        prow[idx] = e;
        lsum += e;
    }
    __shared__ float sv[256];
    sv[tid] = lsum;
    __syncthreads();
    for (int off = 128; off > 0; off >>= 1) {
        if (tid < off) sv[tid] += sv[tid + off];
        __syncthreads();
    }
    if (tid == 0) g_rowsum[row] = sv[0];
}

// ---------------- transposed col exp: pT[m][k] = exp(sim[k][m] - colmax[m]) ------
__global__ void __launch_bounds__(256) transpose_exp_kernel() {
    __shared__ float tile[32][33];
    int m0 = blockIdx.x * 32;
    int k0 = blockIdx.y * 32;
    int tx = threadIdx.x & 31;
    int ty = threadIdx.x >> 5;   // 0..7
    #pragma unroll
    for (int q = 0; q < 4; q++) {
        int r = ty * 4 + q;
        tile[r][tx] = g_sim[(size_t)(k0 + r) * NN + m0 + tx];
    }
    __syncthreads();
    #pragma unroll
    for (int q = 0; q < 4; q++) {
        int r = ty * 4 + q;
        float cm = g_colmax[m0 + r];
        g_pT[(size_t)(m0 + r) * NN + k0 + tx] = fast_exp(tile[tx][r] - cm);
    }
}

// ---------------- selected col sums (rows of pT) ----------------------------------
__global__ void __launch_bounds__(256) colsum_sel_kernel() {
    int b = blockIdx.x;
    if (b >= g_nsel[1]) return;
    int m = g_collist[b];
    int tid = threadIdx.x;
    const float* prow = g_pT + (size_t)m * NN;
    float lsum = 0.0f;
    #pragma unroll
    for (int s = 0; s < 16; s++) lsum += prow[tid + 256 * s];
    __shared__ float sv[256];
    sv[tid] = lsum;
    __syncthreads();
    for (int off = 128; off > 0; off >>= 1) {
        if (tid < off) sv[tid] += sv[tid + off];
        __syncthreads();
    }
    if (tid == 0) g_colsum[m] = sv[0];
}

// ---------------- selected weighted GEMM: Cpart[z][slot] = P[list[slot]] @ B ------
// 128x128 tile, 8x8 microtile, split-K, double-buffered. B is NN x CC (ldb).
__global__ void __launch_bounds__(256) gemm_sel_kernel(
    const float* __restrict__ P,
    const int* __restrict__ list,
    const int* __restrict__ cntp,
    const float* __restrict__ B, int ldb)
{
    const int m0 = blockIdx.y * 128;
    if (m0 >= *cntp) return;
    __shared__ float As[2][8][132];
    __shared__ float Bs[2][8][132];
    const int tid = threadIdx.x;
    const int n0 = blockIdx.x * 128;
    const int kb = blockIdx.z * KCHUNK;
    const int lr = tid >> 1;
    const int lk = (tid & 1) * 4;
    const int bk = tid >> 5;
    const int bc = (tid & 31) * 4;
    const int tx = (tid & 15) * 8;
    const int ty = (tid >> 4) * 8;

    const int arow = list[m0 + lr];
    const float* Ag = P + (size_t)arow * NN + lk;
    const float* Bg = B + n0 + bc;

    float acc[8][8];
    #pragma unroll
    for (int i = 0; i < 8; i++)
        #pragma unroll
        for (int j = 0; j < 8; j++) acc[i][j] = 0.0f;

#define SEL_COMPUTE(BUF)                                                       \
    _Pragma("unroll")                                                          \
    for (int kk = 0; kk < 8; kk++) {                                           \
        float ar[8], br[8];                                                    \
        *(float4*)(ar)     = *(const float4*)&As[BUF][kk][ty];                 \
        *(float4*)(ar + 4) = *(const float4*)&As[BUF][kk][ty + 4];             \
        *(float4*)(br)     = *(const float4*)&Bs[BUF][kk][tx];                 \
        *(float4*)(br + 4) = *(const float4*)&Bs[BUF][kk][tx + 4];             \
        _Pragma("unroll")                                                      \
        for (int i = 0; i < 8; i++)                                            \
            _Pragma("unroll")                                                  \
            for (int j = 0; j < 8; j++)                                        \
                acc[i][j] += ar[i] * br[j];                                    \
    }

    {
        float4 a = *(const float4*)(Ag + kb);
        float4 b = *(const float4*)(Bg + (size_t)(kb + bk) * ldb);
        As[0][lk + 0][lr] = a.x; As[0][lk + 1][lr] = a.y;
        As[0][lk + 2][lr] = a.z; As[0][lk + 3][lr] = a.w;
        *(float4*)&Bs[0][bk][bc] = b;
    }
    __syncthreads();
    int buf = 0;
    for (int kt = 1; kt < KCHUNK / 8; kt++) {
        int k0 = kb + kt * 8;
        float4 a = *(const float4*)(Ag + k0);
        float4 b = *(const float4*)(Bg + (size_t)(k0 + bk) * ldb);
        SEL_COMPUTE(buf);
        int nb = buf ^ 1;
        As[nb][lk + 0][lr] = a.x; As[nb][lk + 1][lr] = a.y;
        As[nb][lk + 2][lr] = a.z; As[nb][lk + 3][lr] = a.w;
        *(float4*)&Bs[nb][bk][bc] = b;
        __syncthreads();
        buf = nb;
    }
    SEL_COMPUTE(buf);
#undef SEL_COMPUTE

    float* Cp0 = g_cpart + (size_t)blockIdx.z * NN * CC;
    #pragma unroll
    for (int i = 0; i < 8; i++) {
        float* Cp = Cp0 + (size_t)(m0 + ty + i) * CC + n0 + tx;
        *(float4*)(Cp)     = make_float4(acc[i][0], acc[i][1], acc[i][2], acc[i][3]);
        *(float4*)(Cp + 4) = make_float4(acc[i][4], acc[i][5], acc[i][6], acc[i][7]);
    }
}

// ---------------- split-K reduce for selected slots, scatter + normalize ----------
__global__ void __launch_bounds__(256) reduce_sel_kernel(
    float* __restrict__ soft, const float* __restrict__ den,
    const int* __restrict__ list, const int* __restrict__ cntp)
{
    int slot = blockIdx.x;
    if (slot >= *cntp) return;
    int row = list[slot];
    int c = threadIdx.x;
    float s = 0.0f;
    #pragma unroll
    for (int z = 0; z < SPLITK; z++)
        s += g_cpart[(size_t)z * NN * CC + (size_t)slot * CC + c];
    soft[(size_t)row * CC + c] = s / den[row];
}

// ---------------- per-ordered-pair loss partials ----------------------------------
__global__ void __launch_bounds__(256) loss_kernel(
    const int* __restrict__ idxA, const int* __restrict__ idxB,
    const float* __restrict__ soft, const float* __restrict__ recon, int op)
{
    int tid = threadIdx.x;
    int b = blockIdx.x;
    float relc = g_relWT[op * CC + tid];
    float lsum = 0.0f;
    int lcnt = 0;
    for (int r = 0; r < 128; r++) {
        int row = b * 128 + r;
        int a = idxA[row];
        if (idxB[a] == row) {
            float d = recon[(size_t)row * CC + tid] + relc - soft[(size_t)row * CC + tid];
            lsum += d * d;
            if (tid == 0) lcnt++;
        }
    }
    __shared__ float ss[256];
    ss[tid] = lsum;
    __syncthreads();
    for (int off = 128; off > 0; off >>= 1) {
        if (tid < off) ss[tid] += ss[tid + off];
        __syncthreads();
    }
    if (tid == 0) {
        g_sq_part[op * 32 + b] = ss[0];
        g_cnt_part[op * 32 + b] = lcnt;
    }
}

__global__ void finalize_kernel(float* __restrict__ out) {
    if (threadIdx.x == 0) {
        float total = 0.0f, count = 0.0f;
        for (int op = 0; op < 12; op++) {
            float sq = 0.0f;
            int cnt = 0;
            for (int b = 0; b < 32; b++) {
                sq += g_sq_part[op * 32 + b];
                cnt += g_cnt_part[op * 32 + b];
            }
            if (cnt > 0) {
                total += sq / fmaxf((float)cnt * (float)CC, 1.0f);
                count += 1.0f;
            }
        }
        out[0] = (count > 0.0f) ? (total / fmaxf(count, 1.0f)) : 0.0f;
    }
}

// ---------------- host launch ------------------------------------------------------
extern "C" void kernel_launch(void* const* d_in, const int* in_sizes, int n_in,
                              void* d_out, int out_size)
{
    const float* desc  = (const float*)d_in[0];
    const float* sf    = (const float*)d_in[1];
    const float* T     = (const float*)d_in[2];
    const float* W_rec = (const float*)d_in[3];
    const float* W_T   = (const float*)d_in[4];
    float* out = (float*)d_out;

    float *dn, *p, *pT, *recon, *rowsum, *colsum, *soft_row, *soft_col;
    int *rowidx, *colidx, *rowlist, *collist, *nsel;
    cudaGetSymbolAddress((void**)&dn, g_dn);
    cudaGetSymbolAddress((void**)&p, g_p);
    cudaGetSymbolAddress((void**)&pT, g_pT);
    cudaGetSymbolAddress((void**)&recon, g_recon);
    cudaGetSymbolAddress((void**)&rowsum, g_rowsum);
    cudaGetSymbolAddress((void**)&colsum, g_colsum);
    cudaGetSymbolAddress((void**)&soft_row, g_soft_row);
    cudaGetSymbolAddress((void**)&soft_col, g_soft_col);
    cudaGetSymbolAddress((void**)&rowidx, g_rowidx);
    cudaGetSymbolAddress((void**)&colidx, g_colidx);
    cudaGetSymbolAddress((void**)&rowlist, g_rowlist);
    cudaGetSymbolAddress((void**)&collist, g_collist);
    cudaGetSymbolAddress((void**)&nsel, g_nsel);

    normalize_kernel<<<NN * VV, 256>>>(desc);
    relwt_kernel<<<12, 256>>>(T, W_T);
    recon_gemm_kernel<<<dim3(CC / 64, NN / 128, VV), 256>>>(W_rec);

    auto OP = [](int i, int j) { return i * 3 + (j < i ? j : j - 1); };

    for (int i = 0; i < VV; i++) {
        for (int j = i + 1; j < VV; j++) {
            // sim + fused max partials
            gemm_nt_stats_kernel<<<dim3(NN / 128, NN / 128), 256>>>(
                dn + i * CC, VV * CC, dn + j * CC, VV * CC);
            maxreduce_kernel<<<NN / 256, 256>>>();

            // deterministic mutual compaction (both directions)
            countseg_kernel<<<64, 128>>>();
            scanseg_kernel<<<1, 32>>>();
            cudaMemsetAsync(rowlist, 0, NN * sizeof(int));
            cudaMemsetAsync(collist, 0, NN * sizeof(int));
            fillseg_kernel<<<64, 128>>>();

            // row direction: exp selected rows, weighted GEMM, scatter
            rowexp_sel_kernel<<<NN, 256>>>();
            gemm_sel_kernel<<<dim3(CC / 128, NN / 128, SPLITK), 256>>>(
                p, rowlist, nsel + 0, sf + j * CC, VV * CC);
            reduce_sel_kernel<<<NN, 256>>>(soft_row, rowsum, rowlist, nsel + 0);

            // col direction: transposed exp (full), selected sums, weighted GEMM
            transpose_exp_kernel<<<dim3(NN / 32, NN / 32), 256>>>();
            colsum_sel_kernel<<<NN, 256>>>();
            gemm_sel_kernel<<<dim3(CC / 128, NN / 128, SPLITK), 256>>>(
                pT, collist, nsel + 1, sf + i * CC, VV * CC);
            reduce_sel_kernel<<<NN, 256>>>(soft_col, colsum, collist, nsel + 1);

            // losses
            loss_kernel<<<32, 256>>>(rowidx, colidx, soft_row,
                                     recon + (size_t)i * NN * CC, OP(i, j));
            loss_kernel<<<32, 256>>>(colidx, rowidx, soft_col,
                                     recon + (size_t)j * NN * CC, OP(j, i));
        }
    }

    finalize_kernel<<<1, 32>>>(out);
}

// round 6
// speedup vs baseline: 1.6373x; 1.6373x over previous
#include <cuda_runtime.h>
#include <cuda_bf16.h>
#include <cfloat>
#include <cstddef>
#include <cstdint>

#define NN 4096
#define CC 256
#define VV 4
#define SPLITK 8

// ---------------- scratch ----------------
__device__ float g_dn[NN * VV * CC];
__device__ __nv_bfloat16 g_dnb_h[VV * NN * CC];
__device__ __nv_bfloat16 g_dnb_r[VV * NN * CC];
__device__ __nv_bfloat16 g_sfT_h[VV * CC * NN];
__device__ __nv_bfloat16 g_sfT_r[VV * CC * NN];
__device__ float g_recon[VV * NN * CC];
__device__ float g_relWT[12 * CC];
__device__ float g_sim[(size_t)NN * NN];
__device__ __nv_bfloat16 g_p_h[(size_t)NN * NN];
__device__ __nv_bfloat16 g_p_r[(size_t)NN * NN];
__device__ __nv_bfloat16 g_pT_h[(size_t)NN * NN];
__device__ __nv_bfloat16 g_pT_r[(size_t)NN * NN];
__device__ float g_cpart[(size_t)SPLITK * NN * CC];

__device__ float g_rowmax_part[32 * NN];
__device__ int   g_rowidx_part[32 * NN];
__device__ float g_colmax_part[32 * NN];
__device__ int   g_colidx_part[32 * NN];
__device__ float g_rowmax[NN];
__device__ int   g_rowidx[NN];
__device__ float g_colmax[NN];
__device__ int   g_colidx[NN];
__device__ float g_rowsum[NN];
__device__ float g_colsum[NN];

__device__ int   g_rowlist[NN];
__device__ int   g_collist[NN];
__device__ int   g_segcnt[64];
__device__ int   g_segoff[64];
__device__ int   g_nsel[2];

__device__ float g_soft_row[NN * CC];
__device__ float g_soft_col[NN * CC];
__device__ float g_sq_part[12 * 32];
__device__ int   g_cnt_part[12 * 32];

__constant__ int c_OPI[12] = {0,0,0,1,1,1,2,2,2,3,3,3};
__constant__ int c_OPJ[12] = {1,2,3,0,2,3,0,1,3,0,1,2};

// ---------------- helpers ----------------
__device__ __forceinline__ uint32_t smem_u32(const void* p) {
    uint32_t a;
    asm("{ .reg .u64 t; cvta.to.shared.u64 t, %1; cvt.u32.u64 %0, t; }" : "=r"(a) : "l"(p));
    return a;
}
// 64B-pitch XOR swizzle: row*64 + ((kc ^ ((row>>1)&3)) * 16), kc in [0,4)
__device__ __forceinline__ uint32_t swz64(int row, int kc) {
    return (uint32_t)(row * 64) + (uint32_t)(((kc ^ ((row >> 1) & 3)) & 3) << 4);
}
__device__ __forceinline__ void ldm_x4(uint32_t addr, uint32_t& r0, uint32_t& r1,
                                       uint32_t& r2, uint32_t& r3) {
    asm volatile("ldmatrix.sync.aligned.m8n8.x4.shared.b16 {%0,%1,%2,%3}, [%4];"
        : "=r"(r0), "=r"(r1), "=r"(r2), "=r"(r3) : "r"(addr));
}
__device__ __forceinline__ void mma_bf16(float* c, const uint32_t* a, uint32_t b0, uint32_t b1) {
    asm volatile("mma.sync.aligned.m16n8k16.row.col.f32.bf16.bf16.f32 "
        "{%0,%1,%2,%3}, {%4,%5,%6,%7}, {%8,%9}, {%0,%1,%2,%3};"
        : "+f"(c[0]), "+f"(c[1]), "+f"(c[2]), "+f"(c[3])
        : "r"(a[0]), "r"(a[1]), "r"(a[2]), "r"(a[3]), "r"(b0), "r"(b1));
}

__device__ __forceinline__ float fast_exp(float x) {
    float y = x * 1.4426950408889634f;
    float n = rintf(y);
    float f = y - n;
    float r = 0.0001540353039338f;
    r = r * f + 0.0013333558146428f;
    r = r * f + 0.0096181291076285f;
    r = r * f + 0.0555041086648216f;
    r = r * f + 0.2402265069591007f;
    r = r * f + 0.6931471805599453f;
    r = r * f + 1.0f;
    return __int_as_float(__float_as_int(r) + ((int)n << 23));
}

// warp-level MMA on one 32x64 warp-tile over a 32-K smem block (2 k16 steps)
__device__ __forceinline__ void mma_block(uint32_t sA, uint32_t sB, int lane,
                                          int m0w, int n0w, float acc[2][8][4]) {
    const int arow = m0w + (lane & 7) + ((lane >> 3) & 1) * 8;
    const int akc  = lane >> 4;           // 0/1
    const int brow = n0w + (lane & 7) + (lane >> 4) * 8;
    const int bkc  = (lane >> 3) & 1;
    #pragma unroll
    for (int ks = 0; ks < 2; ks++) {
        uint32_t a[2][4];
        #pragma unroll
        for (int mt = 0; mt < 2; mt++)
            ldm_x4(sA + swz64(arow + mt * 16, ks * 2 + akc),
                   a[mt][0], a[mt][1], a[mt][2], a[mt][3]);
        #pragma unroll
        for (int np = 0; np < 4; np++) {
            uint32_t b0, b1, b2, b3;
            ldm_x4(sB + swz64(brow + np * 16, ks * 2 + bkc), b0, b1, b2, b3);
            #pragma unroll
            for (int mt = 0; mt < 2; mt++) {
                mma_bf16(acc[mt][np * 2],     a[mt], b0, b1);
                mma_bf16(acc[mt][np * 2 + 1], a[mt], b2, b3);
            }
        }
    }
}

// ---------------- normalize + 2-way bf16 split ----------------
__global__ void __launch_bounds__(256) normalize_kernel(const float* __restrict__ desc) {
    int rv = blockIdx.x;
    int tid = threadIdx.x;
    __shared__ float ss[256];
    float x = desc[(size_t)rv * CC + tid];
    ss[tid] = x * x;
    __syncthreads();
    for (int off = 128; off > 0; off >>= 1) {
        if (tid < off) ss[tid] += ss[tid + off];
        __syncthreads();
    }
    float den = fmaxf(sqrtf(ss[0]), 1e-12f);
    float y = x / den;
    g_dn[(size_t)rv * CC + tid] = y;
    int n = rv / VV, v = rv % VV;
    __nv_bfloat16 h = __float2bfloat16_rn(y);
    size_t off = (size_t)(v * NN + n) * CC + tid;
    g_dnb_h[off] = h;
    g_dnb_r[off] = __float2bfloat16_rn(y - __bfloat162float(h));
}

// ---------------- sf transpose + split ----------------
__global__ void __launch_bounds__(256) sf_split_kernel(const float* __restrict__ sf) {
    __shared__ float t[32][33];
    int v = blockIdx.z;
    int n0 = blockIdx.x * 32, c0 = blockIdx.y * 32;
    int tx = threadIdx.x & 31, ty = threadIdx.x >> 5;
    #pragma unroll
    for (int q = 0; q < 4; q++) {
        int r = ty * 4 + q;
        t[r][tx] = sf[(size_t)(n0 + r) * (VV * CC) + v * CC + c0 + tx];
    }
    __syncthreads();
    #pragma unroll
    for (int q = 0; q < 4; q++) {
        int r = ty * 4 + q;
        float x = t[tx][r];
        __nv_bfloat16 h = __float2bfloat16_rn(x);
        size_t off = (size_t)v * CC * NN + (size_t)(c0 + r) * NN + n0 + tx;
        g_sfT_h[off] = h;
        g_sfT_r[off] = __float2bfloat16_rn(x - __bfloat162float(h));
    }
}

// ---------------- relWT ----------------
__global__ void __launch_bounds__(256) relwt_kernel(const float* __restrict__ T,
                                                    const float* __restrict__ WT) {
    int op = blockIdx.x;
    int c = threadIdx.x;
    int i = c_OPI[op], j = c_OPJ[op];
    float s = 0.0f;
    #pragma unroll
    for (int k = 0; k < 16; k++) s += T[i * 16 + k] * WT[k * CC + c];
    #pragma unroll
    for (int k = 0; k < 16; k++) s += T[j * 16 + k] * WT[(16 + k) * CC + c];
    g_relWT[op * CC + c] = s;
}

// ---------------- recon GEMM (fp32 SIMT, small) ----------------
__global__ void __launch_bounds__(256) recon_gemm_kernel(const float* __restrict__ Wrec) {
    __shared__ float As[8][132];
    __shared__ float Bs[8][68];
    const int tid = threadIdx.x;
    const int v = blockIdx.z;
    const float* A = g_dn + v * CC;
    float* C = g_recon + (size_t)v * NN * CC;
    const int m0 = blockIdx.y * 128;
    const int n0 = blockIdx.x * 64;
    const int tx = (tid & 15) * 4;
    const int ty = (tid >> 4) * 8;
    const int lr = tid >> 1;
    const int lk = (tid & 1) * 4;
    const bool bload = tid < 128;
    const int bk = tid >> 4;
    const int bc = (tid & 15) * 4;
    float acc[8][4];
    #pragma unroll
    for (int i = 0; i < 8; i++)
        #pragma unroll
        for (int j = 0; j < 4; j++) acc[i][j] = 0.0f;
    for (int k0 = 0; k0 < CC; k0 += 8) {
        float4 a = *(const float4*)(A + (size_t)(m0 + lr) * (VV * CC) + k0 + lk);
        float4 b;
        if (bload) b = *(const float4*)(Wrec + (size_t)(k0 + bk) * CC + n0 + bc);
        __syncthreads();
        As[lk + 0][lr] = a.x; As[lk + 1][lr] = a.y; As[lk + 2][lr] = a.z; As[lk + 3][lr] = a.w;
        if (bload) *(float4*)&Bs[bk][bc] = b;
        __syncthreads();
        #pragma unroll
        for (int kk = 0; kk < 8; kk++) {
            float ar[8], br[4];
            *(float4*)(ar)     = *(const float4*)&As[kk][ty];
            *(float4*)(ar + 4) = *(const float4*)&As[kk][ty + 4];
            *(float4*)(br)     = *(const float4*)&Bs[kk][tx];
            #pragma unroll
            for (int i = 0; i < 8; i++)
                #pragma unroll
                for (int j = 0; j < 4; j++)
                    acc[i][j] += ar[i] * br[j];
        }
    }
    #pragma unroll
    for (int i = 0; i < 8; i++) {
        float* Cp = C + (size_t)(m0 + ty + i) * CC + n0 + tx;
        *(float4*)Cp = make_float4(acc[i][0], acc[i][1], acc[i][2], acc[i][3]);
    }
}

// ---------------- sim bf16 MMA + fused row/col max partials ----------------
// grid (32, 32): bx = col tile (128), by = row tile (128). Virtual K = 4*256.
__global__ void __launch_bounds__(256) sim_bf16_kernel(
    const __nv_bfloat16* __restrict__ Ah, const __nv_bfloat16* __restrict__ Ar,
    const __nv_bfloat16* __restrict__ Bh, const __nv_bfloat16* __restrict__ Br)
{
    __shared__ __align__(16) char sm[2][16384];
    __shared__ float s_rv[2][128];
    __shared__ int   s_ri[2][128];
    __shared__ float s_cv[4][128];
    __shared__ int   s_ci[4][128];

    const int t = threadIdx.x;
    const int lane = t & 31, wid = t >> 5;
    const int m0w = (wid & 3) * 32, n0w = (wid >> 2) * 64;
    const int m0 = blockIdx.y * 128, col0 = blockIdx.x * 128;
    const int lrow = t >> 2, q = t & 3;
    const uint32_t sbase = smem_u32(&sm[0][0]);

    float acc[2][8][4];
    #pragma unroll
    for (int a = 0; a < 2; a++)
        #pragma unroll
        for (int b = 0; b < 8; b++)
            #pragma unroll
            for (int c = 0; c < 4; c++) acc[a][b][c] = 0.0f;

    uint4 ra0, ra1, rb0, rb1;
    #define SIM_LDG(KB) do { \
        int kk = ((KB) & 7) << 5; \
        const __nv_bfloat16* ap = ((KB) >= 16) ? Ar : Ah; \
        const __nv_bfloat16* bp = ((KB) & 8) ? Br : Bh; \
        ra0 = *(const uint4*)(ap + (size_t)(m0 + lrow) * CC + kk + q * 8); \
        ra1 = *(const uint4*)(ap + (size_t)(m0 + lrow + 64) * CC + kk + q * 8); \
        rb0 = *(const uint4*)(bp + (size_t)(col0 + lrow) * CC + kk + q * 8); \
        rb1 = *(const uint4*)(bp + (size_t)(col0 + lrow + 64) * CC + kk + q * 8); \
    } while (0)
    #define SIM_STS(BUF) do { \
        char* base = &sm[BUF][0]; \
        *(uint4*)(base + swz64(lrow, q)) = ra0; \
        *(uint4*)(base + swz64(lrow + 64, q)) = ra1; \
        *(uint4*)(base + 8192 + swz64(lrow, q)) = rb0; \
        *(uint4*)(base + 8192 + swz64(lrow + 64, q)) = rb1; \
    } while (0)

    SIM_LDG(0);
    SIM_STS(0);
    __syncthreads();
    for (int kb = 0; kb < 32; kb++) {
        int buf = kb & 1;
        if (kb + 1 < 32) SIM_LDG(kb + 1);
        mma_block(sbase + buf * 16384, sbase + buf * 16384 + 8192, lane, m0w, n0w, acc);
        if (kb + 1 < 32) SIM_STS(buf ^ 1);
        __syncthreads();
    }
    #undef SIM_LDG
    #undef SIM_STS

    const int gid = lane >> 2, tig = lane & 3;
    // write sim
    #pragma unroll
    for (int mt = 0; mt < 2; mt++) {
        int r0 = m0 + m0w + mt * 16 + gid;
        #pragma unroll
        for (int np = 0; np < 8; np++) {
            int c = col0 + n0w + np * 8 + tig * 2;
            *(float2*)&g_sim[(size_t)r0 * NN + c] = make_float2(acc[mt][np][0], acc[mt][np][1]);
            *(float2*)&g_sim[(size_t)(r0 + 8) * NN + c] = make_float2(acc[mt][np][2], acc[mt][np][3]);
        }
    }
    // row-max partials over this 128-col span
    #pragma unroll
    for (int mt = 0; mt < 2; mt++)
        #pragma unroll
        for (int h = 0; h < 2; h++) {
            float bv = -FLT_MAX; int bi = 0;
            #pragma unroll
            for (int np = 0; np < 8; np++)
                #pragma unroll
                for (int e = 0; e < 2; e++) {
                    float v = acc[mt][np][h * 2 + e];
                    int c = col0 + n0w + np * 8 + tig * 2 + e;
                    if (v > bv) { bv = v; bi = c; }
                }
            #pragma unroll
            for (int o = 1; o <= 2; o <<= 1) {
                float v2 = __shfl_xor_sync(0xffffffffu, bv, o);
                int i2 = __shfl_xor_sync(0xffffffffu, bi, o);
                if (v2 > bv || (v2 == bv && i2 < bi)) { bv = v2; bi = i2; }
            }
            if (tig == 0) {
                int rl = m0w + mt * 16 + h * 8 + gid;
                s_rv[wid >> 2][rl] = bv;
                s_ri[wid >> 2][rl] = bi;
            }
        }
    // col-max partials over this 128-row span
    #pragma unroll
    for (int np = 0; np < 8; np++)
        #pragma unroll
        for (int e = 0; e < 2; e++) {
            float bv = -FLT_MAX; int bi = 0;
            #pragma unroll
            for (int mt = 0; mt < 2; mt++)
                #pragma unroll
                for (int h = 0; h < 2; h++) {
                    float v = acc[mt][np][h * 2 + e];
                    int r = m0 + m0w + mt * 16 + h * 8 + gid;
                    if (v > bv) { bv = v; bi = r; }
                }
            #pragma unroll
            for (int o = 4; o <= 16; o <<= 1) {
                float v2 = __shfl_xor_sync(0xffffffffu, bv, o);
                int i2 = __shfl_xor_sync(0xffffffffu, bi, o);
                if (v2 > bv || (v2 == bv && i2 < bi)) { bv = v2; bi = i2; }
            }
            if (gid == 0) {
                int cl = n0w + np * 8 + tig * 2 + e;
                s_cv[wid & 3][cl] = bv;
                s_ci[wid & 3][cl] = bi;
            }
        }
    __syncthreads();
    if (t < 128) {
        float bv = s_rv[0][t]; int bi = s_ri[0][t];
        if (s_rv[1][t] > bv || (s_rv[1][t] == bv && s_ri[1][t] < bi)) { bv = s_rv[1][t]; bi = s_ri[1][t]; }
        g_rowmax_part[blockIdx.x * NN + m0 + t] = bv;
        g_rowidx_part[blockIdx.x * NN + m0 + t] = bi;
        float cv = s_cv[0][t]; int ci = s_ci[0][t];
        #pragma unroll
        for (int w = 1; w < 4; w++) {
            if (s_cv[w][t] > cv || (s_cv[w][t] == cv && s_ci[w][t] < ci)) { cv = s_cv[w][t]; ci = s_ci[w][t]; }
        }
        g_colmax_part[blockIdx.y * NN + col0 + t] = cv;
        g_colidx_part[blockIdx.y * NN + col0 + t] = ci;
    }
}

// ---------------- max reduce ----------------
__global__ void __launch_bounds__(256) maxreduce_kernel() {
    int n = blockIdx.x * 256 + threadIdx.x;
    float bm = g_rowmax_part[n]; int bi = g_rowidx_part[n];
    for (int s = 1; s < 32; s++) {
        float v = g_rowmax_part[s * NN + n];
        int i2 = g_rowidx_part[s * NN + n];
        if (v > bm || (v == bm && i2 < bi)) { bm = v; bi = i2; }
    }
    g_rowmax[n] = bm; g_rowidx[n] = bi;
    bm = g_colmax_part[n]; bi = g_colidx_part[n];
    for (int s = 1; s < 32; s++) {
        float v = g_colmax_part[s * NN + n];
        int i2 = g_colidx_part[s * NN + n];
        if (v > bm || (v == bm && i2 < bi)) { bm = v; bi = i2; }
    }
    g_colmax[n] = bm; g_colidx[n] = bi;
}

// ---------------- mutual compaction ----------------
__device__ __forceinline__ int mutual_flag(int b, int t) {
    if (b < 32) { int n = b * 128 + t; return g_colidx[g_rowidx[n]] == n; }
    else        { int m = (b - 32) * 128 + t; return g_rowidx[g_colidx[m]] == m; }
}

__global__ void __launch_bounds__(128) countseg_kernel() {
    int b = blockIdx.x, t = threadIdx.x;
    __shared__ int sc[128];
    sc[t] = mutual_flag(b, t);
    __syncthreads();
    for (int off = 64; off > 0; off >>= 1) {
        if (t < off) sc[t] += sc[t + off];
        __syncthreads();
    }
    if (t == 0) g_segcnt[b] = sc[0];
}

__global__ void scanseg_kernel() {
    if (threadIdx.x == 0) {
        int off = 0;
        for (int s = 0; s < 32; s++) { g_segoff[s] = off; off += g_segcnt[s]; }
        g_nsel[0] = off;
        off = 0;
        for (int s = 32; s < 64; s++) { g_segoff[s] = off; off += g_segcnt[s]; }
        g_nsel[1] = off;
    }
}

__global__ void __launch_bounds__(128) fillseg_kernel() {
    int b = blockIdx.x, t = threadIdx.x;
    int flag = mutual_flag(b, t);
    __shared__ int sc[128];
    sc[t] = flag;
    __syncthreads();
    for (int off = 1; off < 128; off <<= 1) {
        int v = (t >= off) ? sc[t - off] : 0;
        __syncthreads();
        sc[t] += v;
        __syncthreads();
    }
    if (flag) {
        int rank = sc[t] - 1;
        int idx = (b & 31) * 128 + t;
        if (b < 32) g_rowlist[g_segoff[b] + rank] = idx;
        else        g_collist[g_segoff[b] + rank] = idx;
    }
}

// ---------------- selected row exp -> bf16 split + sum ----------------
__global__ void __launch_bounds__(256) rowexp_sel_kernel() {
    int b = blockIdx.x;
    if (b >= g_nsel[0]) return;
    int row = g_rowlist[b];
    int tid = threadIdx.x;
    const float* srow = g_sim + (size_t)row * NN;
    __nv_bfloat16* ph = g_p_h + (size_t)row * NN;
    __nv_bfloat16* pr = g_p_r + (size_t)row * NN;
    float rmax = g_rowmax[row];
    float lsum = 0.0f;
    #pragma unroll
    for (int s = 0; s < 16; s++) {
        int idx = tid + 256 * s;
        float e = fast_exp(srow[idx] - rmax);
        lsum += e;
        __nv_bfloat16 h = __float2bfloat16_rn(e);
        ph[idx] = h;
        pr[idx] = __float2bfloat16_rn(e - __bfloat162float(h));
    }
    __shared__ float sv[256];
    sv[tid] = lsum;
    __syncthreads();
    for (int off = 128; off > 0; off >>= 1) {
        if (tid < off) sv[tid] += sv[tid + off];
        __syncthreads();
    }
    if (tid == 0) g_rowsum[row] = sv[0];
}

// ---------------- transposed col exp (flag-gated writes) ----------------
__global__ void __launch_bounds__(256) transpose_exp_kernel() {
    __shared__ float tile[32][33];
    __shared__ int s_flag[32];
    __shared__ int s_any;
    int m0 = blockIdx.x * 32;
    int k0 = blockIdx.y * 32;
    int tx = threadIdx.x & 31;
    int ty = threadIdx.x >> 5;
    if (threadIdx.x < 32) {
        int m = m0 + threadIdx.x;
        int f = (g_rowidx[g_colidx[m]] == m);
        s_flag[threadIdx.x] = f;
        unsigned bal = __ballot_sync(0xffffffffu, f);
        if (threadIdx.x == 0) s_any = (bal != 0u);
    }
    __syncthreads();
    if (!s_any) return;
    #pragma unroll
    for (int qq = 0; qq < 4; qq++) {
        int r = ty * 4 + qq;
        tile[r][tx] = g_sim[(size_t)(k0 + r) * NN + m0 + tx];
    }
    __syncthreads();
    #pragma unroll
    for (int qq = 0; qq < 4; qq++) {
        int r = ty * 4 + qq;
        if (!s_flag[r]) continue;
        float e = fast_exp(tile[tx][r] - g_colmax[m0 + r]);
        __nv_bfloat16 h = __float2bfloat16_rn(e);
        size_t off = (size_t)(m0 + r) * NN + k0 + tx;
        g_pT_h[off] = h;
        g_pT_r[off] = __float2bfloat16_rn(e - __bfloat162float(h));
    }
}

// ---------------- selected col sums ----------------
__global__ void __launch_bounds__(256) colsum_sel_kernel() {
    int b = blockIdx.x;
    if (b >= g_nsel[1]) return;
    int m = g_collist[b];
    int tid = threadIdx.x;
    const __nv_bfloat16* ph = g_pT_h + (size_t)m * NN;
    const __nv_bfloat16* pr = g_pT_r + (size_t)m * NN;
    float lsum = 0.0f;
    #pragma unroll
    for (int s = 0; s < 16; s++) {
        int idx = tid + 256 * s;
        lsum += __bfloat162float(ph[idx]) + __bfloat162float(pr[idx]);
    }
    __shared__ float sv[256];
    sv[tid] = lsum;
    __syncthreads();
    for (int off = 128; off > 0; off >>= 1) {
        if (tid < off) sv[tid] += sv[tid + off];
        __syncthreads();
    }
    if (tid == 0) g_colsum[m] = sv[0];
}

// ---------------- weighted bf16 MMA: gathered rows, split-K ----------------
// grid (2, 32, SPLITK): bx = n tile (128 of 256), by = slot tile (128), bz = split.
// Virtual K = 3*4096; chunk = 1536 per split.
__global__ void __launch_bounds__(256) gemm_w_kernel(
    const __nv_bfloat16* __restrict__ Ph, const __nv_bfloat16* __restrict__ Pr,
    const __nv_bfloat16* __restrict__ Sh, const __nv_bfloat16* __restrict__ Sr,
    const int* __restrict__ list, const int* __restrict__ cntp)
{
    const int m0 = blockIdx.y * 128;
    if (m0 >= *cntp) return;
    __shared__ __align__(16) char sm[2][16384];

    const int t = threadIdx.x;
    const int lane = t & 31, wid = t >> 5;
    const int m0w = (wid & 3) * 32, n0w = (wid >> 2) * 64;
    const int n0 = blockIdx.x * 128;
    const int kbase = blockIdx.z * 1536;
    const int lrow = t >> 2, q = t & 3;
    const uint32_t sbase = smem_u32(&sm[0][0]);

    const int grow0 = list[m0 + lrow];
    const int grow1 = list[m0 + lrow + 64];

    float acc[2][8][4];
    #pragma unroll
    for (int a = 0; a < 2; a++)
        #pragma unroll
        for (int b = 0; b < 8; b++)
            #pragma unroll
            for (int c = 0; c < 4; c++) acc[a][b][c] = 0.0f;

    uint4 ra0, ra1, rb0, rb1;
    #define W_LDG(KB) do { \
        int kg = kbase + (KB) * 32; \
        int seg = kg >> 12; \
        int kk = kg & 4095; \
        const __nv_bfloat16* ap = (seg == 2) ? Pr : Ph; \
        const __nv_bfloat16* bp = (seg == 1) ? Sr : Sh; \
        ra0 = *(const uint4*)(ap + (size_t)grow0 * NN + kk + q * 8); \
        ra1 = *(const uint4*)(ap + (size_t)grow1 * NN + kk + q * 8); \
        rb0 = *(const uint4*)(bp + (size_t)(n0 + lrow) * NN + kk + q * 8); \
        rb1 = *(const uint4*)(bp + (size_t)(n0 + lrow + 64) * NN + kk + q * 8); \
    } while (0)
    #define W_STS(BUF) do { \
        char* base = &sm[BUF][0]; \
        *(uint4*)(base + swz64(lrow, q)) = ra0; \
        *(uint4*)(base + swz64(lrow + 64, q)) = ra1; \
        *(uint4*)(base + 8192 + swz64(lrow, q)) = rb0; \
        *(uint4*)(base + 8192 + swz64(lrow + 64, q)) = rb1; \
    } while (0)

    W_LDG(0);
    W_STS(0);
    __syncthreads();
    for (int kb = 0; kb < 48; kb++) {
        int buf = kb & 1;
        if (kb + 1 < 48) W_LDG(kb + 1);
        mma_block(sbase + buf * 16384, sbase + buf * 16384 + 8192, lane, m0w, n0w, acc);
        if (kb + 1 < 48) W_STS(buf ^ 1);
        __syncthreads();
    }
    #undef W_LDG
    #undef W_STS

    const int gid = lane >> 2, tig = lane & 3;
    float* Cp0 = g_cpart + (size_t)blockIdx.z * NN * CC;
    #pragma unroll
    for (int mt = 0; mt < 2; mt++) {
        int r0 = m0 + m0w + mt * 16 + gid;
        #pragma unroll
        for (int np = 0; np < 8; np++) {
            int c = n0 + n0w + np * 8 + tig * 2;
            *(float2*)&Cp0[(size_t)r0 * CC + c] = make_float2(acc[mt][np][0], acc[mt][np][1]);
            *(float2*)&Cp0[(size_t)(r0 + 8) * CC + c] = make_float2(acc[mt][np][2], acc[mt][np][3]);
        }
    }
}

// ---------------- split-K reduce (selected slots) ----------------
__global__ void __launch_bounds__(256) reduce_sel_kernel(
    float* __restrict__ soft, const float* __restrict__ den,
    const int* __restrict__ list, const int* __restrict__ cntp)
{
    int slot = blockIdx.x;
    if (slot >= *cntp) return;
    int row = list[slot];
    int c = threadIdx.x;
    float s = 0.0f;
    #pragma unroll
    for (int z = 0; z < SPLITK; z++)
        s += g_cpart[(size_t)z * NN * CC + (size_t)slot * CC + c];
    soft[(size_t)row * CC + c] = s / den[row];
}

// ---------------- loss + finalize ----------------
__global__ void __launch_bounds__(256) loss_kernel(
    const int* __restrict__ idxA, const int* __restrict__ idxB,
    const float* __restrict__ soft, const float* __restrict__ recon, int op)
{
    int tid = threadIdx.x;
    int b = blockIdx.x;
    float relc = g_relWT[op * CC + tid];
    float lsum = 0.0f;
    int lcnt = 0;
    for (int r = 0; r < 128; r++) {
        int row = b * 128 + r;
        int a = idxA[row];
        if (idxB[a] == row) {
            float d = recon[(size_t)row * CC + tid] + relc - soft[(size_t)row * CC + tid];
            lsum += d * d;
            if (tid == 0) lcnt++;
        }
    }
    __shared__ float ss[256];
    ss[tid] = lsum;
    __syncthreads();
    for (int off = 128; off > 0; off >>= 1) {
        if (tid < off) ss[tid] += ss[tid + off];
        __syncthreads();
    }
    if (tid == 0) {
        g_sq_part[op * 32 + b] = ss[0];
        g_cnt_part[op * 32 + b] = lcnt;
    }
}

__global__ void finalize_kernel(float* __restrict__ out) {
    if (threadIdx.x == 0) {
        float total = 0.0f, count = 0.0f;
        for (int op = 0; op < 12; op++) {
            float sq = 0.0f;
            int cnt = 0;
            for (int b = 0; b < 32; b++) {
                sq += g_sq_part[op * 32 + b];
                cnt += g_cnt_part[op * 32 + b];
            }
            if (cnt > 0) {
                total += sq / fmaxf((float)cnt * (float)CC, 1.0f);
                count += 1.0f;
            }
        }
        out[0] = (count > 0.0f) ? (total / fmaxf(count, 1.0f)) : 0.0f;
    }
}

// ---------------- host launch ----------------
extern "C" void kernel_launch(void* const* d_in, const int* in_sizes, int n_in,
                              void* d_out, int out_size)
{
    const float* desc  = (const float*)d_in[0];
    const float* sf    = (const float*)d_in[1];
    const float* T     = (const float*)d_in[2];
    const float* W_rec = (const float*)d_in[3];
    const float* W_T   = (const float*)d_in[4];
    float* out = (float*)d_out;

    float *recon, *rowsum, *colsum, *soft_row, *soft_col;
    __nv_bfloat16 *dnh, *dnr, *sfh, *sfr, *ph, *pr, *pth, *ptr_;
    int *rowidx, *colidx, *rowlist, *collist, *nsel;
    cudaGetSymbolAddress((void**)&recon, g_recon);
    cudaGetSymbolAddress((void**)&rowsum, g_rowsum);
    cudaGetSymbolAddress((void**)&colsum, g_colsum);
    cudaGetSymbolAddress((void**)&soft_row, g_soft_row);
    cudaGetSymbolAddress((void**)&soft_col, g_soft_col);
    cudaGetSymbolAddress((void**)&dnh, g_dnb_h);
    cudaGetSymbolAddress((void**)&dnr, g_dnb_r);
    cudaGetSymbolAddress((void**)&sfh, g_sfT_h);
    cudaGetSymbolAddress((void**)&sfr, g_sfT_r);
    cudaGetSymbolAddress((void**)&ph, g_p_h);
    cudaGetSymbolAddress((void**)&pr, g_p_r);
    cudaGetSymbolAddress((void**)&pth, g_pT_h);
    cudaGetSymbolAddress((void**)&ptr_, g_pT_r);
    cudaGetSymbolAddress((void**)&rowidx, g_rowidx);
    cudaGetSymbolAddress((void**)&colidx, g_colidx);
    cudaGetSymbolAddress((void**)&rowlist, g_rowlist);
    cudaGetSymbolAddress((void**)&collist, g_collist);
    cudaGetSymbolAddress((void**)&nsel, g_nsel);

    normalize_kernel<<<NN * VV, 256>>>(desc);
    sf_split_kernel<<<dim3(NN / 32, CC / 32, VV), 256>>>(sf);
    relwt_kernel<<<12, 256>>>(T, W_T);
    recon_gemm_kernel<<<dim3(CC / 64, NN / 128, VV), 256>>>(W_rec);

    auto OP = [](int i, int j) { return i * 3 + (j < i ? j : j - 1); };

    for (int i = 0; i < VV; i++) {
        for (int j = i + 1; j < VV; j++) {
            size_t oi = (size_t)i * NN * CC, oj = (size_t)j * NN * CC;
            sim_bf16_kernel<<<dim3(32, 32), 256>>>(dnh + oi, dnr + oi, dnh + oj, dnr + oj);
            maxreduce_kernel<<<16, 256>>>();

            countseg_kernel<<<64, 128>>>();
            scanseg_kernel<<<1, 32>>>();
            cudaMemsetAsync(rowlist, 0, NN * sizeof(int));
            cudaMemsetAsync(collist, 0, NN * sizeof(int));
            fillseg_kernel<<<64, 128>>>();

            // row direction (i,j): P rows over sim rows, targets sf[:,j]
            rowexp_sel_kernel<<<NN, 256>>>();
            gemm_w_kernel<<<dim3(2, 32, SPLITK), 256>>>(
                ph, pr, sfh + (size_t)j * CC * NN, sfr + (size_t)j * CC * NN,
                rowlist, nsel + 0);
            reduce_sel_kernel<<<NN, 256>>>(soft_row, rowsum, rowlist, nsel + 0);

            // col direction (j,i)
            transpose_exp_kernel<<<dim3(NN / 32, NN / 32), 256>>>();
            colsum_sel_kernel<<<NN, 256>>>();
            gemm_w_kernel<<<dim3(2, 32, SPLITK), 256>>>(
                pth, ptr_, sfh + (size_t)i * CC * NN, sfr + (size_t)i * CC * NN,
                collist, nsel + 1);
            reduce_sel_kernel<<<NN, 256>>>(soft_col, colsum, collist, nsel + 1);

            loss_kernel<<<32, 256>>>(rowidx, colidx, soft_row, recon + oi, OP(i, j));
            loss_kernel<<<32, 256>>>(colidx, rowidx, soft_col, recon + oj, OP(j, i));
        }
    }

    finalize_kernel<<<1, 32>>>(out);
}

// round 7
// speedup vs baseline: 1.6873x; 1.0305x over previous
#include <cuda_runtime.h>
#include <cuda_bf16.h>
#include <cfloat>
#include <cstddef>
#include <cstdint>

#define NN 4096
#define CC 256
#define VV 4
#define SPLITK 8

// ---------------- scratch ----------------
__device__ __nv_bfloat16 g_dnb_h[VV * NN * CC];
__device__ __nv_bfloat16 g_dnb_r[VV * NN * CC];
__device__ __nv_bfloat16 g_sfT_h[VV * CC * NN];
__device__ __nv_bfloat16 g_sfT_r[VV * CC * NN];
__device__ __nv_bfloat16 g_wrT_h[CC * CC];
__device__ __nv_bfloat16 g_wrT_r[CC * CC];
__device__ float g_recon[VV * NN * CC];
__device__ float g_relWT[12 * CC];
__device__ float g_sim[(size_t)NN * NN];
__device__ __nv_bfloat16 g_p_h[(size_t)NN * NN];
__device__ __nv_bfloat16 g_p_r[(size_t)NN * NN];
__device__ __nv_bfloat16 g_pT_h[(size_t)NN * NN];
__device__ __nv_bfloat16 g_pT_r[(size_t)NN * NN];
__device__ float g_cpart[(size_t)(2 * SPLITK) * NN * CC];

__device__ float g_rowmax_part[32 * NN];
__device__ int   g_rowidx_part[32 * NN];
__device__ float g_colmax_part[32 * NN];
__device__ int   g_colidx_part[32 * NN];
__device__ float g_rowmax[NN];
__device__ int   g_rowidx[NN];
__device__ float g_colmax[NN];
__device__ int   g_colidx[NN];
__device__ float g_rowsum[NN];
__device__ float g_colsum[NN];

__device__ int   g_rowlist[NN];
__device__ int   g_collist[NN];
__device__ int   g_nsel[2];

__device__ float g_soft_row[NN * CC];
__device__ float g_soft_col[NN * CC];
__device__ float g_sq_part[12 * 32];
__device__ int   g_cnt_part[12 * 32];

__constant__ int c_OPI[12] = {0,0,0,1,1,1,2,2,2,3,3,3};
__constant__ int c_OPJ[12] = {1,2,3,0,2,3,0,1,3,0,1,2};

// ---------------- helpers ----------------
__device__ __forceinline__ uint32_t smem_u32(const void* p) {
    uint32_t a;
    asm("{ .reg .u64 t; cvta.to.shared.u64 t, %1; cvt.u32.u64 %0, t; }" : "=r"(a) : "l"(p));
    return a;
}
__device__ __forceinline__ uint32_t swz64(int row, int kc) {
    return (uint32_t)(row * 64) + (uint32_t)(((kc ^ ((row >> 1) & 3)) & 3) << 4);
}
__device__ __forceinline__ void ldm_x4(uint32_t addr, uint32_t& r0, uint32_t& r1,
                                       uint32_t& r2, uint32_t& r3) {
    asm volatile("ldmatrix.sync.aligned.m8n8.x4.shared.b16 {%0,%1,%2,%3}, [%4];"
        : "=r"(r0), "=r"(r1), "=r"(r2), "=r"(r3) : "r"(addr));
}
__device__ __forceinline__ void mma_bf16(float* c, const uint32_t* a, uint32_t b0, uint32_t b1) {
    asm volatile("mma.sync.aligned.m16n8k16.row.col.f32.bf16.bf16.f32 "
        "{%0,%1,%2,%3}, {%4,%5,%6,%7}, {%8,%9}, {%0,%1,%2,%3};"
        : "+f"(c[0]), "+f"(c[1]), "+f"(c[2]), "+f"(c[3])
        : "r"(a[0]), "r"(a[1]), "r"(a[2]), "r"(a[3]), "r"(b0), "r"(b1));
}
__device__ __forceinline__ float fast_exp(float x) {
    float y = x * 1.4426950408889634f;
    float n = rintf(y);
    float f = y - n;
    float r = 0.0001540353039338f;
    r = r * f + 0.0013333558146428f;
    r = r * f + 0.0096181291076285f;
    r = r * f + 0.0555041086648216f;
    r = r * f + 0.2402265069591007f;
    r = r * f + 0.6931471805599453f;
    r = r * f + 1.0f;
    return __int_as_float(__float_as_int(r) + ((int)n << 23));
}

// warp-level MMA on one 32x64 warp-tile over a 32-K smem block
__device__ __forceinline__ void mma_block(uint32_t sA, uint32_t sB, int lane,
                                          int m0w, int n0w, float acc[2][8][4]) {
    const int arow = m0w + (lane & 7) + ((lane >> 3) & 1) * 8;
    const int akc  = lane >> 4;
    const int brow = n0w + (lane & 7) + (lane >> 4) * 8;
    const int bkc  = (lane >> 3) & 1;
    #pragma unroll
    for (int ks = 0; ks < 2; ks++) {
        uint32_t a[2][4];
        #pragma unroll
        for (int mt = 0; mt < 2; mt++)
            ldm_x4(sA + swz64(arow + mt * 16, ks * 2 + akc),
                   a[mt][0], a[mt][1], a[mt][2], a[mt][3]);
        #pragma unroll
        for (int np = 0; np < 4; np++) {
            uint32_t b0, b1, b2, b3;
            ldm_x4(sB + swz64(brow + np * 16, ks * 2 + bkc), b0, b1, b2, b3);
            #pragma unroll
            for (int mt = 0; mt < 2; mt++) {
                mma_bf16(acc[mt][np * 2],     a[mt], b0, b1);
                mma_bf16(acc[mt][np * 2 + 1], a[mt], b2, b3);
            }
        }
    }
}

// ---------------- normalize + 2-way bf16 split ----------------
__global__ void __launch_bounds__(256) normalize_kernel(const float* __restrict__ desc) {
    int rv = blockIdx.x;
    int tid = threadIdx.x;
    __shared__ float ss[256];
    float x = desc[(size_t)rv * CC + tid];
    ss[tid] = x * x;
    __syncthreads();
    for (int off = 128; off > 0; off >>= 1) {
        if (tid < off) ss[tid] += ss[tid + off];
        __syncthreads();
    }
    float den = fmaxf(sqrtf(ss[0]), 1e-12f);
    float y = x / den;
    int n = rv / VV, v = rv % VV;
    __nv_bfloat16 h = __float2bfloat16_rn(y);
    size_t off = (size_t)(v * NN + n) * CC + tid;
    g_dnb_h[off] = h;
    g_dnb_r[off] = __float2bfloat16_rn(y - __bfloat162float(h));
}

// ---------------- sf transpose + split ----------------
__global__ void __launch_bounds__(256) sf_split_kernel(const float* __restrict__ sf) {
    __shared__ float t[32][33];
    int v = blockIdx.z;
    int n0 = blockIdx.x * 32, c0 = blockIdx.y * 32;
    int tx = threadIdx.x & 31, ty = threadIdx.x >> 5;
    #pragma unroll
    for (int q = 0; q < 4; q++) {
        int r = ty * 4 + q;
        t[r][tx] = sf[(size_t)(n0 + r) * (VV * CC) + v * CC + c0 + tx];
    }
    __syncthreads();
    #pragma unroll
    for (int q = 0; q < 4; q++) {
        int r = ty * 4 + q;
        float x = t[tx][r];
        __nv_bfloat16 h = __float2bfloat16_rn(x);
        size_t off = (size_t)v * CC * NN + (size_t)(c0 + r) * NN + n0 + tx;
        g_sfT_h[off] = h;
        g_sfT_r[off] = __float2bfloat16_rn(x - __bfloat162float(h));
    }
}

// ---------------- W_rec transpose + split ----------------
__global__ void __launch_bounds__(256) wr_split_kernel(const float* __restrict__ W) {
    __shared__ float t[32][33];
    int k0 = blockIdx.y * 32, c0 = blockIdx.x * 32;
    int tx = threadIdx.x & 31, ty = threadIdx.x >> 5;
    #pragma unroll
    for (int q = 0; q < 4; q++) {
        int r = ty * 4 + q;
        t[r][tx] = W[(size_t)(k0 + r) * CC + c0 + tx];
    }
    __syncthreads();
    #pragma unroll
    for (int q = 0; q < 4; q++) {
        int r = ty * 4 + q;
        float x = t[tx][r];
        __nv_bfloat16 h = __float2bfloat16_rn(x);
        size_t off = (size_t)(c0 + r) * CC + k0 + tx;
        g_wrT_h[off] = h;
        g_wrT_r[off] = __float2bfloat16_rn(x - __bfloat162float(h));
    }
}

// ---------------- relWT ----------------
__global__ void __launch_bounds__(256) relwt_kernel(const float* __restrict__ T,
                                                    const float* __restrict__ WT) {
    int op = blockIdx.x;
    int c = threadIdx.x;
    int i = c_OPI[op], j = c_OPJ[op];
    float s = 0.0f;
    #pragma unroll
    for (int k = 0; k < 16; k++) s += T[i * 16 + k] * WT[k * CC + c];
    #pragma unroll
    for (int k = 0; k < 16; k++) s += T[j * 16 + k] * WT[(16 + k) * CC + c];
    g_relWT[op * CC + c] = s;
}

// ---------------- recon bf16 MMA: recon[v] = dn_v @ W_rec (3-term) -------------
// grid (2, 32, VV)
__global__ void __launch_bounds__(256) recon_mma_kernel() {
    __shared__ __align__(16) char sm[2][16384];
    const int t = threadIdx.x;
    const int lane = t & 31, wid = t >> 5;
    const int m0w = (wid & 3) * 32, n0w = (wid >> 2) * 64;
    const int v = blockIdx.z;
    const int m0 = blockIdx.y * 128, n0 = blockIdx.x * 128;
    const int lrow = t >> 2, q = t & 3;
    const uint32_t sbase = smem_u32(&sm[0][0]);
    const __nv_bfloat16* Ah = g_dnb_h + (size_t)v * NN * CC;
    const __nv_bfloat16* Ar = g_dnb_r + (size_t)v * NN * CC;

    float acc[2][8][4];
    #pragma unroll
    for (int a = 0; a < 2; a++)
        #pragma unroll
        for (int b = 0; b < 8; b++)
            #pragma unroll
            for (int c = 0; c < 4; c++) acc[a][b][c] = 0.0f;

    uint4 ra0, ra1, rb0, rb1;
    #define R_LDG(KB) do { \
        int seg = (KB) >> 3; \
        int kk = ((KB) & 7) << 5; \
        const __nv_bfloat16* ap = (seg == 2) ? Ar : Ah; \
        const __nv_bfloat16* bp = (seg == 1) ? g_wrT_r : g_wrT_h; \
        ra0 = *(const uint4*)(ap + (size_t)(m0 + lrow) * CC + kk + q * 8); \
        ra1 = *(const uint4*)(ap + (size_t)(m0 + lrow + 64) * CC + kk + q * 8); \
        rb0 = *(const uint4*)(bp + (size_t)(n0 + lrow) * CC + kk + q * 8); \
        rb1 = *(const uint4*)(bp + (size_t)(n0 + lrow + 64) * CC + kk + q * 8); \
    } while (0)
    #define R_STS(BUF) do { \
        char* base = &sm[BUF][0]; \
        *(uint4*)(base + swz64(lrow, q)) = ra0; \
        *(uint4*)(base + swz64(lrow + 64, q)) = ra1; \
        *(uint4*)(base + 8192 + swz64(lrow, q)) = rb0; \
        *(uint4*)(base + 8192 + swz64(lrow + 64, q)) = rb1; \
    } while (0)

    R_LDG(0);
    R_STS(0);
    __syncthreads();
    for (int kb = 0; kb < 24; kb++) {
        int buf = kb & 1;
        if (kb + 1 < 24) R_LDG(kb + 1);
        mma_block(sbase + buf * 16384, sbase + buf * 16384 + 8192, lane, m0w, n0w, acc);
        if (kb + 1 < 24) R_STS(buf ^ 1);
        __syncthreads();
    }
    #undef R_LDG
    #undef R_STS

    const int gid = lane >> 2, tig = lane & 3;
    float* C = g_recon + (size_t)v * NN * CC;
    #pragma unroll
    for (int mt = 0; mt < 2; mt++) {
        int r0 = m0 + m0w + mt * 16 + gid;
        #pragma unroll
        for (int np = 0; np < 8; np++) {
            int c = n0 + n0w + np * 8 + tig * 2;
            *(float2*)&C[(size_t)r0 * CC + c] = make_float2(acc[mt][np][0], acc[mt][np][1]);
            *(float2*)&C[(size_t)(r0 + 8) * CC + c] = make_float2(acc[mt][np][2], acc[mt][np][3]);
        }
    }
}

// ---------------- sim bf16 MMA + fused row/col max partials ----------------
__global__ void __launch_bounds__(256) sim_bf16_kernel(
    const __nv_bfloat16* __restrict__ Ah, const __nv_bfloat16* __restrict__ Ar,
    const __nv_bfloat16* __restrict__ Bh, const __nv_bfloat16* __restrict__ Br)
{
    __shared__ __align__(16) char sm[2][16384];
    __shared__ float s_rv[2][128];
    __shared__ int   s_ri[2][128];
    __shared__ float s_cv[4][128];
    __shared__ int   s_ci[4][128];

    const int t = threadIdx.x;
    const int lane = t & 31, wid = t >> 5;
    const int m0w = (wid & 3) * 32, n0w = (wid >> 2) * 64;
    const int m0 = blockIdx.y * 128, col0 = blockIdx.x * 128;
    const int lrow = t >> 2, q = t & 3;
    const uint32_t sbase = smem_u32(&sm[0][0]);

    float acc[2][8][4];
    #pragma unroll
    for (int a = 0; a < 2; a++)
        #pragma unroll
        for (int b = 0; b < 8; b++)
            #pragma unroll
            for (int c = 0; c < 4; c++) acc[a][b][c] = 0.0f;

    uint4 ra0, ra1, rb0, rb1;
    #define SIM_LDG(KB) do { \
        int kk = ((KB) & 7) << 5; \
        const __nv_bfloat16* ap = ((KB) >= 16) ? Ar : Ah; \
        const __nv_bfloat16* bp = ((KB) & 8) ? Br : Bh; \
        ra0 = *(const uint4*)(ap + (size_t)(m0 + lrow) * CC + kk + q * 8); \
        ra1 = *(const uint4*)(ap + (size_t)(m0 + lrow + 64) * CC + kk + q * 8); \
        rb0 = *(const uint4*)(bp + (size_t)(col0 + lrow) * CC + kk + q * 8); \
        rb1 = *(const uint4*)(bp + (size_t)(col0 + lrow + 64) * CC + kk + q * 8); \
    } while (0)
    #define SIM_STS(BUF) do { \
        char* base = &sm[BUF][0]; \
        *(uint4*)(base + swz64(lrow, q)) = ra0; \
        *(uint4*)(base + swz64(lrow + 64, q)) = ra1; \
        *(uint4*)(base + 8192 + swz64(lrow, q)) = rb0; \
        *(uint4*)(base + 8192 + swz64(lrow + 64, q)) = rb1; \
    } while (0)

    SIM_LDG(0);
    SIM_STS(0);
    __syncthreads();
    for (int kb = 0; kb < 32; kb++) {
        int buf = kb & 1;
        if (kb + 1 < 32) SIM_LDG(kb + 1);
        mma_block(sbase + buf * 16384, sbase + buf * 16384 + 8192, lane, m0w, n0w, acc);
        if (kb + 1 < 32) SIM_STS(buf ^ 1);
        __syncthreads();
    }
    #undef SIM_LDG
    #undef SIM_STS

    const int gid = lane >> 2, tig = lane & 3;
    #pragma unroll
    for (int mt = 0; mt < 2; mt++) {
        int r0 = m0 + m0w + mt * 16 + gid;
        #pragma unroll
        for (int np = 0; np < 8; np++) {
            int c = col0 + n0w + np * 8 + tig * 2;
            *(float2*)&g_sim[(size_t)r0 * NN + c] = make_float2(acc[mt][np][0], acc[mt][np][1]);
            *(float2*)&g_sim[(size_t)(r0 + 8) * NN + c] = make_float2(acc[mt][np][2], acc[mt][np][3]);
        }
    }
    #pragma unroll
    for (int mt = 0; mt < 2; mt++)
        #pragma unroll
        for (int h = 0; h < 2; h++) {
            float bv = -FLT_MAX; int bi = 0;
            #pragma unroll
            for (int np = 0; np < 8; np++)
                #pragma unroll
                for (int e = 0; e < 2; e++) {
                    float v = acc[mt][np][h * 2 + e];
                    int c = col0 + n0w + np * 8 + tig * 2 + e;
                    if (v > bv) { bv = v; bi = c; }
                }
            #pragma unroll
            for (int o = 1; o <= 2; o <<= 1) {
                float v2 = __shfl_xor_sync(0xffffffffu, bv, o);
                int i2 = __shfl_xor_sync(0xffffffffu, bi, o);
                if (v2 > bv || (v2 == bv && i2 < bi)) { bv = v2; bi = i2; }
            }
            if (tig == 0) {
                int rl = m0w + mt * 16 + h * 8 + gid;
                s_rv[wid >> 2][rl] = bv;
                s_ri[wid >> 2][rl] = bi;
            }
        }
    #pragma unroll
    for (int np = 0; np < 8; np++)
        #pragma unroll
        for (int e = 0; e < 2; e++) {
            float bv = -FLT_MAX; int bi = 0;
            #pragma unroll
            for (int mt = 0; mt < 2; mt++)
                #pragma unroll
                for (int h = 0; h < 2; h++) {
                    float v = acc[mt][np][h * 2 + e];
                    int r = m0 + m0w + mt * 16 + h * 8 + gid;
                    if (v > bv) { bv = v; bi = r; }
                }
            #pragma unroll
            for (int o = 4; o <= 16; o <<= 1) {
                float v2 = __shfl_xor_sync(0xffffffffu, bv, o);
                int i2 = __shfl_xor_sync(0xffffffffu, bi, o);
                if (v2 > bv || (v2 == bv && i2 < bi)) { bv = v2; bi = i2; }
            }
            if (gid == 0) {
                int cl = n0w + np * 8 + tig * 2 + e;
                s_cv[wid & 3][cl] = bv;
                s_ci[wid & 3][cl] = bi;
            }
        }
    __syncthreads();
    if (t < 128) {
        float bv = s_rv[0][t]; int bi = s_ri[0][t];
        if (s_rv[1][t] > bv || (s_rv[1][t] == bv && s_ri[1][t] < bi)) { bv = s_rv[1][t]; bi = s_ri[1][t]; }
        g_rowmax_part[blockIdx.x * NN + m0 + t] = bv;
        g_rowidx_part[blockIdx.x * NN + m0 + t] = bi;
        float cv = s_cv[0][t]; int ci = s_ci[0][t];
        #pragma unroll
        for (int w = 1; w < 4; w++) {
            if (s_cv[w][t] > cv || (s_cv[w][t] == cv && s_ci[w][t] < ci)) { cv = s_cv[w][t]; ci = s_ci[w][t]; }
        }
        g_colmax_part[blockIdx.y * NN + col0 + t] = cv;
        g_colidx_part[blockIdx.y * NN + col0 + t] = ci;
    }
}

// ---------------- max reduce ----------------
__global__ void __launch_bounds__(256) maxreduce_kernel() {
    int n = blockIdx.x * 256 + threadIdx.x;
    float bm = g_rowmax_part[n]; int bi = g_rowidx_part[n];
    for (int s = 1; s < 32; s++) {
        float v = g_rowmax_part[s * NN + n];
        int i2 = g_rowidx_part[s * NN + n];
        if (v > bm || (v == bm && i2 < bi)) { bm = v; bi = i2; }
    }
    g_rowmax[n] = bm; g_rowidx[n] = bi;
    bm = g_colmax_part[n]; bi = g_colidx_part[n];
    for (int s = 1; s < 32; s++) {
        float v = g_colmax_part[s * NN + n];
        int i2 = g_colidx_part[s * NN + n];
        if (v > bm || (v == bm && i2 < bi)) { bm = v; bi = i2; }
    }
    g_colmax[n] = bm; g_colidx[n] = bi;
}

// ---------------- single-block mutual compaction (count+scan+fill+pad) ---------
__global__ void __launch_bounds__(1024) compact_kernel() {
    __shared__ int tsum[1024];
    int t = threadIdx.x;
    int flags[8];
    int s = 0;
    #pragma unroll
    for (int u = 0; u < 8; u++) {
        int idx = t * 8 + u;
        int f;
        if (idx < NN) { int n = idx; f = (g_colidx[g_rowidx[n]] == n); }
        else          { int m = idx - NN; f = (g_rowidx[g_colidx[m]] == m); }
        flags[u] = f;
        s += f;
    }
    tsum[t] = s;
    __syncthreads();
    for (int off = 1; off < 1024; off <<= 1) {
        int v = (t >= off) ? tsum[t - off] : 0;
        __syncthreads();
        tsum[t] += v;
        __syncthreads();
    }
    int rowtot = tsum[511];
    int total = tsum[1023];
    if (t == 0) { g_nsel[0] = rowtot; g_nsel[1] = total - rowtot; }
    int run = (t > 0) ? tsum[t - 1] : 0;
    #pragma unroll
    for (int u = 0; u < 8; u++) {
        if (flags[u]) {
            int idx = t * 8 + u;
            if (idx < NN) g_rowlist[run] = idx;
            else          g_collist[run - rowtot] = idx - NN;
            run++;
        }
    }
    __syncthreads();
    int coltot = total - rowtot;
    for (int i2 = rowtot + t; i2 < NN; i2 += 1024) g_rowlist[i2] = 0;
    for (int i2 = coltot + t; i2 < NN; i2 += 1024) g_collist[i2] = 0;
}

// ---------------- fused exp pass: one sim read -> gated p (row) + pT (col) -----
// grid (NN/32 m-tiles, NN/32 k-tiles), 256 threads
__global__ void __launch_bounds__(256) exp_fused_kernel() {
    __shared__ float tile[32][33];
    __shared__ int rflag[32], cflag[32];
    int m0 = blockIdx.x * 32;
    int k0 = blockIdx.y * 32;
    int tx = threadIdx.x & 31;
    int ty = threadIdx.x >> 5;
    if (threadIdx.x < 32) {
        int k = k0 + threadIdx.x;
        rflag[threadIdx.x] = (g_colidx[g_rowidx[k]] == k);
    } else if (threadIdx.x < 64) {
        int m = m0 + threadIdx.x - 32;
        cflag[threadIdx.x - 32] = (g_rowidx[g_colidx[m]] == m);
    }
    __syncthreads();
    float v[4];
    #pragma unroll
    for (int q = 0; q < 4; q++) {
        int r = ty * 4 + q;
        v[q] = g_sim[(size_t)(k0 + r) * NN + m0 + tx];
        tile[r][tx] = v[q];
    }
    // row-direction (no transpose): p[k][m] = exp(sim - rowmax[k])
    #pragma unroll
    for (int q = 0; q < 4; q++) {
        int r = ty * 4 + q;
        if (!rflag[r]) continue;
        float e = fast_exp(v[q] - g_rowmax[k0 + r]);
        __nv_bfloat16 h = __float2bfloat16_rn(e);
        size_t off = (size_t)(k0 + r) * NN + m0 + tx;
        g_p_h[off] = h;
        g_p_r[off] = __float2bfloat16_rn(e - __bfloat162float(h));
    }
    __syncthreads();
    // col-direction (transposed): pT[m][k] = exp(sim - colmax[m])
    #pragma unroll
    for (int q = 0; q < 4; q++) {
        int r = ty * 4 + q;
        if (!cflag[r]) continue;
        float e = fast_exp(tile[tx][r] - g_colmax[m0 + r]);
        __nv_bfloat16 h = __float2bfloat16_rn(e);
        size_t off = (size_t)(m0 + r) * NN + k0 + tx;
        g_pT_h[off] = h;
        g_pT_r[off] = __float2bfloat16_rn(e - __bfloat162float(h));
    }
}

// ---------------- selected sums (both directions) ----------------
__global__ void __launch_bounds__(256) sums_sel_kernel() {
    int dir = blockIdx.y;
    int b = blockIdx.x;
    if (b >= g_nsel[dir]) return;
    int row = dir ? g_collist[b] : g_rowlist[b];
    const __nv_bfloat16* ph = (dir ? g_pT_h : g_p_h) + (size_t)row * NN;
    const __nv_bfloat16* pr = (dir ? g_pT_r : g_p_r) + (size_t)row * NN;
    int tid = threadIdx.x;
    float lsum = 0.0f;
    #pragma unroll
    for (int s = 0; s < 16; s++) {
        int idx = tid + 256 * s;
        lsum += __bfloat162float(ph[idx]) + __bfloat162float(pr[idx]);
    }
    __shared__ float sv[256];
    sv[tid] = lsum;
    __syncthreads();
    for (int off = 128; off > 0; off >>= 1) {
        if (tid < off) sv[tid] += sv[tid + off];
        __syncthreads();
    }
    if (tid == 0) {
        if (dir) g_colsum[row] = sv[0];
        else     g_rowsum[row] = sv[0];
    }
}

// ---------------- weighted bf16 MMA, both dirs: grid (2, 32, 16) ---------------
__global__ void __launch_bounds__(256) gemm_w_kernel(
    const __nv_bfloat16* __restrict__ Sh0, const __nv_bfloat16* __restrict__ Sr0,
    const __nv_bfloat16* __restrict__ Sh1, const __nv_bfloat16* __restrict__ Sr1)
{
    const int dir = blockIdx.z >> 3;
    const int m0 = blockIdx.y * 128;
    if (m0 >= g_nsel[dir]) return;
    __shared__ __align__(16) char sm[2][16384];

    const int t = threadIdx.x;
    const int lane = t & 31, wid = t >> 5;
    const int m0w = (wid & 3) * 32, n0w = (wid >> 2) * 64;
    const int n0 = blockIdx.x * 128;
    const int kbase = (blockIdx.z & 7) * 1536;
    const int lrow = t >> 2, q = t & 3;
    const uint32_t sbase = smem_u32(&sm[0][0]);

    const int* list = dir ? g_collist : g_rowlist;
    const __nv_bfloat16* Ph = dir ? g_pT_h : g_p_h;
    const __nv_bfloat16* Pr = dir ? g_pT_r : g_p_r;
    const __nv_bfloat16* Sh = dir ? Sh1 : Sh0;
    const __nv_bfloat16* Sr = dir ? Sr1 : Sr0;

    const int grow0 = list[m0 + lrow];
    const int grow1 = list[m0 + lrow + 64];

    float acc[2][8][4];
    #pragma unroll
    for (int a = 0; a < 2; a++)
        #pragma unroll
        for (int b = 0; b < 8; b++)
            #pragma unroll
            for (int c = 0; c < 4; c++) acc[a][b][c] = 0.0f;

    uint4 ra0, ra1, rb0, rb1;
    #define W_LDG(KB) do { \
        int kg = kbase + (KB) * 32; \
        int seg = kg >> 12; \
        int kk = kg & 4095; \
        const __nv_bfloat16* ap = (seg == 2) ? Pr : Ph; \
        const __nv_bfloat16* bp = (seg == 1) ? Sr : Sh; \
        ra0 = *(const uint4*)(ap + (size_t)grow0 * NN + kk + q * 8); \
        ra1 = *(const uint4*)(ap + (size_t)grow1 * NN + kk + q * 8); \
        rb0 = *(const uint4*)(bp + (size_t)(n0 + lrow) * NN + kk + q * 8); \
        rb1 = *(const uint4*)(bp + (size_t)(n0 + lrow + 64) * NN + kk + q * 8); \
    } while (0)
    #define W_STS(BUF) do { \
        char* base = &sm[BUF][0]; \
        *(uint4*)(base + swz64(lrow, q)) = ra0; \
        *(uint4*)(base + swz64(lrow + 64, q)) = ra1; \
        *(uint4*)(base + 8192 + swz64(lrow, q)) = rb0; \
        *(uint4*)(base + 8192 + swz64(lrow + 64, q)) = rb1; \
    } while (0)

    W_LDG(0);
    W_STS(0);
    __syncthreads();
    for (int kb = 0; kb < 48; kb++) {
        int buf = kb & 1;
        if (kb + 1 < 48) W_LDG(kb + 1);
        mma_block(sbase + buf * 16384, sbase + buf * 16384 + 8192, lane, m0w, n0w, acc);
        if (kb + 1 < 48) W_STS(buf ^ 1);
        __syncthreads();
    }
    #undef W_LDG
    #undef W_STS

    const int gid = lane >> 2, tig = lane & 3;
    float* Cp0 = g_cpart + (size_t)blockIdx.z * NN * CC;
    #pragma unroll
    for (int mt = 0; mt < 2; mt++) {
        int r0 = m0 + m0w + mt * 16 + gid;
        #pragma unroll
        for (int np = 0; np < 8; np++) {
            int c = n0 + n0w + np * 8 + tig * 2;
            *(float2*)&Cp0[(size_t)r0 * CC + c] = make_float2(acc[mt][np][0], acc[mt][np][1]);
            *(float2*)&Cp0[(size_t)(r0 + 8) * CC + c] = make_float2(acc[mt][np][2], acc[mt][np][3]);
        }
    }
}

// ---------------- split-K reduce, both directions ----------------
__global__ void __launch_bounds__(256) reduce_both_kernel() {
    int dir = blockIdx.y;
    int slot = blockIdx.x;
    if (slot >= g_nsel[dir]) return;
    int row = dir ? g_collist[slot] : g_rowlist[slot];
    int c = threadIdx.x;
    float s = 0.0f;
    #pragma unroll
    for (int z = 0; z < SPLITK; z++)
        s += g_cpart[(size_t)(dir * SPLITK + z) * NN * CC + (size_t)slot * CC + c];
    float den = dir ? g_colsum[row] : g_rowsum[row];
    float* soft = dir ? g_soft_col : g_soft_row;
    soft[(size_t)row * CC + c] = s / den;
}

// ---------------- loss, both directions ----------------
__global__ void __launch_bounds__(256) loss_both_kernel(
    const float* __restrict__ reci, const float* __restrict__ recj, int op0, int op1)
{
    int dir = blockIdx.y;
    int tid = threadIdx.x;
    int b = blockIdx.x;
    const int* idxA = dir ? g_colidx : g_rowidx;
    const int* idxB = dir ? g_rowidx : g_colidx;
    const float* soft = dir ? g_soft_col : g_soft_row;
    const float* recon = dir ? recj : reci;
    int op = dir ? op1 : op0;
    float relc = g_relWT[op * CC + tid];
    float lsum = 0.0f;
    int lcnt = 0;
    for (int r = 0; r < 128; r++) {
        int row = b * 128 + r;
        int a = idxA[row];
        if (idxB[a] == row) {
            float d = recon[(size_t)row * CC + tid] + relc - soft[(size_t)row * CC + tid];
            lsum += d * d;
            if (tid == 0) lcnt++;
        }
    }
    __shared__ float ss[256];
    ss[tid] = lsum;
    __syncthreads();
    for (int off = 128; off > 0; off >>= 1) {
        if (tid < off) ss[tid] += ss[tid + off];
        __syncthreads();
    }
    if (tid == 0) {
        g_sq_part[op * 32 + b] = ss[0];
        g_cnt_part[op * 32 + b] = lcnt;
    }
}

__global__ void finalize_kernel(float* __restrict__ out) {
    if (threadIdx.x == 0) {
        float total = 0.0f, count = 0.0f;
        for (int op = 0; op < 12; op++) {
            float sq = 0.0f;
            int cnt = 0;
            for (int b = 0; b < 32; b++) {
                sq += g_sq_part[op * 32 + b];
                cnt += g_cnt_part[op * 32 + b];
            }
            if (cnt > 0) {
                total += sq / fmaxf((float)cnt * (float)CC, 1.0f);
                count += 1.0f;
            }
        }
        out[0] = (count > 0.0f) ? (total / fmaxf(count, 1.0f)) : 0.0f;
    }
}

// ---------------- host launch ----------------
extern "C" void kernel_launch(void* const* d_in, const int* in_sizes, int n_in,
                              void* d_out, int out_size)
{
    const float* desc  = (const float*)d_in[0];
    const float* sf    = (const float*)d_in[1];
    const float* T     = (const float*)d_in[2];
    const float* W_rec = (const float*)d_in[3];
    const float* W_T   = (const float*)d_in[4];
    float* out = (float*)d_out;

    float* recon;
    __nv_bfloat16 *dnh, *dnr, *sfh, *sfr;
    cudaGetSymbolAddress((void**)&recon, g_recon);
    cudaGetSymbolAddress((void**)&dnh, g_dnb_h);
    cudaGetSymbolAddress((void**)&dnr, g_dnb_r);
    cudaGetSymbolAddress((void**)&sfh, g_sfT_h);
    cudaGetSymbolAddress((void**)&sfr, g_sfT_r);

    normalize_kernel<<<NN * VV, 256>>>(desc);
    sf_split_kernel<<<dim3(NN / 32, CC / 32, VV), 256>>>(sf);
    wr_split_kernel<<<dim3(8, 8), 256>>>(W_rec);
    relwt_kernel<<<12, 256>>>(T, W_T);
    recon_mma_kernel<<<dim3(2, 32, VV), 256>>>();

    auto OP = [](int i, int j) { return i * 3 + (j < i ? j : j - 1); };

    for (int i = 0; i < VV; i++) {
        for (int j = i + 1; j < VV; j++) {
            size_t oi = (size_t)i * NN * CC, oj = (size_t)j * NN * CC;
            sim_bf16_kernel<<<dim3(32, 32), 256>>>(dnh + oi, dnr + oi, dnh + oj, dnr + oj);
            maxreduce_kernel<<<16, 256>>>();
            compact_kernel<<<1, 1024>>>();
            exp_fused_kernel<<<dim3(NN / 32, NN / 32), 256>>>();
            sums_sel_kernel<<<dim3(NN, 2), 256>>>();
            gemm_w_kernel<<<dim3(2, 32, 2 * SPLITK), 256>>>(
                sfh + (size_t)j * CC * NN, sfr + (size_t)j * CC * NN,
                sfh + (size_t)i * CC * NN, sfr + (size_t)i * CC * NN);
            reduce_both_kernel<<<dim3(NN, 2), 256>>>();
            loss_both_kernel<<<dim3(32, 2), 256>>>(recon + oi, recon + oj, OP(i, j), OP(j, i));
        }
    }

    finalize_kernel<<<1, 32>>>(out);
}

// round 8
// speedup vs baseline: 1.9218x; 1.1390x over previous
#include <cuda_runtime.h>
#include <cuda_bf16.h>
#include <cfloat>
#include <cstddef>
#include <cstdint>

#define NN 4096
#define CC 256
#define VV 4
#define NP 6
#define SPLITK 8
#define SIMSZ ((size_t)NN * NN)

// ---------------- scratch (per-pair axes) ----------------
__device__ __nv_bfloat16 g_dnb_h[VV * NN * CC];
__device__ __nv_bfloat16 g_dnb_r[VV * NN * CC];
__device__ __nv_bfloat16 g_sfT_h[VV * CC * NN];
__device__ __nv_bfloat16 g_sfT_r[VV * CC * NN];
__device__ __nv_bfloat16 g_wrT_h[CC * CC];
__device__ __nv_bfloat16 g_wrT_r[CC * CC];
__device__ float g_recon[VV * NN * CC];
__device__ float g_relWT[12 * CC];
__device__ float g_sim[NP * SIMSZ];
__device__ __nv_bfloat16 g_p_h[NP * SIMSZ];
__device__ __nv_bfloat16 g_p_r[NP * SIMSZ];
__device__ __nv_bfloat16 g_pT_h[NP * SIMSZ];
__device__ __nv_bfloat16 g_pT_r[NP * SIMSZ];
__device__ float g_cpart[(size_t)NP * 2 * SPLITK * NN * CC];

__device__ float g_rowmax_part[NP * 32 * NN];
__device__ int   g_rowidx_part[NP * 32 * NN];
__device__ float g_colmax_part[NP * 32 * NN];
__device__ int   g_colidx_part[NP * 32 * NN];
__device__ float g_rowmax[NP * NN];
__device__ int   g_rowidx[NP * NN];
__device__ float g_colmax[NP * NN];
__device__ int   g_colidx[NP * NN];
__device__ float g_rowsum[NP * NN];
__device__ float g_colsum[NP * NN];
__device__ int   g_rowlist[NP * NN];
__device__ int   g_collist[NP * NN];
__device__ int   g_nsel[NP * 2];

__device__ float g_soft_row[NP * NN * CC];
__device__ float g_soft_col[NP * NN * CC];
__device__ float g_sq_part[12 * 32];
__device__ int   g_cnt_part[12 * 32];

__constant__ int c_OPI[12] = {0,0,0,1,1,1,2,2,2,3,3,3};
__constant__ int c_OPJ[12] = {1,2,3,0,2,3,0,1,3,0,1,2};
__constant__ int c_PI[NP]  = {0,0,0,1,1,2};
__constant__ int c_PJ[NP]  = {1,2,3,2,3,3};
__constant__ int c_OP0[NP] = {0,1,2,4,5,8};
__constant__ int c_OP1[NP] = {3,6,9,7,10,11};

// ---------------- helpers ----------------
__device__ __forceinline__ uint32_t smem_u32(const void* p) {
    uint32_t a;
    asm("{ .reg .u64 t; cvta.to.shared.u64 t, %1; cvt.u32.u64 %0, t; }" : "=r"(a) : "l"(p));
    return a;
}
__device__ __forceinline__ uint32_t swz64(int row, int kc) {
    return (uint32_t)(row * 64) + (uint32_t)(((kc ^ ((row >> 1) & 3)) & 3) << 4);
}
__device__ __forceinline__ void ldm_x4(uint32_t addr, uint32_t& r0, uint32_t& r1,
                                       uint32_t& r2, uint32_t& r3) {
    asm volatile("ldmatrix.sync.aligned.m8n8.x4.shared.b16 {%0,%1,%2,%3}, [%4];"
        : "=r"(r0), "=r"(r1), "=r"(r2), "=r"(r3) : "r"(addr));
}
__device__ __forceinline__ void mma_bf16(float* c, const uint32_t* a, uint32_t b0, uint32_t b1) {
    asm volatile("mma.sync.aligned.m16n8k16.row.col.f32.bf16.bf16.f32 "
        "{%0,%1,%2,%3}, {%4,%5,%6,%7}, {%8,%9}, {%0,%1,%2,%3};"
        : "+f"(c[0]), "+f"(c[1]), "+f"(c[2]), "+f"(c[3])
        : "r"(a[0]), "r"(a[1]), "r"(a[2]), "r"(a[3]), "r"(b0), "r"(b1));
}
__device__ __forceinline__ float fast_exp(float x) {
    float y = x * 1.4426950408889634f;
    float n = rintf(y);
    float f = y - n;
    float r = 0.0001540353039338f;
    r = r * f + 0.0013333558146428f;
    r = r * f + 0.0096181291076285f;
    r = r * f + 0.0555041086648216f;
    r = r * f + 0.2402265069591007f;
    r = r * f + 0.6931471805599453f;
    r = r * f + 1.0f;
    return __int_as_float(__float_as_int(r) + ((int)n << 23));
}

__device__ __forceinline__ void mma_block(uint32_t sA, uint32_t sB, int lane,
                                          int m0w, int n0w, float acc[2][8][4]) {
    const int arow = m0w + (lane & 7) + ((lane >> 3) & 1) * 8;
    const int akc  = lane >> 4;
    const int brow = n0w + (lane & 7) + (lane >> 4) * 8;
    const int bkc  = (lane >> 3) & 1;
    #pragma unroll
    for (int ks = 0; ks < 2; ks++) {
        uint32_t a[2][4];
        #pragma unroll
        for (int mt = 0; mt < 2; mt++)
            ldm_x4(sA + swz64(arow + mt * 16, ks * 2 + akc),
                   a[mt][0], a[mt][1], a[mt][2], a[mt][3]);
        #pragma unroll
        for (int np = 0; np < 4; np++) {
            uint32_t b0, b1, b2, b3;
            ldm_x4(sB + swz64(brow + np * 16, ks * 2 + bkc), b0, b1, b2, b3);
            #pragma unroll
            for (int mt = 0; mt < 2; mt++) {
                mma_bf16(acc[mt][np * 2],     a[mt], b0, b1);
                mma_bf16(acc[mt][np * 2 + 1], a[mt], b2, b3);
            }
        }
    }
}

// ---------------- setup kernels ----------------
__global__ void __launch_bounds__(256) normalize_kernel(const float* __restrict__ desc) {
    int rv = blockIdx.x;
    int tid = threadIdx.x;
    __shared__ float ss[256];
    float x = desc[(size_t)rv * CC + tid];
    ss[tid] = x * x;
    __syncthreads();
    for (int off = 128; off > 0; off >>= 1) {
        if (tid < off) ss[tid] += ss[tid + off];
        __syncthreads();
    }
    float den = fmaxf(sqrtf(ss[0]), 1e-12f);
    float y = x / den;
    int n = rv / VV, v = rv % VV;
    __nv_bfloat16 h = __float2bfloat16_rn(y);
    size_t off = (size_t)(v * NN + n) * CC + tid;
    g_dnb_h[off] = h;
    g_dnb_r[off] = __float2bfloat16_rn(y - __bfloat162float(h));
}

__global__ void __launch_bounds__(256) sf_split_kernel(const float* __restrict__ sf) {
    __shared__ float t[32][33];
    int v = blockIdx.z;
    int n0 = blockIdx.x * 32, c0 = blockIdx.y * 32;
    int tx = threadIdx.x & 31, ty = threadIdx.x >> 5;
    #pragma unroll
    for (int q = 0; q < 4; q++) {
        int r = ty * 4 + q;
        t[r][tx] = sf[(size_t)(n0 + r) * (VV * CC) + v * CC + c0 + tx];
    }
    __syncthreads();
    #pragma unroll
    for (int q = 0; q < 4; q++) {
        int r = ty * 4 + q;
        float x = t[tx][r];
        __nv_bfloat16 h = __float2bfloat16_rn(x);
        size_t off = (size_t)v * CC * NN + (size_t)(c0 + r) * NN + n0 + tx;
        g_sfT_h[off] = h;
        g_sfT_r[off] = __float2bfloat16_rn(x - __bfloat162float(h));
    }
}

__global__ void __launch_bounds__(256) wr_split_kernel(const float* __restrict__ W) {
    __shared__ float t[32][33];
    int k0 = blockIdx.y * 32, c0 = blockIdx.x * 32;
    int tx = threadIdx.x & 31, ty = threadIdx.x >> 5;
    #pragma unroll
    for (int q = 0; q < 4; q++) {
        int r = ty * 4 + q;
        t[r][tx] = W[(size_t)(k0 + r) * CC + c0 + tx];
    }
    __syncthreads();
    #pragma unroll
    for (int q = 0; q < 4; q++) {
        int r = ty * 4 + q;
        float x = t[tx][r];
        __nv_bfloat16 h = __float2bfloat16_rn(x);
        size_t off = (size_t)(c0 + r) * CC + k0 + tx;
        g_wrT_h[off] = h;
        g_wrT_r[off] = __float2bfloat16_rn(x - __bfloat162float(h));
    }
}

__global__ void __launch_bounds__(256) relwt_kernel(const float* __restrict__ T,
                                                    const float* __restrict__ WT) {
    int op = blockIdx.x;
    int c = threadIdx.x;
    int i = c_OPI[op], j = c_OPJ[op];
    float s = 0.0f;
    #pragma unroll
    for (int k = 0; k < 16; k++) s += T[i * 16 + k] * WT[k * CC + c];
    #pragma unroll
    for (int k = 0; k < 16; k++) s += T[j * 16 + k] * WT[(16 + k) * CC + c];
    g_relWT[op * CC + c] = s;
}

// ---------------- recon bf16 MMA (3-term), grid (2, 32, VV) ----------------
__global__ void __launch_bounds__(256) recon_mma_kernel() {
    __shared__ __align__(16) char sm[2][16384];
    const int t = threadIdx.x;
    const int lane = t & 31, wid = t >> 5;
    const int m0w = (wid & 3) * 32, n0w = (wid >> 2) * 64;
    const int v = blockIdx.z;
    const int m0 = blockIdx.y * 128, n0 = blockIdx.x * 128;
    const int lrow = t >> 2, q = t & 3;
    const uint32_t sbase = smem_u32(&sm[0][0]);
    const __nv_bfloat16* Ah = g_dnb_h + (size_t)v * NN * CC;
    const __nv_bfloat16* Ar = g_dnb_r + (size_t)v * NN * CC;

    float acc[2][8][4];
    #pragma unroll
    for (int a = 0; a < 2; a++)
        #pragma unroll
        for (int b = 0; b < 8; b++)
            #pragma unroll
            for (int c = 0; c < 4; c++) acc[a][b][c] = 0.0f;

    uint4 ra0, ra1, rb0, rb1;
    #define R_LDG(KB) do { \
        int seg = (KB) >> 3; \
        int kk = ((KB) & 7) << 5; \
        const __nv_bfloat16* ap = (seg == 2) ? Ar : Ah; \
        const __nv_bfloat16* bp = (seg == 1) ? g_wrT_r : g_wrT_h; \
        ra0 = *(const uint4*)(ap + (size_t)(m0 + lrow) * CC + kk + q * 8); \
        ra1 = *(const uint4*)(ap + (size_t)(m0 + lrow + 64) * CC + kk + q * 8); \
        rb0 = *(const uint4*)(bp + (size_t)(n0 + lrow) * CC + kk + q * 8); \
        rb1 = *(const uint4*)(bp + (size_t)(n0 + lrow + 64) * CC + kk + q * 8); \
    } while (0)
    #define R_STS(BUF) do { \
        char* base = &sm[BUF][0]; \
        *(uint4*)(base + swz64(lrow, q)) = ra0; \
        *(uint4*)(base + swz64(lrow + 64, q)) = ra1; \
        *(uint4*)(base + 8192 + swz64(lrow, q)) = rb0; \
        *(uint4*)(base + 8192 + swz64(lrow + 64, q)) = rb1; \
    } while (0)

    R_LDG(0);
    R_STS(0);
    __syncthreads();
    for (int kb = 0; kb < 24; kb++) {
        int buf = kb & 1;
        if (kb + 1 < 24) R_LDG(kb + 1);
        mma_block(sbase + buf * 16384, sbase + buf * 16384 + 8192, lane, m0w, n0w, acc);
        if (kb + 1 < 24) R_STS(buf ^ 1);
        __syncthreads();
    }
    #undef R_LDG
    #undef R_STS

    const int gid = lane >> 2, tig = lane & 3;
    float* C = g_recon + (size_t)v * NN * CC;
    #pragma unroll
    for (int mt = 0; mt < 2; mt++) {
        int r0 = m0 + m0w + mt * 16 + gid;
        #pragma unroll
        for (int np = 0; np < 8; np++) {
            int c = n0 + n0w + np * 8 + tig * 2;
            *(float2*)&C[(size_t)r0 * CC + c] = make_float2(acc[mt][np][0], acc[mt][np][1]);
            *(float2*)&C[(size_t)(r0 + 8) * CC + c] = make_float2(acc[mt][np][2], acc[mt][np][3]);
        }
    }
}

// ---------------- sim bf16 MMA, all pairs: grid (32, 32, NP) ----------------
__global__ void __launch_bounds__(256) sim_all_kernel() {
    __shared__ __align__(16) char sm[2][16384];
    __shared__ float s_rv[2][128];
    __shared__ int   s_ri[2][128];
    __shared__ float s_cv[4][128];
    __shared__ int   s_ci[4][128];

    const int t = threadIdx.x;
    const int lane = t & 31, wid = t >> 5;
    const int m0w = (wid & 3) * 32, n0w = (wid >> 2) * 64;
    const int p = blockIdx.z;
    const int m0 = blockIdx.y * 128, col0 = blockIdx.x * 128;
    const int lrow = t >> 2, q = t & 3;
    const uint32_t sbase = smem_u32(&sm[0][0]);

    const __nv_bfloat16* Ah = g_dnb_h + (size_t)c_PI[p] * NN * CC;
    const __nv_bfloat16* Ar = g_dnb_r + (size_t)c_PI[p] * NN * CC;
    const __nv_bfloat16* Bh = g_dnb_h + (size_t)c_PJ[p] * NN * CC;
    const __nv_bfloat16* Br = g_dnb_r + (size_t)c_PJ[p] * NN * CC;
    float* simp = g_sim + (size_t)p * SIMSZ;

    float acc[2][8][4];
    #pragma unroll
    for (int a = 0; a < 2; a++)
        #pragma unroll
        for (int b = 0; b < 8; b++)
            #pragma unroll
            for (int c = 0; c < 4; c++) acc[a][b][c] = 0.0f;

    uint4 ra0, ra1, rb0, rb1;
    #define SIM_LDG(KB) do { \
        int kk = ((KB) & 7) << 5; \
        const __nv_bfloat16* ap = ((KB) >= 16) ? Ar : Ah; \
        const __nv_bfloat16* bp = ((KB) & 8) ? Br : Bh; \
        ra0 = *(const uint4*)(ap + (size_t)(m0 + lrow) * CC + kk + q * 8); \
        ra1 = *(const uint4*)(ap + (size_t)(m0 + lrow + 64) * CC + kk + q * 8); \
        rb0 = *(const uint4*)(bp + (size_t)(col0 + lrow) * CC + kk + q * 8); \
        rb1 = *(const uint4*)(bp + (size_t)(col0 + lrow + 64) * CC + kk + q * 8); \
    } while (0)
    #define SIM_STS(BUF) do { \
        char* base = &sm[BUF][0]; \
        *(uint4*)(base + swz64(lrow, q)) = ra0; \
        *(uint4*)(base + swz64(lrow + 64, q)) = ra1; \
        *(uint4*)(base + 8192 + swz64(lrow, q)) = rb0; \
        *(uint4*)(base + 8192 + swz64(lrow + 64, q)) = rb1; \
    } while (0)

    SIM_LDG(0);
    SIM_STS(0);
    __syncthreads();
    for (int kb = 0; kb < 32; kb++) {
        int buf = kb & 1;
        if (kb + 1 < 32) SIM_LDG(kb + 1);
        mma_block(sbase + buf * 16384, sbase + buf * 16384 + 8192, lane, m0w, n0w, acc);
        if (kb + 1 < 32) SIM_STS(buf ^ 1);
        __syncthreads();
    }
    #undef SIM_LDG
    #undef SIM_STS

    const int gid = lane >> 2, tig = lane & 3;
    #pragma unroll
    for (int mt = 0; mt < 2; mt++) {
        int r0 = m0 + m0w + mt * 16 + gid;
        #pragma unroll
        for (int np = 0; np < 8; np++) {
            int c = col0 + n0w + np * 8 + tig * 2;
            *(float2*)&simp[(size_t)r0 * NN + c] = make_float2(acc[mt][np][0], acc[mt][np][1]);
            *(float2*)&simp[(size_t)(r0 + 8) * NN + c] = make_float2(acc[mt][np][2], acc[mt][np][3]);
        }
    }
    #pragma unroll
    for (int mt = 0; mt < 2; mt++)
        #pragma unroll
        for (int h = 0; h < 2; h++) {
            float bv = -FLT_MAX; int bi = 0;
            #pragma unroll
            for (int np = 0; np < 8; np++)
                #pragma unroll
                for (int e = 0; e < 2; e++) {
                    float v = acc[mt][np][h * 2 + e];
                    int c = col0 + n0w + np * 8 + tig * 2 + e;
                    if (v > bv) { bv = v; bi = c; }
                }
            #pragma unroll
            for (int o = 1; o <= 2; o <<= 1) {
                float v2 = __shfl_xor_sync(0xffffffffu, bv, o);
                int i2 = __shfl_xor_sync(0xffffffffu, bi, o);
                if (v2 > bv || (v2 == bv && i2 < bi)) { bv = v2; bi = i2; }
            }
            if (tig == 0) {
                int rl = m0w + mt * 16 + h * 8 + gid;
                s_rv[wid >> 2][rl] = bv;
                s_ri[wid >> 2][rl] = bi;
            }
        }
    #pragma unroll
    for (int np = 0; np < 8; np++)
        #pragma unroll
        for (int e = 0; e < 2; e++) {
            float bv = -FLT_MAX; int bi = 0;
            #pragma unroll
            for (int mt = 0; mt < 2; mt++)
                #pragma unroll
                for (int h = 0; h < 2; h++) {
                    float v = acc[mt][np][h * 2 + e];
                    int r = m0 + m0w + mt * 16 + h * 8 + gid;
                    if (v > bv) { bv = v; bi = r; }
                }
            #pragma unroll
            for (int o = 4; o <= 16; o <<= 1) {
                float v2 = __shfl_xor_sync(0xffffffffu, bv, o);
                int i2 = __shfl_xor_sync(0xffffffffu, bi, o);
                if (v2 > bv || (v2 == bv && i2 < bi)) { bv = v2; bi = i2; }
            }
            if (gid == 0) {
                int cl = n0w + np * 8 + tig * 2 + e;
                s_cv[wid & 3][cl] = bv;
                s_ci[wid & 3][cl] = bi;
            }
        }
    __syncthreads();
    if (t < 128) {
        float bv = s_rv[0][t]; int bi = s_ri[0][t];
        if (s_rv[1][t] > bv || (s_rv[1][t] == bv && s_ri[1][t] < bi)) { bv = s_rv[1][t]; bi = s_ri[1][t]; }
        g_rowmax_part[(size_t)p * 32 * NN + blockIdx.x * NN + m0 + t] = bv;
        g_rowidx_part[(size_t)p * 32 * NN + blockIdx.x * NN + m0 + t] = bi;
        float cv = s_cv[0][t]; int ci = s_ci[0][t];
        #pragma unroll
        for (int w = 1; w < 4; w++) {
            if (s_cv[w][t] > cv || (s_cv[w][t] == cv && s_ci[w][t] < ci)) { cv = s_cv[w][t]; ci = s_ci[w][t]; }
        }
        g_colmax_part[(size_t)p * 32 * NN + blockIdx.y * NN + col0 + t] = cv;
        g_colidx_part[(size_t)p * 32 * NN + blockIdx.y * NN + col0 + t] = ci;
    }
}

// ---------------- max reduce, all pairs: grid (16, NP) ----------------
__global__ void __launch_bounds__(256) maxreduce_all_kernel() {
    int p = blockIdx.y;
    int n = blockIdx.x * 256 + threadIdx.x;
    size_t pb = (size_t)p * 32 * NN;
    float bm = g_rowmax_part[pb + n]; int bi = g_rowidx_part[pb + n];
    for (int s = 1; s < 32; s++) {
        float v = g_rowmax_part[pb + s * NN + n];
        int i2 = g_rowidx_part[pb + s * NN + n];
        if (v > bm || (v == bm && i2 < bi)) { bm = v; bi = i2; }
    }
    g_rowmax[p * NN + n] = bm; g_rowidx[p * NN + n] = bi;
    bm = g_colmax_part[pb + n]; bi = g_colidx_part[pb + n];
    for (int s = 1; s < 32; s++) {
        float v = g_colmax_part[pb + s * NN + n];
        int i2 = g_colidx_part[pb + s * NN + n];
        if (v > bm || (v == bm && i2 < bi)) { bm = v; bi = i2; }
    }
    g_colmax[p * NN + n] = bm; g_colidx[p * NN + n] = bi;
}

// ---------------- compaction, all pairs: grid NP ----------------
__global__ void __launch_bounds__(1024) compact_all_kernel() {
    __shared__ int tsum[1024];
    int p = blockIdx.x;
    const int* ridx = g_rowidx + p * NN;
    const int* cidx = g_colidx + p * NN;
    int* rlist = g_rowlist + p * NN;
    int* clist = g_collist + p * NN;
    int t = threadIdx.x;
    int flags[8];
    int s = 0;
    #pragma unroll
    for (int u = 0; u < 8; u++) {
        int idx = t * 8 + u;
        int f;
        if (idx < NN) { int n = idx; f = (cidx[ridx[n]] == n); }
        else          { int m = idx - NN; f = (ridx[cidx[m]] == m); }
        flags[u] = f;
        s += f;
    }
    tsum[t] = s;
    __syncthreads();
    for (int off = 1; off < 1024; off <<= 1) {
        int v = (t >= off) ? tsum[t - off] : 0;
        __syncthreads();
        tsum[t] += v;
        __syncthreads();
    }
    int rowtot = tsum[511];
    int total = tsum[1023];
    if (t == 0) { g_nsel[p * 2] = rowtot; g_nsel[p * 2 + 1] = total - rowtot; }
    int run = (t > 0) ? tsum[t - 1] : 0;
    #pragma unroll
    for (int u = 0; u < 8; u++) {
        if (flags[u]) {
            int idx = t * 8 + u;
            if (idx < NN) rlist[run] = idx;
            else          clist[run - rowtot] = idx - NN;
            run++;
        }
    }
    __syncthreads();
    int coltot = total - rowtot;
    for (int i2 = rowtot + t; i2 < NN; i2 += 1024) rlist[i2] = 0;
    for (int i2 = coltot + t; i2 < NN; i2 += 1024) clist[i2] = 0;
}

// ---------------- fused exp, all pairs: grid (128, 128, NP) ----------------
__global__ void __launch_bounds__(256) exp_all_kernel() {
    __shared__ float tile[32][33];
    __shared__ int rflag[32], cflag[32];
    int p = blockIdx.z;
    int m0 = blockIdx.x * 32;
    int k0 = blockIdx.y * 32;
    int tx = threadIdx.x & 31;
    int ty = threadIdx.x >> 5;
    const int* ridx = g_rowidx + p * NN;
    const int* cidx = g_colidx + p * NN;
    const float* simp = g_sim + (size_t)p * SIMSZ;
    if (threadIdx.x < 32) {
        int k = k0 + threadIdx.x;
        rflag[threadIdx.x] = (cidx[ridx[k]] == k);
    } else if (threadIdx.x < 64) {
        int m = m0 + threadIdx.x - 32;
        cflag[threadIdx.x - 32] = (ridx[cidx[m]] == m);
    }
    __syncthreads();
    float v[4];
    #pragma unroll
    for (int q = 0; q < 4; q++) {
        int r = ty * 4 + q;
        v[q] = simp[(size_t)(k0 + r) * NN + m0 + tx];
        tile[r][tx] = v[q];
    }
    #pragma unroll
    for (int q = 0; q < 4; q++) {
        int r = ty * 4 + q;
        if (!rflag[r]) continue;
        float e = fast_exp(v[q] - g_rowmax[p * NN + k0 + r]);
        __nv_bfloat16 h = __float2bfloat16_rn(e);
        size_t off = (size_t)p * SIMSZ + (size_t)(k0 + r) * NN + m0 + tx;
        g_p_h[off] = h;
        g_p_r[off] = __float2bfloat16_rn(e - __bfloat162float(h));
    }
    __syncthreads();
    #pragma unroll
    for (int q = 0; q < 4; q++) {
        int r = ty * 4 + q;
        if (!cflag[r]) continue;
        float e = fast_exp(tile[tx][r] - g_colmax[p * NN + m0 + r]);
        __nv_bfloat16 h = __float2bfloat16_rn(e);
        size_t off = (size_t)p * SIMSZ + (size_t)(m0 + r) * NN + k0 + tx;
        g_pT_h[off] = h;
        g_pT_r[off] = __float2bfloat16_rn(e - __bfloat162float(h));
    }
}

// ---------------- selected sums, all: grid (NN, 2, NP) ----------------
__global__ void __launch_bounds__(256) sums_all_kernel() {
    int p = blockIdx.z;
    int dir = blockIdx.y;
    int b = blockIdx.x;
    if (b >= g_nsel[p * 2 + dir]) return;
    int row = dir ? g_collist[p * NN + b] : g_rowlist[p * NN + b];
    const __nv_bfloat16* ph = (dir ? g_pT_h : g_p_h) + (size_t)p * SIMSZ + (size_t)row * NN;
    const __nv_bfloat16* pr = (dir ? g_pT_r : g_p_r) + (size_t)p * SIMSZ + (size_t)row * NN;
    int tid = threadIdx.x;
    float lsum = 0.0f;
    #pragma unroll
    for (int s = 0; s < 16; s++) {
        int idx = tid + 256 * s;
        lsum += __bfloat162float(ph[idx]) + __bfloat162float(pr[idx]);
    }
    __shared__ float sv[256];
    sv[tid] = lsum;
    __syncthreads();
    for (int off = 128; off > 0; off >>= 1) {
        if (tid < off) sv[tid] += sv[tid + off];
        __syncthreads();
    }
    if (tid == 0) {
        if (dir) g_colsum[p * NN + row] = sv[0];
        else     g_rowsum[p * NN + row] = sv[0];
    }
}

// ---------------- weighted bf16 MMA, all: grid (2, 32, NP*16) ----------------
__global__ void __launch_bounds__(256) gemm_all_kernel() {
    const int p = blockIdx.z >> 4;
    const int dir = (blockIdx.z >> 3) & 1;
    const int m0 = blockIdx.y * 128;
    if (m0 >= g_nsel[p * 2 + dir]) return;
    __shared__ __align__(16) char sm[2][16384];

    const int t = threadIdx.x;
    const int lane = t & 31, wid = t >> 5;
    const int m0w = (wid & 3) * 32, n0w = (wid >> 2) * 64;
    const int n0 = blockIdx.x * 128;
    const int kbase = (blockIdx.z & 7) * 1536;
    const int lrow = t >> 2, q = t & 3;
    const uint32_t sbase = smem_u32(&sm[0][0]);

    const int* list = (dir ? g_collist : g_rowlist) + p * NN;
    const __nv_bfloat16* Ph = (dir ? g_pT_h : g_p_h) + (size_t)p * SIMSZ;
    const __nv_bfloat16* Pr = (dir ? g_pT_r : g_p_r) + (size_t)p * SIMSZ;
    const int sv = dir ? c_PI[p] : c_PJ[p];
    const __nv_bfloat16* Sh = g_sfT_h + (size_t)sv * CC * NN;
    const __nv_bfloat16* Sr = g_sfT_r + (size_t)sv * CC * NN;

    const int grow0 = list[m0 + lrow];
    const int grow1 = list[m0 + lrow + 64];

    float acc[2][8][4];
    #pragma unroll
    for (int a = 0; a < 2; a++)
        #pragma unroll
        for (int b = 0; b < 8; b++)
            #pragma unroll
            for (int c = 0; c < 4; c++) acc[a][b][c] = 0.0f;

    uint4 ra0, ra1, rb0, rb1;
    #define W_LDG(KB) do { \
        int kg = kbase + (KB) * 32; \
        int seg = kg >> 12; \
        int kk = kg & 4095; \
        const __nv_bfloat16* ap = (seg == 2) ? Pr : Ph; \
        const __nv_bfloat16* bp = (seg == 1) ? Sr : Sh; \
        ra0 = *(const uint4*)(ap + (size_t)grow0 * NN + kk + q * 8); \
        ra1 = *(const uint4*)(ap + (size_t)grow1 * NN + kk + q * 8); \
        rb0 = *(const uint4*)(bp + (size_t)(n0 + lrow) * NN + kk + q * 8); \
        rb1 = *(const uint4*)(bp + (size_t)(n0 + lrow + 64) * NN + kk + q * 8); \
    } while (0)
    #define W_STS(BUF) do { \
        char* base = &sm[BUF][0]; \
        *(uint4*)(base + swz64(lrow, q)) = ra0; \
        *(uint4*)(base + swz64(lrow + 64, q)) = ra1; \
        *(uint4*)(base + 8192 + swz64(lrow, q)) = rb0; \
        *(uint4*)(base + 8192 + swz64(lrow + 64, q)) = rb1; \
    } while (0)

    W_LDG(0);
    W_STS(0);
    __syncthreads();
    for (int kb = 0; kb < 48; kb++) {
        int buf = kb & 1;
        if (kb + 1 < 48) W_LDG(kb + 1);
        mma_block(sbase + buf * 16384, sbase + buf * 16384 + 8192, lane, m0w, n0w, acc);
        if (kb + 1 < 48) W_STS(buf ^ 1);
        __syncthreads();
    }
    #undef W_LDG
    #undef W_STS

    const int gid = lane >> 2, tig = lane & 3;
    float* Cp0 = g_cpart + (size_t)blockIdx.z * NN * CC;
    #pragma unroll
    for (int mt = 0; mt < 2; mt++) {
        int r0 = m0 + m0w + mt * 16 + gid;
        #pragma unroll
        for (int np = 0; np < 8; np++) {
            int c = n0 + n0w + np * 8 + tig * 2;
            *(float2*)&Cp0[(size_t)r0 * CC + c] = make_float2(acc[mt][np][0], acc[mt][np][1]);
            *(float2*)&Cp0[(size_t)(r0 + 8) * CC + c] = make_float2(acc[mt][np][2], acc[mt][np][3]);
        }
    }
}

// ---------------- split-K reduce, all: grid (NN, 2, NP) ----------------
__global__ void __launch_bounds__(256) reduce_all_kernel() {
    int p = blockIdx.z;
    int dir = blockIdx.y;
    int slot = blockIdx.x;
    if (slot >= g_nsel[p * 2 + dir]) return;
    int row = dir ? g_collist[p * NN + slot] : g_rowlist[p * NN + slot];
    int c = threadIdx.x;
    size_t sb = (size_t)(p * 16 + dir * 8) * NN * CC;
    float s = 0.0f;
    #pragma unroll
    for (int z = 0; z < SPLITK; z++)
        s += g_cpart[sb + (size_t)z * NN * CC + (size_t)slot * CC + c];
    float den = dir ? g_colsum[p * NN + row] : g_rowsum[p * NN + row];
    float* soft = (dir ? g_soft_col : g_soft_row) + (size_t)p * NN * CC;
    soft[(size_t)row * CC + c] = s / den;
}

// ---------------- loss, all: grid (32, 2, NP) ----------------
__global__ void __launch_bounds__(256) loss_all_kernel() {
    int p = blockIdx.z;
    int dir = blockIdx.y;
    int tid = threadIdx.x;
    int b = blockIdx.x;
    const int* idxA = (dir ? g_colidx : g_rowidx) + p * NN;
    const int* idxB = (dir ? g_rowidx : g_colidx) + p * NN;
    const float* soft = (dir ? g_soft_col : g_soft_row) + (size_t)p * NN * CC;
    const float* recon = g_recon + (size_t)(dir ? c_PJ[p] : c_PI[p]) * NN * CC;
    int op = dir ? c_OP1[p] : c_OP0[p];
    float relc = g_relWT[op * CC + tid];
    float lsum = 0.0f;
    int lcnt = 0;
    for (int r = 0; r < 128; r++) {
        int row = b * 128 + r;
        int a = idxA[row];
        if (idxB[a] == row) {
            float d = recon[(size_t)row * CC + tid] + relc - soft[(size_t)row * CC + tid];
            lsum += d * d;
            if (tid == 0) lcnt++;
        }
    }
    __shared__ float ss[256];
    ss[tid] = lsum;
    __syncthreads();
    for (int off = 128; off > 0; off >>= 1) {
        if (tid < off) ss[tid] += ss[tid + off];
        __syncthreads();
    }
    if (tid == 0) {
        g_sq_part[op * 32 + b] = ss[0];
        g_cnt_part[op * 32 + b] = lcnt;
    }
}

__global__ void finalize_kernel(float* __restrict__ out) {
    if (threadIdx.x == 0) {
        float total = 0.0f, count = 0.0f;
        for (int op = 0; op < 12; op++) {
            float sq = 0.0f;
            int cnt = 0;
            for (int b = 0; b < 32; b++) {
                sq += g_sq_part[op * 32 + b];
                cnt += g_cnt_part[op * 32 + b];
            }
            if (cnt > 0) {
                total += sq / fmaxf((float)cnt * (float)CC, 1.0f);
                count += 1.0f;
            }
        }
        out[0] = (count > 0.0f) ? (total / fmaxf(count, 1.0f)) : 0.0f;
    }
}

// ---------------- host launch ----------------
extern "C" void kernel_launch(void* const* d_in, const int* in_sizes, int n_in,
                              void* d_out, int out_size)
{
    const float* desc  = (const float*)d_in[0];
    const float* sf    = (const float*)d_in[1];
    const float* T     = (const float*)d_in[2];
    const float* W_rec = (const float*)d_in[3];
    const float* W_T   = (const float*)d_in[4];
    float* out = (float*)d_out;

    normalize_kernel<<<NN * VV, 256>>>(desc);
    sf_split_kernel<<<dim3(NN / 32, CC / 32, VV), 256>>>(sf);
    wr_split_kernel<<<dim3(8, 8), 256>>>(W_rec);
    relwt_kernel<<<12, 256>>>(T, W_T);
    recon_mma_kernel<<<dim3(2, 32, VV), 256>>>();

    sim_all_kernel<<<dim3(32, 32, NP), 256>>>();
    maxreduce_all_kernel<<<dim3(16, NP), 256>>>();
    compact_all_kernel<<<NP, 1024>>>();
    exp_all_kernel<<<dim3(NN / 32, NN / 32, NP), 256>>>();
    sums_all_kernel<<<dim3(NN, 2, NP), 256>>>();
    gemm_all_kernel<<<dim3(2, 32, NP * 16), 256>>>();
    reduce_all_kernel<<<dim3(NN, 2, NP), 256>>>();
    loss_all_kernel<<<dim3(32, 2, NP), 256>>>();

    finalize_kernel<<<1, 32>>>(out);
}

// round 9
// speedup vs baseline: 2.4057x; 1.2518x over previous
#include <cuda_runtime.h>
#include <cuda_bf16.h>
#include <cfloat>
#include <cstddef>
#include <cstdint>

#define NN 4096
#define CC 256
#define VV 4
#define NP 6
#define SIMSZ ((size_t)NN * NN)

// ---------------- scratch (per-pair axes) ----------------
__device__ __nv_bfloat16 g_dnb_h[VV * NN * CC];
__device__ __nv_bfloat16 g_dnb_r[VV * NN * CC];
__device__ __nv_bfloat16 g_sfT_h[VV * CC * NN];
__device__ __nv_bfloat16 g_wrT_h[CC * CC];
__device__ __nv_bfloat16 g_wrT_r[CC * CC];
__device__ float g_recon[VV * NN * CC];
__device__ float g_relWT[12 * CC];
__device__ float g_sim[NP * SIMSZ];
__device__ __nv_bfloat16 g_p_h[NP * SIMSZ];
__device__ __nv_bfloat16 g_pT_h[NP * SIMSZ];

__device__ float g_rowmax_part[NP * 32 * NN];
__device__ int   g_rowidx_part[NP * 32 * NN];
__device__ float g_colmax_part[NP * 32 * NN];
__device__ int   g_colidx_part[NP * 32 * NN];
__device__ float g_rowmax[NP * NN];
__device__ int   g_rowidx[NP * NN];
__device__ float g_colmax[NP * NN];
__device__ int   g_colidx[NP * NN];
__device__ float g_rowsum[NP * NN];
__device__ float g_colsum[NP * NN];
__device__ int   g_rowlist[NP * NN];
__device__ int   g_collist[NP * NN];
__device__ int   g_nsel[NP * 2];

__device__ float g_soft_row[NP * NN * CC];
__device__ float g_soft_col[NP * NN * CC];
__device__ float g_sq_part[12 * 32];
__device__ int   g_cnt_part[12 * 32];

__constant__ int c_OPI[12] = {0,0,0,1,1,1,2,2,2,3,3,3};
__constant__ int c_OPJ[12] = {1,2,3,0,2,3,0,1,3,0,1,2};
__constant__ int c_PI[NP]  = {0,0,0,1,1,2};
__constant__ int c_PJ[NP]  = {1,2,3,2,3,3};
__constant__ int c_OP0[NP] = {0,1,2,4,5,8};
__constant__ int c_OP1[NP] = {3,6,9,7,10,11};

// ---------------- helpers ----------------
__device__ __forceinline__ uint32_t smem_u32(const void* p) {
    uint32_t a;
    asm("{ .reg .u64 t; cvta.to.shared.u64 t, %1; cvt.u32.u64 %0, t; }" : "=r"(a) : "l"(p));
    return a;
}
__device__ __forceinline__ uint32_t swz64(int row, int kc) {
    return (uint32_t)(row * 64) + (uint32_t)(((kc ^ ((row >> 1) & 3)) & 3) << 4);
}
__device__ __forceinline__ void ldm_x4(uint32_t addr, uint32_t& r0, uint32_t& r1,
                                       uint32_t& r2, uint32_t& r3) {
    asm volatile("ldmatrix.sync.aligned.m8n8.x4.shared.b16 {%0,%1,%2,%3}, [%4];"
        : "=r"(r0), "=r"(r1), "=r"(r2), "=r"(r3) : "r"(addr));
}
__device__ __forceinline__ void mma_bf16(float* c, const uint32_t* a, uint32_t b0, uint32_t b1) {
    asm volatile("mma.sync.aligned.m16n8k16.row.col.f32.bf16.bf16.f32 "
        "{%0,%1,%2,%3}, {%4,%5,%6,%7}, {%8,%9}, {%0,%1,%2,%3};"
        : "+f"(c[0]), "+f"(c[1]), "+f"(c[2]), "+f"(c[3])
        : "r"(a[0]), "r"(a[1]), "r"(a[2]), "r"(a[3]), "r"(b0), "r"(b1));
}
__device__ __forceinline__ float fast_exp(float x) {
    float y = x * 1.4426950408889634f;
    float n = rintf(y);
    float f = y - n;
    float r = 0.0001540353039338f;
    r = r * f + 0.0013333558146428f;
    r = r * f + 0.0096181291076285f;
    r = r * f + 0.0555041086648216f;
    r = r * f + 0.2402265069591007f;
    r = r * f + 0.6931471805599453f;
    r = r * f + 1.0f;
    return __int_as_float(__float_as_int(r) + ((int)n << 23));
}

__device__ __forceinline__ void mma_block(uint32_t sA, uint32_t sB, int lane,
                                          int m0w, int n0w, float acc[2][8][4]) {
    const int arow = m0w + (lane & 7) + ((lane >> 3) & 1) * 8;
    const int akc  = lane >> 4;
    const int brow = n0w + (lane & 7) + (lane >> 4) * 8;
    const int bkc  = (lane >> 3) & 1;
    #pragma unroll
    for (int ks = 0; ks < 2; ks++) {
        uint32_t a[2][4];
        #pragma unroll
        for (int mt = 0; mt < 2; mt++)
            ldm_x4(sA + swz64(arow + mt * 16, ks * 2 + akc),
                   a[mt][0], a[mt][1], a[mt][2], a[mt][3]);
        #pragma unroll
        for (int np = 0; np < 4; np++) {
            uint32_t b0, b1, b2, b3;
            ldm_x4(sB + swz64(brow + np * 16, ks * 2 + bkc), b0, b1, b2, b3);
            #pragma unroll
            for (int mt = 0; mt < 2; mt++) {
                mma_bf16(acc[mt][np * 2],     a[mt], b0, b1);
                mma_bf16(acc[mt][np * 2 + 1], a[mt], b2, b3);
            }
        }
    }
}

// ---------------- setup kernels ----------------
__global__ void __launch_bounds__(256) normalize_kernel(const float* __restrict__ desc) {
    int rv = blockIdx.x;
    int tid = threadIdx.x;
    __shared__ float ss[256];
    float x = desc[(size_t)rv * CC + tid];
    ss[tid] = x * x;
    __syncthreads();
    for (int off = 128; off > 0; off >>= 1) {
        if (tid < off) ss[tid] += ss[tid + off];
        __syncthreads();
    }
    float den = fmaxf(sqrtf(ss[0]), 1e-12f);
    float y = x / den;
    int n = rv / VV, v = rv % VV;
    __nv_bfloat16 h = __float2bfloat16_rn(y);
    size_t off = (size_t)(v * NN + n) * CC + tid;
    g_dnb_h[off] = h;
    g_dnb_r[off] = __float2bfloat16_rn(y - __bfloat162float(h));
}

__global__ void __launch_bounds__(256) sf_split_kernel(const float* __restrict__ sf) {
    __shared__ float t[32][33];
    int v = blockIdx.z;
    int n0 = blockIdx.x * 32, c0 = blockIdx.y * 32;
    int tx = threadIdx.x & 31, ty = threadIdx.x >> 5;
    #pragma unroll
    for (int q = 0; q < 4; q++) {
        int r = ty * 4 + q;
        t[r][tx] = sf[(size_t)(n0 + r) * (VV * CC) + v * CC + c0 + tx];
    }
    __syncthreads();
    #pragma unroll
    for (int q = 0; q < 4; q++) {
        int r = ty * 4 + q;
        g_sfT_h[(size_t)v * CC * NN + (size_t)(c0 + r) * NN + n0 + tx] =
            __float2bfloat16_rn(t[tx][r]);
    }
}

__global__ void __launch_bounds__(256) wr_split_kernel(const float* __restrict__ W) {
    __shared__ float t[32][33];
    int k0 = blockIdx.y * 32, c0 = blockIdx.x * 32;
    int tx = threadIdx.x & 31, ty = threadIdx.x >> 5;
    #pragma unroll
    for (int q = 0; q < 4; q++) {
        int r = ty * 4 + q;
        t[r][tx] = W[(size_t)(k0 + r) * CC + c0 + tx];
    }
    __syncthreads();
    #pragma unroll
    for (int q = 0; q < 4; q++) {
        int r = ty * 4 + q;
        float x = t[tx][r];
        __nv_bfloat16 h = __float2bfloat16_rn(x);
        size_t off = (size_t)(c0 + r) * CC + k0 + tx;
        g_wrT_h[off] = h;
        g_wrT_r[off] = __float2bfloat16_rn(x - __bfloat162float(h));
    }
}

__global__ void __launch_bounds__(256) relwt_kernel(const float* __restrict__ T,
                                                    const float* __restrict__ WT) {
    int op = blockIdx.x;
    int c = threadIdx.x;
    int i = c_OPI[op], j = c_OPJ[op];
    float s = 0.0f;
    #pragma unroll
    for (int k = 0; k < 16; k++) s += T[i * 16 + k] * WT[k * CC + c];
    #pragma unroll
    for (int k = 0; k < 16; k++) s += T[j * 16 + k] * WT[(16 + k) * CC + c];
    g_relWT[op * CC + c] = s;
}

// ---------------- recon bf16 MMA (3-term), grid (2, 32, VV) ----------------
__global__ void __launch_bounds__(256) recon_mma_kernel() {
    __shared__ __align__(16) char sm[2][16384];
    const int t = threadIdx.x;
    const int lane = t & 31, wid = t >> 5;
    const int m0w = (wid & 3) * 32, n0w = (wid >> 2) * 64;
    const int v = blockIdx.z;
    const int m0 = blockIdx.y * 128, n0 = blockIdx.x * 128;
    const int lrow = t >> 2, q = t & 3;
    const uint32_t sbase = smem_u32(&sm[0][0]);
    const __nv_bfloat16* Ah = g_dnb_h + (size_t)v * NN * CC;
    const __nv_bfloat16* Ar = g_dnb_r + (size_t)v * NN * CC;

    float acc[2][8][4];
    #pragma unroll
    for (int a = 0; a < 2; a++)
        #pragma unroll
        for (int b = 0; b < 8; b++)
            #pragma unroll
            for (int c = 0; c < 4; c++) acc[a][b][c] = 0.0f;

    uint4 ra0, ra1, rb0, rb1;
    #define R_LDG(KB) do { \
        int seg = (KB) >> 3; \
        int kk = ((KB) & 7) << 5; \
        const __nv_bfloat16* ap = (seg == 2) ? Ar : Ah; \
        const __nv_bfloat16* bp = (seg == 1) ? g_wrT_r : g_wrT_h; \
        ra0 = *(const uint4*)(ap + (size_t)(m0 + lrow) * CC + kk + q * 8); \
        ra1 = *(const uint4*)(ap + (size_t)(m0 + lrow + 64) * CC + kk + q * 8); \
        rb0 = *(const uint4*)(bp + (size_t)(n0 + lrow) * CC + kk + q * 8); \
        rb1 = *(const uint4*)(bp + (size_t)(n0 + lrow + 64) * CC + kk + q * 8); \
    } while (0)
    #define R_STS(BUF) do { \
        char* base = &sm[BUF][0]; \
        *(uint4*)(base + swz64(lrow, q)) = ra0; \
        *(uint4*)(base + swz64(lrow + 64, q)) = ra1; \
        *(uint4*)(base + 8192 + swz64(lrow, q)) = rb0; \
        *(uint4*)(base + 8192 + swz64(lrow + 64, q)) = rb1; \
    } while (0)

    R_LDG(0);
    R_STS(0);
    __syncthreads();
    for (int kb = 0; kb < 24; kb++) {
        int buf = kb & 1;
        if (kb + 1 < 24) R_LDG(kb + 1);
        mma_block(sbase + buf * 16384, sbase + buf * 16384 + 8192, lane, m0w, n0w, acc);
        if (kb + 1 < 24) R_STS(buf ^ 1);
        __syncthreads();
    }
    #undef R_LDG
    #undef R_STS

    const int gid = lane >> 2, tig = lane & 3;
    float* C = g_recon + (size_t)v * NN * CC;
    #pragma unroll
    for (int mt = 0; mt < 2; mt++) {
        int r0 = m0 + m0w + mt * 16 + gid;
        #pragma unroll
        for (int np = 0; np < 8; np++) {
            int c = n0 + n0w + np * 8 + tig * 2;
            *(float2*)&C[(size_t)r0 * CC + c] = make_float2(acc[mt][np][0], acc[mt][np][1]);
            *(float2*)&C[(size_t)(r0 + 8) * CC + c] = make_float2(acc[mt][np][2], acc[mt][np][3]);
        }
    }
}

// ---------------- sim bf16 MMA, all pairs: grid (32, 32, NP) ----------------
__global__ void __launch_bounds__(256) sim_all_kernel() {
    __shared__ __align__(16) char sm[2][16384];
    __shared__ float s_rv[2][128];
    __shared__ int   s_ri[2][128];
    __shared__ float s_cv[4][128];
    __shared__ int   s_ci[4][128];

    const int t = threadIdx.x;
    const int lane = t & 31, wid = t >> 5;
    const int m0w = (wid & 3) * 32, n0w = (wid >> 2) * 64;
    const int p = blockIdx.z;
    const int m0 = blockIdx.y * 128, col0 = blockIdx.x * 128;
    const int lrow = t >> 2, q = t & 3;
    const uint32_t sbase = smem_u32(&sm[0][0]);

    const __nv_bfloat16* Ah = g_dnb_h + (size_t)c_PI[p] * NN * CC;
    const __nv_bfloat16* Ar = g_dnb_r + (size_t)c_PI[p] * NN * CC;
    const __nv_bfloat16* Bh = g_dnb_h + (size_t)c_PJ[p] * NN * CC;
    const __nv_bfloat16* Br = g_dnb_r + (size_t)c_PJ[p] * NN * CC;
    float* simp = g_sim + (size_t)p * SIMSZ;

    float acc[2][8][4];
    #pragma unroll
    for (int a = 0; a < 2; a++)
        #pragma unroll
        for (int b = 0; b < 8; b++)
            #pragma unroll
            for (int c = 0; c < 4; c++) acc[a][b][c] = 0.0f;

    uint4 ra0, ra1, rb0, rb1;
    #define SIM_LDG(KB) do { \
        int kk = ((KB) & 7) << 5; \
        const __nv_bfloat16* ap = ((KB) >= 16) ? Ar : Ah; \
        const __nv_bfloat16* bp = ((KB) & 8) ? Br : Bh; \
        ra0 = *(const uint4*)(ap + (size_t)(m0 + lrow) * CC + kk + q * 8); \
        ra1 = *(const uint4*)(ap + (size_t)(m0 + lrow + 64) * CC + kk + q * 8); \
        rb0 = *(const uint4*)(bp + (size_t)(col0 + lrow) * CC + kk + q * 8); \
        rb1 = *(const uint4*)(bp + (size_t)(col0 + lrow + 64) * CC + kk + q * 8); \
    } while (0)
    #define SIM_STS(BUF) do { \
        char* base = &sm[BUF][0]; \
        *(uint4*)(base + swz64(lrow, q)) = ra0; \
        *(uint4*)(base + swz64(lrow + 64, q)) = ra1; \
        *(uint4*)(base + 8192 + swz64(lrow, q)) = rb0; \
        *(uint4*)(base + 8192 + swz64(lrow + 64, q)) = rb1; \
    } while (0)

    SIM_LDG(0);
    SIM_STS(0);
    __syncthreads();
    for (int kb = 0; kb < 32; kb++) {
        int buf = kb & 1;
        if (kb + 1 < 32) SIM_LDG(kb + 1);
        mma_block(sbase + buf * 16384, sbase + buf * 16384 + 8192, lane, m0w, n0w, acc);
        if (kb + 1 < 32) SIM_STS(buf ^ 1);
        __syncthreads();
    }
    #undef SIM_LDG
    #undef SIM_STS

    const int gid = lane >> 2, tig = lane & 3;
    #pragma unroll
    for (int mt = 0; mt < 2; mt++) {
        int r0 = m0 + m0w + mt * 16 + gid;
        #pragma unroll
        for (int np = 0; np < 8; np++) {
            int c = col0 + n0w + np * 8 + tig * 2;
            *(float2*)&simp[(size_t)r0 * NN + c] = make_float2(acc[mt][np][0], acc[mt][np][1]);
            *(float2*)&simp[(size_t)(r0 + 8) * NN + c] = make_float2(acc[mt][np][2], acc[mt][np][3]);
        }
    }
    #pragma unroll
    for (int mt = 0; mt < 2; mt++)
        #pragma unroll
        for (int h = 0; h < 2; h++) {
            float bv = -FLT_MAX; int bi = 0;
            #pragma unroll
            for (int np = 0; np < 8; np++)
                #pragma unroll
                for (int e = 0; e < 2; e++) {
                    float v = acc[mt][np][h * 2 + e];
                    int c = col0 + n0w + np * 8 + tig * 2 + e;
                    if (v > bv) { bv = v; bi = c; }
                }
            #pragma unroll
            for (int o = 1; o <= 2; o <<= 1) {
                float v2 = __shfl_xor_sync(0xffffffffu, bv, o);
                int i2 = __shfl_xor_sync(0xffffffffu, bi, o);
                if (v2 > bv || (v2 == bv && i2 < bi)) { bv = v2; bi = i2; }
            }
            if (tig == 0) {
                int rl = m0w + mt * 16 + h * 8 + gid;
                s_rv[wid >> 2][rl] = bv;
                s_ri[wid >> 2][rl] = bi;
            }
        }
    #pragma unroll
    for (int np = 0; np < 8; np++)
        #pragma unroll
        for (int e = 0; e < 2; e++) {
            float bv = -FLT_MAX; int bi = 0;
            #pragma unroll
            for (int mt = 0; mt < 2; mt++)
                #pragma unroll
                for (int h = 0; h < 2; h++) {
                    float v = acc[mt][np][h * 2 + e];
                    int r = m0 + m0w + mt * 16 + h * 8 + gid;
                    if (v > bv) { bv = v; bi = r; }
                }
            #pragma unroll
            for (int o = 4; o <= 16; o <<= 1) {
                float v2 = __shfl_xor_sync(0xffffffffu, bv, o);
                int i2 = __shfl_xor_sync(0xffffffffu, bi, o);
                if (v2 > bv || (v2 == bv && i2 < bi)) { bv = v2; bi = i2; }
            }
            if (gid == 0) {
                int cl = n0w + np * 8 + tig * 2 + e;
                s_cv[wid & 3][cl] = bv;
                s_ci[wid & 3][cl] = bi;
            }
        }
    __syncthreads();
    if (t < 128) {
        float bv = s_rv[0][t]; int bi = s_ri[0][t];
        if (s_rv[1][t] > bv || (s_rv[1][t] == bv && s_ri[1][t] < bi)) { bv = s_rv[1][t]; bi = s_ri[1][t]; }
        g_rowmax_part[(size_t)p * 32 * NN + blockIdx.x * NN + m0 + t] = bv;
        g_rowidx_part[(size_t)p * 32 * NN + blockIdx.x * NN + m0 + t] = bi;
        float cv = s_cv[0][t]; int ci = s_ci[0][t];
        #pragma unroll
        for (int w = 1; w < 4; w++) {
            if (s_cv[w][t] > cv || (s_cv[w][t] == cv && s_ci[w][t] < ci)) { cv = s_cv[w][t]; ci = s_ci[w][t]; }
        }
        g_colmax_part[(size_t)p * 32 * NN + blockIdx.y * NN + col0 + t] = cv;
        g_colidx_part[(size_t)p * 32 * NN + blockIdx.y * NN + col0 + t] = ci;
    }
}

// ---------------- max reduce, all pairs: grid (16, NP) ----------------
__global__ void __launch_bounds__(256) maxreduce_all_kernel() {
    int p = blockIdx.y;
    int n = blockIdx.x * 256 + threadIdx.x;
    size_t pb = (size_t)p * 32 * NN;
    float bm = g_rowmax_part[pb + n]; int bi = g_rowidx_part[pb + n];
    for (int s = 1; s < 32; s++) {
        float v = g_rowmax_part[pb + s * NN + n];
        int i2 = g_rowidx_part[pb + s * NN + n];
        if (v > bm || (v == bm && i2 < bi)) { bm = v; bi = i2; }
    }
    g_rowmax[p * NN + n] = bm; g_rowidx[p * NN + n] = bi;
    bm = g_colmax_part[pb + n]; bi = g_colidx_part[pb + n];
    for (int s = 1; s < 32; s++) {
        float v = g_colmax_part[pb + s * NN + n];
        int i2 = g_colidx_part[pb + s * NN + n];
        if (v > bm || (v == bm && i2 < bi)) { bm = v; bi = i2; }
    }
    g_colmax[p * NN + n] = bm; g_colidx[p * NN + n] = bi;
}

// ---------------- compaction, all pairs: grid NP ----------------
__global__ void __launch_bounds__(1024) compact_all_kernel() {
    __shared__ int tsum[1024];
    int p = blockIdx.x;
    const int* ridx = g_rowidx + p * NN;
    const int* cidx = g_colidx + p * NN;
    int* rlist = g_rowlist + p * NN;
    int* clist = g_collist + p * NN;
    int t = threadIdx.x;
    int flags[8];
    int s = 0;
    #pragma unroll
    for (int u = 0; u < 8; u++) {
        int idx = t * 8 + u;
        int f;
        if (idx < NN) { int n = idx; f = (cidx[ridx[n]] == n); }
        else          { int m = idx - NN; f = (ridx[cidx[m]] == m); }
        flags[u] = f;
        s += f;
    }
    tsum[t] = s;
    __syncthreads();
    for (int off = 1; off < 1024; off <<= 1) {
        int v = (t >= off) ? tsum[t - off] : 0;
        __syncthreads();
        tsum[t] += v;
        __syncthreads();
    }
    int rowtot = tsum[511];
    int total = tsum[1023];
    if (t == 0) { g_nsel[p * 2] = rowtot; g_nsel[p * 2 + 1] = total - rowtot; }
    int run = (t > 0) ? tsum[t - 1] : 0;
    #pragma unroll
    for (int u = 0; u < 8; u++) {
        if (flags[u]) {
            int idx = t * 8 + u;
            if (idx < NN) rlist[run] = idx;
            else          clist[run - rowtot] = idx - NN;
            run++;
        }
    }
    __syncthreads();
    int coltot = total - rowtot;
    for (int i2 = rowtot + t; i2 < NN; i2 += 1024) rlist[i2] = 0;
    for (int i2 = coltot + t; i2 < NN; i2 += 1024) clist[i2] = 0;
}

// ---------------- fused exp (bf16 out), all pairs: grid (128, 128, NP) ---------
__global__ void __launch_bounds__(256) exp_all_kernel() {
    __shared__ float tile[32][33];
    __shared__ int rflag[32], cflag[32];
    int p = blockIdx.z;
    int m0 = blockIdx.x * 32;
    int k0 = blockIdx.y * 32;
    int tx = threadIdx.x & 31;
    int ty = threadIdx.x >> 5;
    const int* ridx = g_rowidx + p * NN;
    const int* cidx = g_colidx + p * NN;
    const float* simp = g_sim + (size_t)p * SIMSZ;
    if (threadIdx.x < 32) {
        int k = k0 + threadIdx.x;
        rflag[threadIdx.x] = (cidx[ridx[k]] == k);
    } else if (threadIdx.x < 64) {
        int m = m0 + threadIdx.x - 32;
        cflag[threadIdx.x - 32] = (ridx[cidx[m]] == m);
    }
    __syncthreads();
    float v[4];
    #pragma unroll
    for (int q = 0; q < 4; q++) {
        int r = ty * 4 + q;
        v[q] = simp[(size_t)(k0 + r) * NN + m0 + tx];
        tile[r][tx] = v[q];
    }
    #pragma unroll
    for (int q = 0; q < 4; q++) {
        int r = ty * 4 + q;
        if (!rflag[r]) continue;
        float e = fast_exp(v[q] - g_rowmax[p * NN + k0 + r]);
        g_p_h[(size_t)p * SIMSZ + (size_t)(k0 + r) * NN + m0 + tx] = __float2bfloat16_rn(e);
    }
    __syncthreads();
    #pragma unroll
    for (int q = 0; q < 4; q++) {
        int r = ty * 4 + q;
        if (!cflag[r]) continue;
        float e = fast_exp(tile[tx][r] - g_colmax[p * NN + m0 + r]);
        g_pT_h[(size_t)p * SIMSZ + (size_t)(m0 + r) * NN + k0 + tx] = __float2bfloat16_rn(e);
    }
}

// ---------------- selected sums (bf16 numerators), all: grid (NN, 2, NP) -------
__global__ void __launch_bounds__(256) sums_all_kernel() {
    int p = blockIdx.z;
    int dir = blockIdx.y;
    int b = blockIdx.x;
    if (b >= g_nsel[p * 2 + dir]) return;
    int row = dir ? g_collist[p * NN + b] : g_rowlist[p * NN + b];
    const __nv_bfloat16* ph = (dir ? g_pT_h : g_p_h) + (size_t)p * SIMSZ + (size_t)row * NN;
    int tid = threadIdx.x;
    float lsum = 0.0f;
    #pragma unroll
    for (int s = 0; s < 16; s++)
        lsum += __bfloat162float(ph[tid + 256 * s]);
    __shared__ float sv[256];
    sv[tid] = lsum;
    __syncthreads();
    for (int off = 128; off > 0; off >>= 1) {
        if (tid < off) sv[tid] += sv[tid + off];
        __syncthreads();
    }
    if (tid == 0) {
        if (dir) g_colsum[p * NN + row] = sv[0];
        else     g_rowsum[p * NN + row] = sv[0];
    }
}

// ---------------- weighted bf16 MMA, 1-term, no split-K: grid (2, 32, NP*2) ----
// Epilogue: normalize by rowsum/colsum and scatter into soft directly.
__global__ void __launch_bounds__(256) gemm_all_kernel() {
    const int p = blockIdx.z >> 1;
    const int dir = blockIdx.z & 1;
    const int m0 = blockIdx.y * 128;
    const int nsel = g_nsel[p * 2 + dir];
    if (m0 >= nsel) return;
    __shared__ __align__(16) char sm[2][16384];

    const int t = threadIdx.x;
    const int lane = t & 31, wid = t >> 5;
    const int m0w = (wid & 3) * 32, n0w = (wid >> 2) * 64;
    const int n0 = blockIdx.x * 128;
    const int lrow = t >> 2, q = t & 3;
    const uint32_t sbase = smem_u32(&sm[0][0]);

    const int* list = (dir ? g_collist : g_rowlist) + p * NN;
    const __nv_bfloat16* Ph = (dir ? g_pT_h : g_p_h) + (size_t)p * SIMSZ;
    const int sv = dir ? c_PI[p] : c_PJ[p];
    const __nv_bfloat16* Sh = g_sfT_h + (size_t)sv * CC * NN;

    const int grow0 = list[m0 + lrow];
    const int grow1 = list[m0 + lrow + 64];

    float acc[2][8][4];
    #pragma unroll
    for (int a = 0; a < 2; a++)
        #pragma unroll
        for (int b = 0; b < 8; b++)
            #pragma unroll
            for (int c = 0; c < 4; c++) acc[a][b][c] = 0.0f;

    uint4 ra0, ra1, rb0, rb1;
    #define W_LDG(KB) do { \
        int kk = (KB) * 32; \
        ra0 = *(const uint4*)(Ph + (size_t)grow0 * NN + kk + q * 8); \
        ra1 = *(const uint4*)(Ph + (size_t)grow1 * NN + kk + q * 8); \
        rb0 = *(const uint4*)(Sh + (size_t)(n0 + lrow) * NN + kk + q * 8); \
        rb1 = *(const uint4*)(Sh + (size_t)(n0 + lrow + 64) * NN + kk + q * 8); \
    } while (0)
    #define W_STS(BUF) do { \
        char* base = &sm[BUF][0]; \
        *(uint4*)(base + swz64(lrow, q)) = ra0; \
        *(uint4*)(base + swz64(lrow + 64, q)) = ra1; \
        *(uint4*)(base + 8192 + swz64(lrow, q)) = rb0; \
        *(uint4*)(base + 8192 + swz64(lrow + 64, q)) = rb1; \
    } while (0)

    W_LDG(0);
    W_STS(0);
    __syncthreads();
    for (int kb = 0; kb < 128; kb++) {
        int buf = kb & 1;
        if (kb + 1 < 128) W_LDG(kb + 1);
        mma_block(sbase + buf * 16384, sbase + buf * 16384 + 8192, lane, m0w, n0w, acc);
        if (kb + 1 < 128) W_STS(buf ^ 1);
        __syncthreads();
    }
    #undef W_LDG
    #undef W_STS

    const int gid = lane >> 2, tig = lane & 3;
    const float* sums = dir ? g_colsum : g_rowsum;
    float* soft = (dir ? g_soft_col : g_soft_row) + (size_t)p * NN * CC;
    #pragma unroll
    for (int mt = 0; mt < 2; mt++) {
        int s0 = m0 + m0w + mt * 16 + gid;
        #pragma unroll
        for (int h = 0; h < 2; h++) {
            int slot = s0 + h * 8;
            if (slot >= nsel) continue;
            int row = list[slot];
            float inv = 1.0f / sums[p * NN + row];
            #pragma unroll
            for (int np = 0; np < 8; np++) {
                int c = n0 + n0w + np * 8 + tig * 2;
                *(float2*)&soft[(size_t)row * CC + c] =
                    make_float2(acc[mt][np][h * 2] * inv, acc[mt][np][h * 2 + 1] * inv);
            }
        }
    }
}

// ---------------- loss, all: grid (32, 2, NP) ----------------
__global__ void __launch_bounds__(256) loss_all_kernel() {
    int p = blockIdx.z;
    int dir = blockIdx.y;
    int tid = threadIdx.x;
    int b = blockIdx.x;
    const int* idxA = (dir ? g_colidx : g_rowidx) + p * NN;
    const int* idxB = (dir ? g_rowidx : g_colidx) + p * NN;
    const float* soft = (dir ? g_soft_col : g_soft_row) + (size_t)p * NN * CC;
    const float* recon = g_recon + (size_t)(dir ? c_PJ[p] : c_PI[p]) * NN * CC;
    int op = dir ? c_OP1[p] : c_OP0[p];
    float relc = g_relWT[op * CC + tid];
    float lsum = 0.0f;
    int lcnt = 0;
    for (int r = 0; r < 128; r++) {
        int row = b * 128 + r;
        int a = idxA[row];
        if (idxB[a] == row) {
            float d = recon[(size_t)row * CC + tid] + relc - soft[(size_t)row * CC + tid];
            lsum += d * d;
            if (tid == 0) lcnt++;
        }
    }
    __shared__ float ss[256];
    ss[tid] = lsum;
    __syncthreads();
    for (int off = 128; off > 0; off >>= 1) {
        if (tid < off) ss[tid] += ss[tid + off];
        __syncthreads();
    }
    if (tid == 0) {
        g_sq_part[op * 32 + b] = ss[0];
        g_cnt_part[op * 32 + b] = lcnt;
    }
}

__global__ void finalize_kernel(float* __restrict__ out) {
    if (threadIdx.x == 0) {
        float total = 0.0f, count = 0.0f;
        for (int op = 0; op < 12; op++) {
            float sq = 0.0f;
            int cnt = 0;
            for (int b = 0; b < 32; b++) {
                sq += g_sq_part[op * 32 + b];
                cnt += g_cnt_part[op * 32 + b];
            }
            if (cnt > 0) {
                total += sq / fmaxf((float)cnt * (float)CC, 1.0f);
                count += 1.0f;
            }
        }
        out[0] = (count > 0.0f) ? (total / fmaxf(count, 1.0f)) : 0.0f;
    }
}

// ---------------- host launch ----------------
extern "C" void kernel_launch(void* const* d_in, const int* in_sizes, int n_in,
                              void* d_out, int out_size)
{
    const float* desc  = (const float*)d_in[0];
    const float* sf    = (const float*)d_in[1];
    const float* T     = (const float*)d_in[2];
    const float* W_rec = (const float*)d_in[3];
    const float* W_T   = (const float*)d_in[4];
    float* out = (float*)d_out;

    normalize_kernel<<<NN * VV, 256>>>(desc);
    sf_split_kernel<<<dim3(NN / 32, CC / 32, VV), 256>>>(sf);
    wr_split_kernel<<<dim3(8, 8), 256>>>(W_rec);
    relwt_kernel<<<12, 256>>>(T, W_T);
    recon_mma_kernel<<<dim3(2, 32, VV), 256>>>();

    sim_all_kernel<<<dim3(32, 32, NP), 256>>>();
    maxreduce_all_kernel<<<dim3(16, NP), 256>>>();
    compact_all_kernel<<<NP, 1024>>>();
    exp_all_kernel<<<dim3(NN / 32, NN / 32, NP), 256>>>();
    sums_all_kernel<<<dim3(NN, 2, NP), 256>>>();
    gemm_all_kernel<<<dim3(2, 32, NP * 2), 256>>>();
    loss_all_kernel<<<dim3(32, 2, NP), 256>>>();

    finalize_kernel<<<1, 32>>>(out);
}

// round 10
// speedup vs baseline: 2.9848x; 1.2407x over previous
#include <cuda_runtime.h>
#include <cuda_bf16.h>
#include <cfloat>
#include <cstddef>
#include <cstdint>

#define NN 4096
#define CC 256
#define VV 4
#define NP 6
#define SIMSZ ((size_t)NN * NN)

// ---------------- scratch (per-pair axes) ----------------
__device__ __nv_bfloat16 g_dnb_h[VV * NN * CC];
__device__ __nv_bfloat16 g_dnb_r[VV * NN * CC];
__device__ __nv_bfloat16 g_sfT_h[VV * CC * NN];
__device__ __nv_bfloat16 g_wrT_h[CC * CC];
__device__ __nv_bfloat16 g_wrT_r[CC * CC];
__device__ float g_recon[VV * NN * CC];
__device__ float g_relWT[12 * CC];
__device__ __nv_bfloat16 g_simb[NP * SIMSZ];
__device__ __nv_bfloat16 g_p_h[NP * SIMSZ];
__device__ __nv_bfloat16 g_pT_h[NP * SIMSZ];

__device__ float g_rowmax_part[NP * 32 * NN];
__device__ int   g_rowidx_part[NP * 32 * NN];
__device__ float g_colmax_part[NP * 32 * NN];
__device__ int   g_colidx_part[NP * 32 * NN];
__device__ float g_rowmax[NP * NN];
__device__ int   g_rowidx[NP * NN];
__device__ float g_colmax[NP * NN];
__device__ int   g_colidx[NP * NN];
__device__ float g_rowsum[NP * NN];
__device__ float g_colsum[NP * NN];
__device__ int   g_rowlist[NP * NN];
__device__ int   g_collist[NP * NN];
__device__ int   g_nsel[NP * 2];

__device__ float g_sprow[(size_t)NP * NN * 128];   // per-32-col-tile row-sum partials
__device__ float g_spcol[(size_t)NP * NN * 128];

__device__ float g_soft_row[NP * NN * CC];
__device__ float g_soft_col[NP * NN * CC];
__device__ float g_sq_part[12 * 32];
__device__ int   g_cnt_part[12 * 32];

__constant__ int c_OPI[12] = {0,0,0,1,1,1,2,2,2,3,3,3};
__constant__ int c_OPJ[12] = {1,2,3,0,2,3,0,1,3,0,1,2};
__constant__ int c_PI[NP]  = {0,0,0,1,1,2};
__constant__ int c_PJ[NP]  = {1,2,3,2,3,3};
__constant__ int c_OP0[NP] = {0,1,2,4,5,8};
__constant__ int c_OP1[NP] = {3,6,9,7,10,11};

// ---------------- helpers ----------------
__device__ __forceinline__ uint32_t smem_u32(const void* p) {
    uint32_t a;
    asm("{ .reg .u64 t; cvta.to.shared.u64 t, %1; cvt.u32.u64 %0, t; }" : "=r"(a) : "l"(p));
    return a;
}
__device__ __forceinline__ uint32_t swz64(int row, int kc) {
    return (uint32_t)(row * 64) + (uint32_t)(((kc ^ ((row >> 1) & 3)) & 3) << 4);
}
__device__ __forceinline__ void ldm_x4(uint32_t addr, uint32_t& r0, uint32_t& r1,
                                       uint32_t& r2, uint32_t& r3) {
    asm volatile("ldmatrix.sync.aligned.m8n8.x4.shared.b16 {%0,%1,%2,%3}, [%4];"
        : "=r"(r0), "=r"(r1), "=r"(r2), "=r"(r3) : "r"(addr));
}
__device__ __forceinline__ void mma_bf16(float* c, const uint32_t* a, uint32_t b0, uint32_t b1) {
    asm volatile("mma.sync.aligned.m16n8k16.row.col.f32.bf16.bf16.f32 "
        "{%0,%1,%2,%3}, {%4,%5,%6,%7}, {%8,%9}, {%0,%1,%2,%3};"
        : "+f"(c[0]), "+f"(c[1]), "+f"(c[2]), "+f"(c[3])
        : "r"(a[0]), "r"(a[1]), "r"(a[2]), "r"(a[3]), "r"(b0), "r"(b1));
}
__device__ __forceinline__ float fast_exp(float x) {
    float y = x * 1.4426950408889634f;
    float n = rintf(y);
    float f = y - n;
    float r = 0.0001540353039338f;
    r = r * f + 0.0013333558146428f;
    r = r * f + 0.0096181291076285f;
    r = r * f + 0.0555041086648216f;
    r = r * f + 0.2402265069591007f;
    r = r * f + 0.6931471805599453f;
    r = r * f + 1.0f;
    return __int_as_float(__float_as_int(r) + ((int)n << 23));
}

__device__ __forceinline__ void mma_block(uint32_t sA, uint32_t sB, int lane,
                                          int m0w, int n0w, float acc[2][8][4]) {
    const int arow = m0w + (lane & 7) + ((lane >> 3) & 1) * 8;
    const int akc  = lane >> 4;
    const int brow = n0w + (lane & 7) + (lane >> 4) * 8;
    const int bkc  = (lane >> 3) & 1;
    #pragma unroll
    for (int ks = 0; ks < 2; ks++) {
        uint32_t a[2][4];
        #pragma unroll
        for (int mt = 0; mt < 2; mt++)
            ldm_x4(sA + swz64(arow + mt * 16, ks * 2 + akc),
                   a[mt][0], a[mt][1], a[mt][2], a[mt][3]);
        #pragma unroll
        for (int np = 0; np < 4; np++) {
            uint32_t b0, b1, b2, b3;
            ldm_x4(sB + swz64(brow + np * 16, ks * 2 + bkc), b0, b1, b2, b3);
            #pragma unroll
            for (int mt = 0; mt < 2; mt++) {
                mma_bf16(acc[mt][np * 2],     a[mt], b0, b1);
                mma_bf16(acc[mt][np * 2 + 1], a[mt], b2, b3);
            }
        }
    }
}

// ---------------- setup kernels ----------------
__global__ void __launch_bounds__(256) normalize_kernel(const float* __restrict__ desc) {
    int rv = blockIdx.x;
    int tid = threadIdx.x;
    __shared__ float ss[256];
    float x = desc[(size_t)rv * CC + tid];
    ss[tid] = x * x;
    __syncthreads();
    for (int off = 128; off > 0; off >>= 1) {
        if (tid < off) ss[tid] += ss[tid + off];
        __syncthreads();
    }
    float den = fmaxf(sqrtf(ss[0]), 1e-12f);
    float y = x / den;
    int n = rv / VV, v = rv % VV;
    __nv_bfloat16 h = __float2bfloat16_rn(y);
    size_t off = (size_t)(v * NN + n) * CC + tid;
    g_dnb_h[off] = h;
    g_dnb_r[off] = __float2bfloat16_rn(y - __bfloat162float(h));
}

__global__ void __launch_bounds__(256) sf_split_kernel(const float* __restrict__ sf) {
    __shared__ float t[32][33];
    int v = blockIdx.z;
    int n0 = blockIdx.x * 32, c0 = blockIdx.y * 32;
    int tx = threadIdx.x & 31, ty = threadIdx.x >> 5;
    #pragma unroll
    for (int q = 0; q < 4; q++) {
        int r = ty * 4 + q;
        t[r][tx] = sf[(size_t)(n0 + r) * (VV * CC) + v * CC + c0 + tx];
    }
    __syncthreads();
    #pragma unroll
    for (int q = 0; q < 4; q++) {
        int r = ty * 4 + q;
        g_sfT_h[(size_t)v * CC * NN + (size_t)(c0 + r) * NN + n0 + tx] =
            __float2bfloat16_rn(t[tx][r]);
    }
}

__global__ void __launch_bounds__(256) wr_split_kernel(const float* __restrict__ W) {
    __shared__ float t[32][33];
    int k0 = blockIdx.y * 32, c0 = blockIdx.x * 32;
    int tx = threadIdx.x & 31, ty = threadIdx.x >> 5;
    #pragma unroll
    for (int q = 0; q < 4; q++) {
        int r = ty * 4 + q;
        t[r][tx] = W[(size_t)(k0 + r) * CC + c0 + tx];
    }
    __syncthreads();
    #pragma unroll
    for (int q = 0; q < 4; q++) {
        int r = ty * 4 + q;
        float x = t[tx][r];
        __nv_bfloat16 h = __float2bfloat16_rn(x);
        size_t off = (size_t)(c0 + r) * CC + k0 + tx;
        g_wrT_h[off] = h;
        g_wrT_r[off] = __float2bfloat16_rn(x - __bfloat162float(h));
    }
}

__global__ void __launch_bounds__(256) relwt_kernel(const float* __restrict__ T,
                                                    const float* __restrict__ WT) {
    int op = blockIdx.x;
    int c = threadIdx.x;
    int i = c_OPI[op], j = c_OPJ[op];
    float s = 0.0f;
    #pragma unroll
    for (int k = 0; k < 16; k++) s += T[i * 16 + k] * WT[k * CC + c];
    #pragma unroll
    for (int k = 0; k < 16; k++) s += T[j * 16 + k] * WT[(16 + k) * CC + c];
    g_relWT[op * CC + c] = s;
}

// ---------------- recon bf16 MMA (3-term), grid (2, 32, VV) ----------------
__global__ void __launch_bounds__(256) recon_mma_kernel() {
    __shared__ __align__(16) char sm[2][16384];
    const int t = threadIdx.x;
    const int lane = t & 31, wid = t >> 5;
    const int m0w = (wid & 3) * 32, n0w = (wid >> 2) * 64;
    const int v = blockIdx.z;
    const int m0 = blockIdx.y * 128, n0 = blockIdx.x * 128;
    const int lrow = t >> 2, q = t & 3;
    const uint32_t sbase = smem_u32(&sm[0][0]);
    const __nv_bfloat16* Ah = g_dnb_h + (size_t)v * NN * CC;
    const __nv_bfloat16* Ar = g_dnb_r + (size_t)v * NN * CC;

    float acc[2][8][4];
    #pragma unroll
    for (int a = 0; a < 2; a++)
        #pragma unroll
        for (int b = 0; b < 8; b++)
            #pragma unroll
            for (int c = 0; c < 4; c++) acc[a][b][c] = 0.0f;

    uint4 ra0, ra1, rb0, rb1;
    #define R_LDG(KB) do { \
        int seg = (KB) >> 3; \
        int kk = ((KB) & 7) << 5; \
        const __nv_bfloat16* ap = (seg == 2) ? Ar : Ah; \
        const __nv_bfloat16* bp = (seg == 1) ? g_wrT_r : g_wrT_h; \
        ra0 = *(const uint4*)(ap + (size_t)(m0 + lrow) * CC + kk + q * 8); \
        ra1 = *(const uint4*)(ap + (size_t)(m0 + lrow + 64) * CC + kk + q * 8); \
        rb0 = *(const uint4*)(bp + (size_t)(n0 + lrow) * CC + kk + q * 8); \
        rb1 = *(const uint4*)(bp + (size_t)(n0 + lrow + 64) * CC + kk + q * 8); \
    } while (0)
    #define R_STS(BUF) do { \
        char* base = &sm[BUF][0]; \
        *(uint4*)(base + swz64(lrow, q)) = ra0; \
        *(uint4*)(base + swz64(lrow + 64, q)) = ra1; \
        *(uint4*)(base + 8192 + swz64(lrow, q)) = rb0; \
        *(uint4*)(base + 8192 + swz64(lrow + 64, q)) = rb1; \
    } while (0)

    R_LDG(0);
    R_STS(0);
    __syncthreads();
    for (int kb = 0; kb < 24; kb++) {
        int buf = kb & 1;
        if (kb + 1 < 24) R_LDG(kb + 1);
        mma_block(sbase + buf * 16384, sbase + buf * 16384 + 8192, lane, m0w, n0w, acc);
        if (kb + 1 < 24) R_STS(buf ^ 1);
        __syncthreads();
    }
    #undef R_LDG
    #undef R_STS

    const int gid = lane >> 2, tig = lane & 3;
    float* C = g_recon + (size_t)v * NN * CC;
    #pragma unroll
    for (int mt = 0; mt < 2; mt++) {
        int r0 = m0 + m0w + mt * 16 + gid;
        #pragma unroll
        for (int np = 0; np < 8; np++) {
            int c = n0 + n0w + np * 8 + tig * 2;
            *(float2*)&C[(size_t)r0 * CC + c] = make_float2(acc[mt][np][0], acc[mt][np][1]);
            *(float2*)&C[(size_t)(r0 + 8) * CC + c] = make_float2(acc[mt][np][2], acc[mt][np][3]);
        }
    }
}

// ---------------- sim bf16 MMA (3-term), all pairs: grid (32, 32, NP) ----------
__global__ void __launch_bounds__(256) sim_all_kernel() {
    __shared__ __align__(16) char sm[2][16384];
    __shared__ float s_rv[2][128];
    __shared__ int   s_ri[2][128];
    __shared__ float s_cv[4][128];
    __shared__ int   s_ci[4][128];

    const int t = threadIdx.x;
    const int lane = t & 31, wid = t >> 5;
    const int m0w = (wid & 3) * 32, n0w = (wid >> 2) * 64;
    const int p = blockIdx.z;
    const int m0 = blockIdx.y * 128, col0 = blockIdx.x * 128;
    const int lrow = t >> 2, q = t & 3;
    const uint32_t sbase = smem_u32(&sm[0][0]);

    const __nv_bfloat16* Ah = g_dnb_h + (size_t)c_PI[p] * NN * CC;
    const __nv_bfloat16* Ar = g_dnb_r + (size_t)c_PI[p] * NN * CC;
    const __nv_bfloat16* Bh = g_dnb_h + (size_t)c_PJ[p] * NN * CC;
    const __nv_bfloat16* Br = g_dnb_r + (size_t)c_PJ[p] * NN * CC;
    __nv_bfloat16* simp = g_simb + (size_t)p * SIMSZ;

    float acc[2][8][4];
    #pragma unroll
    for (int a = 0; a < 2; a++)
        #pragma unroll
        for (int b = 0; b < 8; b++)
            #pragma unroll
            for (int c = 0; c < 4; c++) acc[a][b][c] = 0.0f;

    uint4 ra0, ra1, rb0, rb1;
    // terms: 0: h*h, 1: h*r, 2: r*h  (rr dropped: |rr| ~2e-7 << argmax gaps)
    #define SIM_LDG(KB) do { \
        int seg = (KB) >> 3; \
        int kk = ((KB) & 7) << 5; \
        const __nv_bfloat16* ap = (seg == 2) ? Ar : Ah; \
        const __nv_bfloat16* bp = (seg == 1) ? Br : Bh; \
        ra0 = *(const uint4*)(ap + (size_t)(m0 + lrow) * CC + kk + q * 8); \
        ra1 = *(const uint4*)(ap + (size_t)(m0 + lrow + 64) * CC + kk + q * 8); \
        rb0 = *(const uint4*)(bp + (size_t)(col0 + lrow) * CC + kk + q * 8); \
        rb1 = *(const uint4*)(bp + (size_t)(col0 + lrow + 64) * CC + kk + q * 8); \
    } while (0)
    #define SIM_STS(BUF) do { \
        char* base = &sm[BUF][0]; \
        *(uint4*)(base + swz64(lrow, q)) = ra0; \
        *(uint4*)(base + swz64(lrow + 64, q)) = ra1; \
        *(uint4*)(base + 8192 + swz64(lrow, q)) = rb0; \
        *(uint4*)(base + 8192 + swz64(lrow + 64, q)) = rb1; \
    } while (0)

    SIM_LDG(0);
    SIM_STS(0);
    __syncthreads();
    for (int kb = 0; kb < 24; kb++) {
        int buf = kb & 1;
        if (kb + 1 < 24) SIM_LDG(kb + 1);
        mma_block(sbase + buf * 16384, sbase + buf * 16384 + 8192, lane, m0w, n0w, acc);
        if (kb + 1 < 24) SIM_STS(buf ^ 1);
        __syncthreads();
    }
    #undef SIM_LDG
    #undef SIM_STS

    const int gid = lane >> 2, tig = lane & 3;
    // write sim as bf16 (mask decisions below use fp32 accs)
    #pragma unroll
    for (int mt = 0; mt < 2; mt++) {
        int r0 = m0 + m0w + mt * 16 + gid;
        #pragma unroll
        for (int np = 0; np < 8; np++) {
            int c = col0 + n0w + np * 8 + tig * 2;
            __nv_bfloat162 lo = __float22bfloat162_rn(make_float2(acc[mt][np][0], acc[mt][np][1]));
            __nv_bfloat162 hi = __float22bfloat162_rn(make_float2(acc[mt][np][2], acc[mt][np][3]));
            *(__nv_bfloat162*)&simp[(size_t)r0 * NN + c] = lo;
            *(__nv_bfloat162*)&simp[(size_t)(r0 + 8) * NN + c] = hi;
        }
    }
    #pragma unroll
    for (int mt = 0; mt < 2; mt++)
        #pragma unroll
        for (int h = 0; h < 2; h++) {
            float bv = -FLT_MAX; int bi = 0;
            #pragma unroll
            for (int np = 0; np < 8; np++)
                #pragma unroll
                for (int e = 0; e < 2; e++) {
                    float v = acc[mt][np][h * 2 + e];
                    int c = col0 + n0w + np * 8 + tig * 2 + e;
                    if (v > bv) { bv = v; bi = c; }
                }
            #pragma unroll
            for (int o = 1; o <= 2; o <<= 1) {
                float v2 = __shfl_xor_sync(0xffffffffu, bv, o);
                int i2 = __shfl_xor_sync(0xffffffffu, bi, o);
                if (v2 > bv || (v2 == bv && i2 < bi)) { bv = v2; bi = i2; }
            }
            if (tig == 0) {
                int rl = m0w + mt * 16 + h * 8 + gid;
                s_rv[wid >> 2][rl] = bv;
                s_ri[wid >> 2][rl] = bi;
            }
        }
    #pragma unroll
    for (int np = 0; np < 8; np++)
        #pragma unroll
        for (int e = 0; e < 2; e++) {
            float bv = -FLT_MAX; int bi = 0;
            #pragma unroll
            for (int mt = 0; mt < 2; mt++)
                #pragma unroll
                for (int h = 0; h < 2; h++) {
                    float v = acc[mt][np][h * 2 + e];
                    int r = m0 + m0w + mt * 16 + h * 8 + gid;
                    if (v > bv) { bv = v; bi = r; }
                }
            #pragma unroll
            for (int o = 4; o <= 16; o <<= 1) {
                float v2 = __shfl_xor_sync(0xffffffffu, bv, o);
                int i2 = __shfl_xor_sync(0xffffffffu, bi, o);
                if (v2 > bv || (v2 == bv && i2 < bi)) { bv = v2; bi = i2; }
            }
            if (gid == 0) {
                int cl = n0w + np * 8 + tig * 2 + e;
                s_cv[wid & 3][cl] = bv;
                s_ci[wid & 3][cl] = bi;
            }
        }
    __syncthreads();
    if (t < 128) {
        float bv = s_rv[0][t]; int bi = s_ri[0][t];
        if (s_rv[1][t] > bv || (s_rv[1][t] == bv && s_ri[1][t] < bi)) { bv = s_rv[1][t]; bi = s_ri[1][t]; }
        g_rowmax_part[(size_t)p * 32 * NN + blockIdx.x * NN + m0 + t] = bv;
        g_rowidx_part[(size_t)p * 32 * NN + blockIdx.x * NN + m0 + t] = bi;
        float cv = s_cv[0][t]; int ci = s_ci[0][t];
        #pragma unroll
        for (int w = 1; w < 4; w++) {
            if (s_cv[w][t] > cv || (s_cv[w][t] == cv && s_ci[w][t] < ci)) { cv = s_cv[w][t]; ci = s_ci[w][t]; }
        }
        g_colmax_part[(size_t)p * 32 * NN + blockIdx.y * NN + col0 + t] = cv;
        g_colidx_part[(size_t)p * 32 * NN + blockIdx.y * NN + col0 + t] = ci;
    }
}

// ---------------- max reduce, all pairs: grid (16, NP) ----------------
__global__ void __launch_bounds__(256) maxreduce_all_kernel() {
    int p = blockIdx.y;
    int n = blockIdx.x * 256 + threadIdx.x;
    size_t pb = (size_t)p * 32 * NN;
    float bm = g_rowmax_part[pb + n]; int bi = g_rowidx_part[pb + n];
    for (int s = 1; s < 32; s++) {
        float v = g_rowmax_part[pb + s * NN + n];
        int i2 = g_rowidx_part[pb + s * NN + n];
        if (v > bm || (v == bm && i2 < bi)) { bm = v; bi = i2; }
    }
    g_rowmax[p * NN + n] = bm; g_rowidx[p * NN + n] = bi;
    bm = g_colmax_part[pb + n]; bi = g_colidx_part[pb + n];
    for (int s = 1; s < 32; s++) {
        float v = g_colmax_part[pb + s * NN + n];
        int i2 = g_colidx_part[pb + s * NN + n];
        if (v > bm || (v == bm && i2 < bi)) { bm = v; bi = i2; }
    }
    g_colmax[p * NN + n] = bm; g_colidx[p * NN + n] = bi;
}

// ---------------- compaction, all pairs: grid NP ----------------
__global__ void __launch_bounds__(1024) compact_all_kernel() {
    __shared__ int tsum[1024];
    int p = blockIdx.x;
    const int* ridx = g_rowidx + p * NN;
    const int* cidx = g_colidx + p * NN;
    int* rlist = g_rowlist + p * NN;
    int* clist = g_collist + p * NN;
    int t = threadIdx.x;
    int flags[8];
    int s = 0;
    #pragma unroll
    for (int u = 0; u < 8; u++) {
        int idx = t * 8 + u;
        int f;
        if (idx < NN) { int n = idx; f = (cidx[ridx[n]] == n); }
        else          { int m = idx - NN; f = (ridx[cidx[m]] == m); }
        flags[u] = f;
        s += f;
    }
    tsum[t] = s;
    __syncthreads();
    for (int off = 1; off < 1024; off <<= 1) {
        int v = (t >= off) ? tsum[t - off] : 0;
        __syncthreads();
        tsum[t] += v;
        __syncthreads();
    }
    int rowtot = tsum[511];
    int total = tsum[1023];
    if (t == 0) { g_nsel[p * 2] = rowtot; g_nsel[p * 2 + 1] = total - rowtot; }
    int run = (t > 0) ? tsum[t - 1] : 0;
    #pragma unroll
    for (int u = 0; u < 8; u++) {
        if (flags[u]) {
            int idx = t * 8 + u;
            if (idx < NN) rlist[run] = idx;
            else          clist[run - rowtot] = idx - NN;
            run++;
        }
    }
    __syncthreads();
    int coltot = total - rowtot;
    for (int i2 = rowtot + t; i2 < NN; i2 += 1024) rlist[i2] = 0;
    for (int i2 = coltot + t; i2 < NN; i2 += 1024) clist[i2] = 0;
}

// ---------------- fused exp + sum partials, all pairs: grid (128, 128, NP) ------
__global__ void __launch_bounds__(256) exp_all_kernel() {
    __shared__ float tile[32][33];
    __shared__ int rflag[32], cflag[32];
    int p = blockIdx.z;
    int m0 = blockIdx.x * 32;
    int k0 = blockIdx.y * 32;
    int tx = threadIdx.x & 31;
    int ty = threadIdx.x >> 5;
    const int* ridx = g_rowidx + p * NN;
    const int* cidx = g_colidx + p * NN;
    const __nv_bfloat16* simp = g_simb + (size_t)p * SIMSZ;
    if (threadIdx.x < 32) {
        int k = k0 + threadIdx.x;
        rflag[threadIdx.x] = (cidx[ridx[k]] == k);
    } else if (threadIdx.x < 64) {
        int m = m0 + threadIdx.x - 32;
        cflag[threadIdx.x - 32] = (ridx[cidx[m]] == m);
    }
    __syncthreads();
    float v[4];
    #pragma unroll
    for (int q = 0; q < 4; q++) {
        int r = ty * 4 + q;
        v[q] = __bfloat162float(simp[(size_t)(k0 + r) * NN + m0 + tx]);
        tile[r][tx] = v[q];
    }
    // row dir: p[k][m], partial row sums over this 32-col tile (warp = one row per q)
    #pragma unroll
    for (int q = 0; q < 4; q++) {
        int r = ty * 4 + q;
        if (!rflag[r]) continue;
        float e = fast_exp(v[q] - g_rowmax[p * NN + k0 + r]);
        g_p_h[(size_t)p * SIMSZ + (size_t)(k0 + r) * NN + m0 + tx] = __float2bfloat16_rn(e);
        float s = e;
        #pragma unroll
        for (int o = 16; o > 0; o >>= 1) s += __shfl_xor_sync(0xffffffffu, s, o);
        if (tx == 0)
            g_sprow[(size_t)p * NN * 128 + (size_t)(k0 + r) * 128 + (m0 >> 5)] = s;
    }
    __syncthreads();
    // col dir: pT[m][k], partial sums over this 32-k tile
    #pragma unroll
    for (int q = 0; q < 4; q++) {
        int r = ty * 4 + q;
        if (!cflag[r]) continue;
        float e = fast_exp(tile[tx][r] - g_colmax[p * NN + m0 + r]);
        g_pT_h[(size_t)p * SIMSZ + (size_t)(m0 + r) * NN + k0 + tx] = __float2bfloat16_rn(e);
        float s = e;
        #pragma unroll
        for (int o = 16; o > 0; o >>= 1) s += __shfl_xor_sync(0xffffffffu, s, o);
        if (tx == 0)
            g_spcol[(size_t)p * NN * 128 + (size_t)(m0 + r) * 128 + (k0 >> 5)] = s;
    }
}

// ---------------- sums from partials, all: grid (NN, 2, NP), 128 thr -----------
__global__ void __launch_bounds__(128) sums_all_kernel() {
    int p = blockIdx.z;
    int dir = blockIdx.y;
    int b = blockIdx.x;
    if (b >= g_nsel[p * 2 + dir]) return;
    int row = dir ? g_collist[p * NN + b] : g_rowlist[p * NN + b];
    const float* part = (dir ? g_spcol : g_sprow) + (size_t)p * NN * 128 + (size_t)row * 128;
    int t = threadIdx.x;
    __shared__ float sv[128];
    sv[t] = part[t];
    __syncthreads();
    for (int off = 64; off > 0; off >>= 1) {
        if (t < off) sv[t] += sv[t + off];
        __syncthreads();
    }
    if (t == 0) {
        if (dir) g_colsum[p * NN + row] = sv[0];
        else     g_rowsum[p * NN + row] = sv[0];
    }
}

// ---------------- weighted bf16 MMA, 1-term: grid (2, 32, NP*2) ----------------
__global__ void __launch_bounds__(256) gemm_all_kernel() {
    const int p = blockIdx.z >> 1;
    const int dir = blockIdx.z & 1;
    const int m0 = blockIdx.y * 128;
    const int nsel = g_nsel[p * 2 + dir];
    if (m0 >= nsel) return;
    __shared__ __align__(16) char sm[2][16384];

    const int t = threadIdx.x;
    const int lane = t & 31, wid = t >> 5;
    const int m0w = (wid & 3) * 32, n0w = (wid >> 2) * 64;
    const int n0 = blockIdx.x * 128;
    const int lrow = t >> 2, q = t & 3;
    const uint32_t sbase = smem_u32(&sm[0][0]);

    const int* list = (dir ? g_collist : g_rowlist) + p * NN;
    const __nv_bfloat16* Ph = (dir ? g_pT_h : g_p_h) + (size_t)p * SIMSZ;
    const int sv = dir ? c_PI[p] : c_PJ[p];
    const __nv_bfloat16* Sh = g_sfT_h + (size_t)sv * CC * NN;

    const int grow0 = list[m0 + lrow];
    const int grow1 = list[m0 + lrow + 64];

    float acc[2][8][4];
    #pragma unroll
    for (int a = 0; a < 2; a++)
        #pragma unroll
        for (int b = 0; b < 8; b++)
            #pragma unroll
            for (int c = 0; c < 4; c++) acc[a][b][c] = 0.0f;

    uint4 ra0, ra1, rb0, rb1;
    #define W_LDG(KB) do { \
        int kk = (KB) * 32; \
        ra0 = *(const uint4*)(Ph + (size_t)grow0 * NN + kk + q * 8); \
        ra1 = *(const uint4*)(Ph + (size_t)grow1 * NN + kk + q * 8); \
        rb0 = *(const uint4*)(Sh + (size_t)(n0 + lrow) * NN + kk + q * 8); \
        rb1 = *(const uint4*)(Sh + (size_t)(n0 + lrow + 64) * NN + kk + q * 8); \
    } while (0)
    #define W_STS(BUF) do { \
        char* base = &sm[BUF][0]; \
        *(uint4*)(base + swz64(lrow, q)) = ra0; \
        *(uint4*)(base + swz64(lrow + 64, q)) = ra1; \
        *(uint4*)(base + 8192 + swz64(lrow, q)) = rb0; \
        *(uint4*)(base + 8192 + swz64(lrow + 64, q)) = rb1; \
    } while (0)

    W_LDG(0);
    W_STS(0);
    __syncthreads();
    for (int kb = 0; kb < 128; kb++) {
        int buf = kb & 1;
        if (kb + 1 < 128) W_LDG(kb + 1);
        mma_block(sbase + buf * 16384, sbase + buf * 16384 + 8192, lane, m0w, n0w, acc);
        if (kb + 1 < 128) W_STS(buf ^ 1);
        __syncthreads();
    }
    #undef W_LDG
    #undef W_STS

    const int gid = lane >> 2, tig = lane & 3;
    const float* sums = dir ? g_colsum : g_rowsum;
    float* soft = (dir ? g_soft_col : g_soft_row) + (size_t)p * NN * CC;
    #pragma unroll
    for (int mt = 0; mt < 2; mt++) {
        int s0 = m0 + m0w + mt * 16 + gid;
        #pragma unroll
        for (int h = 0; h < 2; h++) {
            int slot = s0 + h * 8;
            if (slot >= nsel) continue;
            int row = list[slot];
            float inv = 1.0f / sums[p * NN + row];
            #pragma unroll
            for (int np = 0; np < 8; np++) {
                int c = n0 + n0w + np * 8 + tig * 2;
                *(float2*)&soft[(size_t)row * CC + c] =
                    make_float2(acc[mt][np][h * 2] * inv, acc[mt][np][h * 2 + 1] * inv);
            }
        }
    }
}

// ---------------- loss, all: grid (32, 2, NP) ----------------
__global__ void __launch_bounds__(256) loss_all_kernel() {
    int p = blockIdx.z;
    int dir = blockIdx.y;
    int tid = threadIdx.x;
    int b = blockIdx.x;
    const int* idxA = (dir ? g_colidx : g_rowidx) + p * NN;
    const int* idxB = (dir ? g_rowidx : g_colidx) + p * NN;
    const float* soft = (dir ? g_soft_col : g_soft_row) + (size_t)p * NN * CC;
    const float* recon = g_recon + (size_t)(dir ? c_PJ[p] : c_PI[p]) * NN * CC;
    int op = dir ? c_OP1[p] : c_OP0[p];
    float relc = g_relWT[op * CC + tid];
    float lsum = 0.0f;
    int lcnt = 0;
    for (int r = 0; r < 128; r++) {
        int row = b * 128 + r;
        int a = idxA[row];
        if (idxB[a] == row) {
            float d = recon[(size_t)row * CC + tid] + relc - soft[(size_t)row * CC + tid];
            lsum += d * d;
            if (tid == 0) lcnt++;
        }
    }
    __shared__ float ss[256];
    ss[tid] = lsum;
    __syncthreads();
    for (int off = 128; off > 0; off >>= 1) {
        if (tid < off) ss[tid] += ss[tid + off];
        __syncthreads();
    }
    if (tid == 0) {
        g_sq_part[op * 32 + b] = ss[0];
        g_cnt_part[op * 32 + b] = lcnt;
    }
}

__global__ void finalize_kernel(float* __restrict__ out) {
    if (threadIdx.x == 0) {
        float total = 0.0f, count = 0.0f;
        for (int op = 0; op < 12; op++) {
            float sq = 0.0f;
            int cnt = 0;
            for (int b = 0; b < 32; b++) {
                sq += g_sq_part[op * 32 + b];
                cnt += g_cnt_part[op * 32 + b];
            }
            if (cnt > 0) {
                total += sq / fmaxf((float)cnt * (float)CC, 1.0f);
                count += 1.0f;
            }
        }
        out[0] = (count > 0.0f) ? (total / fmaxf(count, 1.0f)) : 0.0f;
    }
}

// ---------------- host launch ----------------
extern "C" void kernel_launch(void* const* d_in, const int* in_sizes, int n_in,
                              void* d_out, int out_size)
{
    const float* desc  = (const float*)d_in[0];
    const float* sf    = (const float*)d_in[1];
    const float* T     = (const float*)d_in[2];
    const float* W_rec = (const float*)d_in[3];
    const float* W_T   = (const float*)d_in[4];
    float* out = (float*)d_out;

    normalize_kernel<<<NN * VV, 256>>>(desc);
    sf_split_kernel<<<dim3(NN / 32, CC / 32, VV), 256>>>(sf);
    wr_split_kernel<<<dim3(8, 8), 256>>>(W_rec);
    relwt_kernel<<<12, 256>>>(T, W_T);
    recon_mma_kernel<<<dim3(2, 32, VV), 256>>>();

    sim_all_kernel<<<dim3(32, 32, NP), 256>>>();
    maxreduce_all_kernel<<<dim3(16, NP), 256>>>();
    compact_all_kernel<<<NP, 1024>>>();
    exp_all_kernel<<<dim3(NN / 32, NN / 32, NP), 256>>>();
    sums_all_kernel<<<dim3(NN, 2, NP), 128>>>();
    gemm_all_kernel<<<dim3(2, 32, NP * 2), 256>>>();
    loss_all_kernel<<<dim3(32, 2, NP), 256>>>();

    finalize_kernel<<<1, 32>>>(out);
}

// round 11
// speedup vs baseline: 3.4324x; 1.1499x over previous
#include <cuda_runtime.h>
#include <cuda_bf16.h>
#include <cfloat>
#include <cstddef>
#include <cstdint>

#define NN 4096
#define CC 256
#define VV 4
#define NP 6
#define SIMSZ ((size_t)NN * NN)

// ---------------- scratch (per-pair axes) ----------------
__device__ __nv_bfloat16 g_dnb_h[VV * NN * CC];
__device__ __nv_bfloat16 g_dnb_r[VV * NN * CC];
__device__ __nv_bfloat16 g_sfT_h[VV * CC * NN];
__device__ __nv_bfloat16 g_wrT_h[CC * CC];
__device__ __nv_bfloat16 g_wrT_r[CC * CC];
__device__ float g_recon[VV * NN * CC];
__device__ float g_relWT[12 * CC];
__device__ __nv_bfloat16 g_simb[NP * SIMSZ];
__device__ __nv_bfloat16 g_p_h[NP * SIMSZ];
__device__ __nv_bfloat16 g_pT_h[NP * SIMSZ];

__device__ float g_rowmax_part[NP * 32 * NN];
__device__ int   g_rowidx_part[NP * 32 * NN];
__device__ float g_colmax_part[NP * 32 * NN];
__device__ int   g_colidx_part[NP * 32 * NN];
__device__ float g_rowmax[NP * NN];
__device__ int   g_rowidx[NP * NN];
__device__ float g_colmax[NP * NN];
__device__ int   g_colidx[NP * NN];
__device__ float g_rowsum[NP * NN];
__device__ float g_colsum[NP * NN];
__device__ int   g_rowlist[NP * NN];
__device__ int   g_collist[NP * NN];
__device__ int   g_nsel[NP * 2];

__device__ float g_sprow[(size_t)NP * NN * 64];   // per-64-col-tile row-sum partials
__device__ float g_spcol[(size_t)NP * NN * 64];

__device__ float g_soft_row[NP * NN * CC];
__device__ float g_soft_col[NP * NN * CC];
__device__ float g_sq_part[12 * 32];
__device__ int   g_cnt_part[12 * 32];

__constant__ int c_OPI[12] = {0,0,0,1,1,1,2,2,2,3,3,3};
__constant__ int c_OPJ[12] = {1,2,3,0,2,3,0,1,3,0,1,2};
__constant__ int c_PI[NP]  = {0,0,0,1,1,2};
__constant__ int c_PJ[NP]  = {1,2,3,2,3,3};
__constant__ int c_OP0[NP] = {0,1,2,4,5,8};
__constant__ int c_OP1[NP] = {3,6,9,7,10,11};

// ---------------- helpers ----------------
__device__ __forceinline__ uint32_t smem_u32(const void* p) {
    uint32_t a;
    asm("{ .reg .u64 t; cvta.to.shared.u64 t, %1; cvt.u32.u64 %0, t; }" : "=r"(a) : "l"(p));
    return a;
}
__device__ __forceinline__ uint32_t swz64(int row, int kc) {
    return (uint32_t)(row * 64) + (uint32_t)(((kc ^ ((row >> 1) & 3)) & 3) << 4);
}
__device__ __forceinline__ void ldm_x4(uint32_t addr, uint32_t& r0, uint32_t& r1,
                                       uint32_t& r2, uint32_t& r3) {
    asm volatile("ldmatrix.sync.aligned.m8n8.x4.shared.b16 {%0,%1,%2,%3}, [%4];"
        : "=r"(r0), "=r"(r1), "=r"(r2), "=r"(r3) : "r"(addr));
}
__device__ __forceinline__ void mma_bf16(float* c, const uint32_t* a, uint32_t b0, uint32_t b1) {
    asm volatile("mma.sync.aligned.m16n8k16.row.col.f32.bf16.bf16.f32 "
        "{%0,%1,%2,%3}, {%4,%5,%6,%7}, {%8,%9}, {%0,%1,%2,%3};"
        : "+f"(c[0]), "+f"(c[1]), "+f"(c[2]), "+f"(c[3])
        : "r"(a[0]), "r"(a[1]), "r"(a[2]), "r"(a[3]), "r"(b0), "r"(b1));
}
__device__ __forceinline__ float fast_exp(float x) {
    float y = x * 1.4426950408889634f;
    float n = rintf(y);
    float f = y - n;
    float r = 0.0001540353039338f;
    r = r * f + 0.0013333558146428f;
    r = r * f + 0.0096181291076285f;
    r = r * f + 0.0555041086648216f;
    r = r * f + 0.2402265069591007f;
    r = r * f + 0.6931471805599453f;
    r = r * f + 1.0f;
    return __int_as_float(__float_as_int(r) + ((int)n << 23));
}

__device__ __forceinline__ void mma_block(uint32_t sA, uint32_t sB, int lane,
                                          int m0w, int n0w, float acc[2][8][4]) {
    const int arow = m0w + (lane & 7) + ((lane >> 3) & 1) * 8;
    const int akc  = lane >> 4;
    const int brow = n0w + (lane & 7) + (lane >> 4) * 8;
    const int bkc  = (lane >> 3) & 1;
    #pragma unroll
    for (int ks = 0; ks < 2; ks++) {
        uint32_t a[2][4];
        #pragma unroll
        for (int mt = 0; mt < 2; mt++)
            ldm_x4(sA + swz64(arow + mt * 16, ks * 2 + akc),
                   a[mt][0], a[mt][1], a[mt][2], a[mt][3]);
        #pragma unroll
        for (int np = 0; np < 4; np++) {
            uint32_t b0, b1, b2, b3;
            ldm_x4(sB + swz64(brow + np * 16, ks * 2 + bkc), b0, b1, b2, b3);
            #pragma unroll
            for (int mt = 0; mt < 2; mt++) {
                mma_bf16(acc[mt][np * 2],     a[mt], b0, b1);
                mma_bf16(acc[mt][np * 2 + 1], a[mt], b2, b3);
            }
        }
    }
}

// ---------------- setup kernels ----------------
__global__ void __launch_bounds__(256) normalize_kernel(const float* __restrict__ desc) {
    int rv = blockIdx.x;
    int tid = threadIdx.x;
    __shared__ float ss[256];
    float x = desc[(size_t)rv * CC + tid];
    ss[tid] = x * x;
    __syncthreads();
    for (int off = 128; off > 0; off >>= 1) {
        if (tid < off) ss[tid] += ss[tid + off];
        __syncthreads();
    }
    float den = fmaxf(sqrtf(ss[0]), 1e-12f);
    float y = x / den;
    int n = rv / VV, v = rv % VV;
    __nv_bfloat16 h = __float2bfloat16_rn(y);
    size_t off = (size_t)(v * NN + n) * CC + tid;
    g_dnb_h[off] = h;
    g_dnb_r[off] = __float2bfloat16_rn(y - __bfloat162float(h));
}

__global__ void __launch_bounds__(256) sf_split_kernel(const float* __restrict__ sf) {
    __shared__ float t[32][33];
    int v = blockIdx.z;
    int n0 = blockIdx.x * 32, c0 = blockIdx.y * 32;
    int tx = threadIdx.x & 31, ty = threadIdx.x >> 5;
    #pragma unroll
    for (int q = 0; q < 4; q++) {
        int r = ty * 4 + q;
        t[r][tx] = sf[(size_t)(n0 + r) * (VV * CC) + v * CC + c0 + tx];
    }
    __syncthreads();
    #pragma unroll
    for (int q = 0; q < 4; q++) {
        int r = ty * 4 + q;
        g_sfT_h[(size_t)v * CC * NN + (size_t)(c0 + r) * NN + n0 + tx] =
            __float2bfloat16_rn(t[tx][r]);
    }
}

__global__ void __launch_bounds__(256) wr_split_kernel(const float* __restrict__ W) {
    __shared__ float t[32][33];
    int k0 = blockIdx.y * 32, c0 = blockIdx.x * 32;
    int tx = threadIdx.x & 31, ty = threadIdx.x >> 5;
    #pragma unroll
    for (int q = 0; q < 4; q++) {
        int r = ty * 4 + q;
        t[r][tx] = W[(size_t)(k0 + r) * CC + c0 + tx];
    }
    __syncthreads();
    #pragma unroll
    for (int q = 0; q < 4; q++) {
        int r = ty * 4 + q;
        float x = t[tx][r];
        __nv_bfloat16 h = __float2bfloat16_rn(x);
        size_t off = (size_t)(c0 + r) * CC + k0 + tx;
        g_wrT_h[off] = h;
        g_wrT_r[off] = __float2bfloat16_rn(x - __bfloat162float(h));
    }
}

__global__ void __launch_bounds__(256) relwt_kernel(const float* __restrict__ T,
                                                    const float* __restrict__ WT) {
    int op = blockIdx.x;
    int c = threadIdx.x;
    int i = c_OPI[op], j = c_OPJ[op];
    float s = 0.0f;
    #pragma unroll
    for (int k = 0; k < 16; k++) s += T[i * 16 + k] * WT[k * CC + c];
    #pragma unroll
    for (int k = 0; k < 16; k++) s += T[j * 16 + k] * WT[(16 + k) * CC + c];
    g_relWT[op * CC + c] = s;
}

// ---------------- recon bf16 MMA (3-term), grid (2, 32, VV) ----------------
__global__ void __launch_bounds__(256) recon_mma_kernel() {
    __shared__ __align__(16) char sm[2][16384];
    const int t = threadIdx.x;
    const int lane = t & 31, wid = t >> 5;
    const int m0w = (wid & 3) * 32, n0w = (wid >> 2) * 64;
    const int v = blockIdx.z;
    const int m0 = blockIdx.y * 128, n0 = blockIdx.x * 128;
    const int lrow = t >> 2, q = t & 3;
    const uint32_t sbase = smem_u32(&sm[0][0]);
    const __nv_bfloat16* Ah = g_dnb_h + (size_t)v * NN * CC;
    const __nv_bfloat16* Ar = g_dnb_r + (size_t)v * NN * CC;

    float acc[2][8][4];
    #pragma unroll
    for (int a = 0; a < 2; a++)
        #pragma unroll
        for (int b = 0; b < 8; b++)
            #pragma unroll
            for (int c = 0; c < 4; c++) acc[a][b][c] = 0.0f;

    uint4 ra0, ra1, rb0, rb1;
    #define R_LDG(KB) do { \
        int seg = (KB) >> 3; \
        int kk = ((KB) & 7) << 5; \
        const __nv_bfloat16* ap = (seg == 2) ? Ar : Ah; \
        const __nv_bfloat16* bp = (seg == 1) ? g_wrT_r : g_wrT_h; \
        ra0 = *(const uint4*)(ap + (size_t)(m0 + lrow) * CC + kk + q * 8); \
        ra1 = *(const uint4*)(ap + (size_t)(m0 + lrow + 64) * CC + kk + q * 8); \
        rb0 = *(const uint4*)(bp + (size_t)(n0 + lrow) * CC + kk + q * 8); \
        rb1 = *(const uint4*)(bp + (size_t)(n0 + lrow + 64) * CC + kk + q * 8); \
    } while (0)
    #define R_STS(BUF) do { \
        char* base = &sm[BUF][0]; \
        *(uint4*)(base + swz64(lrow, q)) = ra0; \
        *(uint4*)(base + swz64(lrow + 64, q)) = ra1; \
        *(uint4*)(base + 8192 + swz64(lrow, q)) = rb0; \
        *(uint4*)(base + 8192 + swz64(lrow + 64, q)) = rb1; \
    } while (0)

    R_LDG(0);
    R_STS(0);
    __syncthreads();
    for (int kb = 0; kb < 24; kb++) {
        int buf = kb & 1;
        if (kb + 1 < 24) R_LDG(kb + 1);
        mma_block(sbase + buf * 16384, sbase + buf * 16384 + 8192, lane, m0w, n0w, acc);
        if (kb + 1 < 24) R_STS(buf ^ 1);
        __syncthreads();
    }
    #undef R_LDG
    #undef R_STS

    const int gid = lane >> 2, tig = lane & 3;
    float* C = g_recon + (size_t)v * NN * CC;
    #pragma unroll
    for (int mt = 0; mt < 2; mt++) {
        int r0 = m0 + m0w + mt * 16 + gid;
        #pragma unroll
        for (int np = 0; np < 8; np++) {
            int c = n0 + n0w + np * 8 + tig * 2;
            *(float2*)&C[(size_t)r0 * CC + c] = make_float2(acc[mt][np][0], acc[mt][np][1]);
            *(float2*)&C[(size_t)(r0 + 8) * CC + c] = make_float2(acc[mt][np][2], acc[mt][np][3]);
        }
    }
}

// ---------------- sim bf16 MMA (3-term), all pairs: grid (32, 32, NP) ----------
__global__ void __launch_bounds__(256) sim_all_kernel() {
    __shared__ __align__(16) char sm[2][16384];
    __shared__ float s_rv[2][128];
    __shared__ int   s_ri[2][128];
    __shared__ float s_cv[4][128];
    __shared__ int   s_ci[4][128];

    const int t = threadIdx.x;
    const int lane = t & 31, wid = t >> 5;
    const int m0w = (wid & 3) * 32, n0w = (wid >> 2) * 64;
    const int p = blockIdx.z;
    const int m0 = blockIdx.y * 128, col0 = blockIdx.x * 128;
    const int lrow = t >> 2, q = t & 3;
    const uint32_t sbase = smem_u32(&sm[0][0]);

    const __nv_bfloat16* Ah = g_dnb_h + (size_t)c_PI[p] * NN * CC;
    const __nv_bfloat16* Ar = g_dnb_r + (size_t)c_PI[p] * NN * CC;
    const __nv_bfloat16* Bh = g_dnb_h + (size_t)c_PJ[p] * NN * CC;
    const __nv_bfloat16* Br = g_dnb_r + (size_t)c_PJ[p] * NN * CC;
    __nv_bfloat16* simp = g_simb + (size_t)p * SIMSZ;

    float acc[2][8][4];
    #pragma unroll
    for (int a = 0; a < 2; a++)
        #pragma unroll
        for (int b = 0; b < 8; b++)
            #pragma unroll
            for (int c = 0; c < 4; c++) acc[a][b][c] = 0.0f;

    uint4 ra0, ra1, rb0, rb1;
    // terms: 0: h*h, 1: h*r, 2: r*h  (rr dropped)
    #define SIM_LDG(KB) do { \
        int seg = (KB) >> 3; \
        int kk = ((KB) & 7) << 5; \
        const __nv_bfloat16* ap = (seg == 2) ? Ar : Ah; \
        const __nv_bfloat16* bp = (seg == 1) ? Br : Bh; \
        ra0 = *(const uint4*)(ap + (size_t)(m0 + lrow) * CC + kk + q * 8); \
        ra1 = *(const uint4*)(ap + (size_t)(m0 + lrow + 64) * CC + kk + q * 8); \
        rb0 = *(const uint4*)(bp + (size_t)(col0 + lrow) * CC + kk + q * 8); \
        rb1 = *(const uint4*)(bp + (size_t)(col0 + lrow + 64) * CC + kk + q * 8); \
    } while (0)
    #define SIM_STS(BUF) do { \
        char* base = &sm[BUF][0]; \
        *(uint4*)(base + swz64(lrow, q)) = ra0; \
        *(uint4*)(base + swz64(lrow + 64, q)) = ra1; \
        *(uint4*)(base + 8192 + swz64(lrow, q)) = rb0; \
        *(uint4*)(base + 8192 + swz64(lrow + 64, q)) = rb1; \
    } while (0)

    SIM_LDG(0);
    SIM_STS(0);
    __syncthreads();
    for (int kb = 0; kb < 24; kb++) {
        int buf = kb & 1;
        if (kb + 1 < 24) SIM_LDG(kb + 1);
        mma_block(sbase + buf * 16384, sbase + buf * 16384 + 8192, lane, m0w, n0w, acc);
        if (kb + 1 < 24) SIM_STS(buf ^ 1);
        __syncthreads();
    }
    #undef SIM_LDG
    #undef SIM_STS

    const int gid = lane >> 2, tig = lane & 3;
    #pragma unroll
    for (int mt = 0; mt < 2; mt++) {
        int r0 = m0 + m0w + mt * 16 + gid;
        #pragma unroll
        for (int np = 0; np < 8; np++) {
            int c = col0 + n0w + np * 8 + tig * 2;
            __nv_bfloat162 lo = __float22bfloat162_rn(make_float2(acc[mt][np][0], acc[mt][np][1]));
            __nv_bfloat162 hi = __float22bfloat162_rn(make_float2(acc[mt][np][2], acc[mt][np][3]));
            *(__nv_bfloat162*)&simp[(size_t)r0 * NN + c] = lo;
            *(__nv_bfloat162*)&simp[(size_t)(r0 + 8) * NN + c] = hi;
        }
    }
    #pragma unroll
    for (int mt = 0; mt < 2; mt++)
        #pragma unroll
        for (int h = 0; h < 2; h++) {
            float bv = -FLT_MAX; int bi = 0;
            #pragma unroll
            for (int np = 0; np < 8; np++)
                #pragma unroll
                for (int e = 0; e < 2; e++) {
                    float v = acc[mt][np][h * 2 + e];
                    int c = col0 + n0w + np * 8 + tig * 2 + e;
                    if (v > bv) { bv = v; bi = c; }
                }
            #pragma unroll
            for (int o = 1; o <= 2; o <<= 1) {
                float v2 = __shfl_xor_sync(0xffffffffu, bv, o);
                int i2 = __shfl_xor_sync(0xffffffffu, bi, o);
                if (v2 > bv || (v2 == bv && i2 < bi)) { bv = v2; bi = i2; }
            }
            if (tig == 0) {
                int rl = m0w + mt * 16 + h * 8 + gid;
                s_rv[wid >> 2][rl] = bv;
                s_ri[wid >> 2][rl] = bi;
            }
        }
    #pragma unroll
    for (int np = 0; np < 8; np++)
        #pragma unroll
        for (int e = 0; e < 2; e++) {
            float bv = -FLT_MAX; int bi = 0;
            #pragma unroll
            for (int mt = 0; mt < 2; mt++)
                #pragma unroll
                for (int h = 0; h < 2; h++) {
                    float v = acc[mt][np][h * 2 + e];
                    int r = m0 + m0w + mt * 16 + h * 8 + gid;
                    if (v > bv) { bv = v; bi = r; }
                }
            #pragma unroll
            for (int o = 4; o <= 16; o <<= 1) {
                float v2 = __shfl_xor_sync(0xffffffffu, bv, o);
                int i2 = __shfl_xor_sync(0xffffffffu, bi, o);
                if (v2 > bv || (v2 == bv && i2 < bi)) { bv = v2; bi = i2; }
            }
            if (gid == 0) {
                int cl = n0w + np * 8 + tig * 2 + e;
                s_cv[wid & 3][cl] = bv;
                s_ci[wid & 3][cl] = bi;
            }
        }
    __syncthreads();
    if (t < 128) {
        float bv = s_rv[0][t]; int bi = s_ri[0][t];
        if (s_rv[1][t] > bv || (s_rv[1][t] == bv && s_ri[1][t] < bi)) { bv = s_rv[1][t]; bi = s_ri[1][t]; }
        g_rowmax_part[(size_t)p * 32 * NN + blockIdx.x * NN + m0 + t] = bv;
        g_rowidx_part[(size_t)p * 32 * NN + blockIdx.x * NN + m0 + t] = bi;
        float cv = s_cv[0][t]; int ci = s_ci[0][t];
        #pragma unroll
        for (int w = 1; w < 4; w++) {
            if (s_cv[w][t] > cv || (s_cv[w][t] == cv && s_ci[w][t] < ci)) { cv = s_cv[w][t]; ci = s_ci[w][t]; }
        }
        g_colmax_part[(size_t)p * 32 * NN + blockIdx.y * NN + col0 + t] = cv;
        g_colidx_part[(size_t)p * 32 * NN + blockIdx.y * NN + col0 + t] = ci;
    }
}

// ---------------- max reduce, all pairs: grid (16, NP) ----------------
__global__ void __launch_bounds__(256) maxreduce_all_kernel() {
    int p = blockIdx.y;
    int n = blockIdx.x * 256 + threadIdx.x;
    size_t pb = (size_t)p * 32 * NN;
    float bm = g_rowmax_part[pb + n]; int bi = g_rowidx_part[pb + n];
    for (int s = 1; s < 32; s++) {
        float v = g_rowmax_part[pb + s * NN + n];
        int i2 = g_rowidx_part[pb + s * NN + n];
        if (v > bm || (v == bm && i2 < bi)) { bm = v; bi = i2; }
    }
    g_rowmax[p * NN + n] = bm; g_rowidx[p * NN + n] = bi;
    bm = g_colmax_part[pb + n]; bi = g_colidx_part[pb + n];
    for (int s = 1; s < 32; s++) {
        float v = g_colmax_part[pb + s * NN + n];
        int i2 = g_colidx_part[pb + s * NN + n];
        if (v > bm || (v == bm && i2 < bi)) { bm = v; bi = i2; }
    }
    g_colmax[p * NN + n] = bm; g_colidx[p * NN + n] = bi;
}

// ---------------- compaction, all pairs: grid NP ----------------
__global__ void __launch_bounds__(1024) compact_all_kernel() {
    __shared__ int tsum[1024];
    int p = blockIdx.x;
    const int* ridx = g_rowidx + p * NN;
    const int* cidx = g_colidx + p * NN;
    int* rlist = g_rowlist + p * NN;
    int* clist = g_collist + p * NN;
    int t = threadIdx.x;
    int flags[8];
    int s = 0;
    #pragma unroll
    for (int u = 0; u < 8; u++) {
        int idx = t * 8 + u;
        int f;
        if (idx < NN) { int n = idx; f = (cidx[ridx[n]] == n); }
        else          { int m = idx - NN; f = (ridx[cidx[m]] == m); }
        flags[u] = f;
        s += f;
    }
    tsum[t] = s;
    __syncthreads();
    for (int off = 1; off < 1024; off <<= 1) {
        int v = (t >= off) ? tsum[t - off] : 0;
        __syncthreads();
        tsum[t] += v;
        __syncthreads();
    }
    int rowtot = tsum[511];
    int total = tsum[1023];
    if (t == 0) { g_nsel[p * 2] = rowtot; g_nsel[p * 2 + 1] = total - rowtot; }
    int run = (t > 0) ? tsum[t - 1] : 0;
    #pragma unroll
    for (int u = 0; u < 8; u++) {
        if (flags[u]) {
            int idx = t * 8 + u;
            if (idx < NN) rlist[run] = idx;
            else          clist[run - rowtot] = idx - NN;
            run++;
        }
    }
    __syncthreads();
    int coltot = total - rowtot;
    for (int i2 = rowtot + t; i2 < NN; i2 += 1024) rlist[i2] = 0;
    for (int i2 = coltot + t; i2 < NN; i2 += 1024) clist[i2] = 0;
}

// ---------------- fused exp + sum partials v2: grid (64, 64, NP) ----------------
// 64x64 tile per block, vectorized bf16 IO, early exit, 64-wide sum partials.
__global__ void __launch_bounds__(256) exp_all_kernel() {
    __shared__ float tile[64][65];
    __shared__ int rflag[64], cflag[64];
    __shared__ int s_any;
    const int p = blockIdx.z;
    const int m0 = blockIdx.x * 64;
    const int k0 = blockIdx.y * 64;
    const int t = threadIdx.x;
    const int l = t & 31;
    const int* ridx = g_rowidx + p * NN;
    const int* cidx = g_colidx + p * NN;
    if (t == 0) s_any = 0;
    __syncthreads();
    if (t < 64) {
        int k = k0 + t;
        int f = (cidx[ridx[k]] == k);
        rflag[t] = f;
        if (__ballot_sync(0xffffffffu, f) && l == 0) atomicOr(&s_any, 1);
    } else if (t < 128) {
        int m = m0 + t - 64;
        int f = (ridx[cidx[m]] == m);
        cflag[t - 64] = f;
        if (__ballot_sync(0xffffffffu, f) && l == 0) atomicOr(&s_any, 1);
    }
    __syncthreads();
    if (!s_any) return;

    const int r = (t >> 5) * 8 + (l >> 2);   // 0..63
    const int c0 = (l & 3) * 16;
    const __nv_bfloat16* simp = g_simb + (size_t)p * SIMSZ;

    float fv[16];
    {
        uint4 va = *(const uint4*)(simp + (size_t)(k0 + r) * NN + m0 + c0);
        uint4 vb = *(const uint4*)(simp + (size_t)(k0 + r) * NN + m0 + c0 + 8);
        const uint32_t* ua = (const uint32_t*)&va;
        const uint32_t* ub = (const uint32_t*)&vb;
        #pragma unroll
        for (int i = 0; i < 4; i++) {
            float2 f2 = __bfloat1622float2(*(const __nv_bfloat162*)&ua[i]);
            fv[2 * i] = f2.x; fv[2 * i + 1] = f2.y;
        }
        #pragma unroll
        for (int i = 0; i < 4; i++) {
            float2 f2 = __bfloat1622float2(*(const __nv_bfloat162*)&ub[i]);
            fv[8 + 2 * i] = f2.x; fv[9 + 2 * i] = f2.y;
        }
    }
    #pragma unroll
    for (int i = 0; i < 16; i++) tile[r][c0 + i] = fv[i];

    // ---- row direction: p[k][m] ----
    float s = 0.0f;
    uint32_t out[8];
    const bool fr = rflag[r];
    if (fr) {
        float rm = g_rowmax[p * NN + k0 + r];
        #pragma unroll
        for (int i = 0; i < 8; i++) {
            float e0 = fast_exp(fv[2 * i] - rm);
            float e1 = fast_exp(fv[2 * i + 1] - rm);
            s += e0 + e1;
            __nv_bfloat162 b2 = __float22bfloat162_rn(make_float2(e0, e1));
            out[i] = *(uint32_t*)&b2;
        }
    }
    s += __shfl_xor_sync(0xffffffffu, s, 1);
    s += __shfl_xor_sync(0xffffffffu, s, 2);
    if (fr) {
        __nv_bfloat16* dst = g_p_h + (size_t)p * SIMSZ + (size_t)(k0 + r) * NN + m0 + c0;
        *(uint4*)dst = *(uint4*)&out[0];
        *(uint4*)(dst + 8) = *(uint4*)&out[4];
        if ((l & 3) == 0)
            g_sprow[((size_t)p * NN + k0 + r) * 64 + (m0 >> 6)] = s;
    }
    __syncthreads();

    // ---- col direction: pT[m][k] = exp(sim[k][m] - colmax[m]) ----
    s = 0.0f;
    const bool fc = cflag[r];   // r now indexes the m (column) within tile
    if (fc) {
        float cm = g_colmax[p * NN + m0 + r];
        #pragma unroll
        for (int i = 0; i < 8; i++) {
            float e0 = fast_exp(tile[c0 + 2 * i][r] - cm);
            float e1 = fast_exp(tile[c0 + 2 * i + 1][r] - cm);
            s += e0 + e1;
            __nv_bfloat162 b2 = __float22bfloat162_rn(make_float2(e0, e1));
            out[i] = *(uint32_t*)&b2;
        }
    }
    s += __shfl_xor_sync(0xffffffffu, s, 1);
    s += __shfl_xor_sync(0xffffffffu, s, 2);
    if (fc) {
        __nv_bfloat16* dst = g_pT_h + (size_t)p * SIMSZ + (size_t)(m0 + r) * NN + k0 + c0;
        *(uint4*)dst = *(uint4*)&out[0];
        *(uint4*)(dst + 8) = *(uint4*)&out[4];
        if ((l & 3) == 0)
            g_spcol[((size_t)p * NN + m0 + r) * 64 + (k0 >> 6)] = s;
    }
}

// ---------------- sums from 64 partials: grid (NN, 2, NP), 32 thr ----------------
__global__ void __launch_bounds__(32) sums_all_kernel() {
    int p = blockIdx.z;
    int dir = blockIdx.y;
    int b = blockIdx.x;
    if (b >= g_nsel[p * 2 + dir]) return;
    int row = dir ? g_collist[p * NN + b] : g_rowlist[p * NN + b];
    const float* part = (dir ? g_spcol : g_sprow) + ((size_t)p * NN + row) * 64;
    int t = threadIdx.x;
    float s = part[t] + part[t + 32];
    #pragma unroll
    for (int o = 16; o > 0; o >>= 1) s += __shfl_xor_sync(0xffffffffu, s, o);
    if (t == 0) {
        if (dir) g_colsum[p * NN + row] = s;
        else     g_rowsum[p * NN + row] = s;
    }
}

// ---------------- weighted bf16 MMA, 1-term: grid (2, 32, NP*2) ----------------
__global__ void __launch_bounds__(256) gemm_all_kernel() {
    const int p = blockIdx.z >> 1;
    const int dir = blockIdx.z & 1;
    const int m0 = blockIdx.y * 128;
    const int nsel = g_nsel[p * 2 + dir];
    if (m0 >= nsel) return;
    __shared__ __align__(16) char sm[2][16384];

    const int t = threadIdx.x;
    const int lane = t & 31, wid = t >> 5;
    const int m0w = (wid & 3) * 32, n0w = (wid >> 2) * 64;
    const int n0 = blockIdx.x * 128;
    const int lrow = t >> 2, q = t & 3;
    const uint32_t sbase = smem_u32(&sm[0][0]);

    const int* list = (dir ? g_collist : g_rowlist) + p * NN;
    const __nv_bfloat16* Ph = (dir ? g_pT_h : g_p_h) + (size_t)p * SIMSZ;
    const int sv = dir ? c_PI[p] : c_PJ[p];
    const __nv_bfloat16* Sh = g_sfT_h + (size_t)sv * CC * NN;

    const int grow0 = list[m0 + lrow];
    const int grow1 = list[m0 + lrow + 64];

    float acc[2][8][4];
    #pragma unroll
    for (int a = 0; a < 2; a++)
        #pragma unroll
        for (int b = 0; b < 8; b++)
            #pragma unroll
            for (int c = 0; c < 4; c++) acc[a][b][c] = 0.0f;

    uint4 ra0, ra1, rb0, rb1;
    #define W_LDG(KB) do { \
        int kk = (KB) * 32; \
        ra0 = *(const uint4*)(Ph + (size_t)grow0 * NN + kk + q * 8); \
        ra1 = *(const uint4*)(Ph + (size_t)grow1 * NN + kk + q * 8); \
        rb0 = *(const uint4*)(Sh + (size_t)(n0 + lrow) * NN + kk + q * 8); \
        rb1 = *(const uint4*)(Sh + (size_t)(n0 + lrow + 64) * NN + kk + q * 8); \
    } while (0)
    #define W_STS(BUF) do { \
        char* base = &sm[BUF][0]; \
        *(uint4*)(base + swz64(lrow, q)) = ra0; \
        *(uint4*)(base + swz64(lrow + 64, q)) = ra1; \
        *(uint4*)(base + 8192 + swz64(lrow, q)) = rb0; \
        *(uint4*)(base + 8192 + swz64(lrow + 64, q)) = rb1; \
    } while (0)

    W_LDG(0);
    W_STS(0);
    __syncthreads();
    for (int kb = 0; kb < 128; kb++) {
        int buf = kb & 1;
        if (kb + 1 < 128) W_LDG(kb + 1);
        mma_block(sbase + buf * 16384, sbase + buf * 16384 + 8192, lane, m0w, n0w, acc);
        if (kb + 1 < 128) W_STS(buf ^ 1);
        __syncthreads();
    }
    #undef W_LDG
    #undef W_STS

    const int gid = lane >> 2, tig = lane & 3;
    const float* sums = dir ? g_colsum : g_rowsum;
    float* soft = (dir ? g_soft_col : g_soft_row) + (size_t)p * NN * CC;
    #pragma unroll
    for (int mt = 0; mt < 2; mt++) {
        int s0 = m0 + m0w + mt * 16 + gid;
        #pragma unroll
        for (int h = 0; h < 2; h++) {
            int slot = s0 + h * 8;
            if (slot >= nsel) continue;
            int row = list[slot];
            float inv = 1.0f / sums[p * NN + row];
            #pragma unroll
            for (int np = 0; np < 8; np++) {
                int c = n0 + n0w + np * 8 + tig * 2;
                *(float2*)&soft[(size_t)row * CC + c] =
                    make_float2(acc[mt][np][h * 2] * inv, acc[mt][np][h * 2 + 1] * inv);
            }
        }
    }
}

// ---------------- loss (slot-based), all: grid (32, 2, NP) ----------------
__global__ void __launch_bounds__(256) loss_all_kernel() {
    int p = blockIdx.z;
    int dir = blockIdx.y;
    int tid = threadIdx.x;
    int b = blockIdx.x;
    int op = dir ? c_OP1[p] : c_OP0[p];
    int nsel = g_nsel[p * 2 + dir];
    int start = b * 128;
    int cnt = nsel - start;
    if (cnt > 128) cnt = 128;
    if (cnt <= 0) {
        if (tid == 0) { g_sq_part[op * 32 + b] = 0.0f; g_cnt_part[op * 32 + b] = 0; }
        return;
    }
    const int* list = (dir ? g_collist : g_rowlist) + p * NN;
    __shared__ int rows[128];
    if (tid < 128 && tid < cnt) rows[tid] = list[start + tid];
    __syncthreads();
    const float* soft = (dir ? g_soft_col : g_soft_row) + (size_t)p * NN * CC;
    const float* recon = g_recon + (size_t)(dir ? c_PJ[p] : c_PI[p]) * NN * CC;
    float relc = g_relWT[op * CC + tid];
    float lsum = 0.0f;
    for (int i = 0; i < cnt; i++) {
        int row = rows[i];
        float d = recon[(size_t)row * CC + tid] + relc - soft[(size_t)row * CC + tid];
        lsum += d * d;
    }
    __shared__ float ss[256];
    ss[tid] = lsum;
    __syncthreads();
    for (int off = 128; off > 0; off >>= 1) {
        if (tid < off) ss[tid] += ss[tid + off];
        __syncthreads();
    }
    if (tid == 0) {
        g_sq_part[op * 32 + b] = ss[0];
        g_cnt_part[op * 32 + b] = cnt;
    }
}

__global__ void finalize_kernel(float* __restrict__ out) {
    if (threadIdx.x == 0) {
        float total = 0.0f, count = 0.0f;
        for (int op = 0; op < 12; op++) {
            float sq = 0.0f;
            int cnt = 0;
            for (int b = 0; b < 32; b++) {
                sq += g_sq_part[op * 32 + b];
                cnt += g_cnt_part[op * 32 + b];
            }
            if (cnt > 0) {
                total += sq / fmaxf((float)cnt * (float)CC, 1.0f);
                count += 1.0f;
            }
        }
        out[0] = (count > 0.0f) ? (total / fmaxf(count, 1.0f)) : 0.0f;
    }
}

// ---------------- host launch ----------------
extern "C" void kernel_launch(void* const* d_in, const int* in_sizes, int n_in,
                              void* d_out, int out_size)
{
    const float* desc  = (const float*)d_in[0];
    const float* sf    = (const float*)d_in[1];
    const float* T     = (const float*)d_in[2];
    const float* W_rec = (const float*)d_in[3];
    const float* W_T   = (const float*)d_in[4];
    float* out = (float*)d_out;

    normalize_kernel<<<NN * VV, 256>>>(desc);
    sf_split_kernel<<<dim3(NN / 32, CC / 32, VV), 256>>>(sf);
    wr_split_kernel<<<dim3(8, 8), 256>>>(W_rec);
    relwt_kernel<<<12, 256>>>(T, W_T);
    recon_mma_kernel<<<dim3(2, 32, VV), 256>>>();

    sim_all_kernel<<<dim3(32, 32, NP), 256>>>();
    maxreduce_all_kernel<<<dim3(16, NP), 256>>>();
    compact_all_kernel<<<NP, 1024>>>();
    exp_all_kernel<<<dim3(NN / 64, NN / 64, NP), 256>>>();
    sums_all_kernel<<<dim3(NN, 2, NP), 32>>>();
    gemm_all_kernel<<<dim3(2, 32, NP * 2), 256>>>();
    loss_all_kernel<<<dim3(32, 2, NP), 256>>>();

    finalize_kernel<<<1, 32>>>(out);
}